// round 1
// baseline (speedup 1.0000x reference)
#include <cuda_runtime.h>
#include <cstdint>

// Problem constants
#define BB   16
#define NN   4096
#define CC   768
#define HH   8
#define DD   96
#define C3   2304
#define MM   (BB * NN)          // 65536

// Scratch (allocation-free rule: __device__ globals)
__device__ float g_qkv[(size_t)MM * C3];     // [B*N, 3C]  (b,n major) ~604MB
__device__ float g_attn[BB * HH * DD * DD];  // [b,h,d,e]
__device__ float g_ao[(size_t)MM * CC];      // [B*N, C]   ~201MB

// ---------------------------------------------------------------------------
// SGEMM: C[m,n] = sum_k A[m,k] * W[n,k] + bias[n]
// A row-major [M,K], W row-major [Nc,K]. BM=BN=128, BK=8, 256 thr, 8x8 micro.
// mode 0: A = x (param),  C = g_qkv
// mode 1: A = g_ao,       C = out (param)
// ---------------------------------------------------------------------------
#define BM 128
#define BN 128
#define BK 8
#define PAD 132   // padded BM/BN dim in smem

__global__ __launch_bounds__(256)
void sgemm_nt_bias(const float* __restrict__ Aexp,
                   const float* __restrict__ W,
                   const float* __restrict__ bias,
                   float* __restrict__ Cexp,
                   int M, int Nc, int K, int mode)
{
    const float* A = (mode == 0) ? Aexp : g_ao;
    float*       C = (mode == 0) ? g_qkv : Cexp;

    __shared__ float As[2][BK][PAD];
    __shared__ float Bs[2][BK][PAD];

    const int tid = threadIdx.x;
    const int bn  = blockIdx.x;   // N tile
    const int bm  = blockIdx.y;   // M tile
    const int tx  = tid & 15;     // 0..15  (n dir)
    const int ty  = tid >> 4;     // 0..15  (m dir)

    // tile-load mapping: one float4 from A and one from W per thread per BK-slab
    const int lrow = tid >> 1;          // 0..127
    const int lk4  = (tid & 1) * 4;     // 0 or 4
    const float* Aptr = A + (size_t)(bm * BM + lrow) * K + lk4;
    const float* Wptr = W + (size_t)(bn * BN + lrow) * K + lk4;

    // prologue: load slab 0
    float4 a4 = *(const float4*)Aptr;
    float4 b4 = *(const float4*)Wptr;
    As[0][lk4 + 0][lrow] = a4.x; As[0][lk4 + 1][lrow] = a4.y;
    As[0][lk4 + 2][lrow] = a4.z; As[0][lk4 + 3][lrow] = a4.w;
    Bs[0][lk4 + 0][lrow] = b4.x; Bs[0][lk4 + 1][lrow] = b4.y;
    Bs[0][lk4 + 2][lrow] = b4.z; Bs[0][lk4 + 3][lrow] = b4.w;
    __syncthreads();

    float acc[8][8];
    #pragma unroll
    for (int i = 0; i < 8; i++)
        #pragma unroll
        for (int j = 0; j < 8; j++) acc[i][j] = 0.f;

    const int nk = K / BK;
    int buf = 0;
    for (int kb = 0; kb < nk; ++kb) {
        float4 a4n, b4n;
        if (kb + 1 < nk) {
            a4n = *(const float4*)(Aptr + (size_t)(kb + 1) * BK);
            b4n = *(const float4*)(Wptr + (size_t)(kb + 1) * BK);
        }
        #pragma unroll
        for (int kk = 0; kk < BK; ++kk) {
            float4 ar0 = *(const float4*)&As[buf][kk][ty * 8];
            float4 ar1 = *(const float4*)&As[buf][kk][ty * 8 + 4];
            float4 br0 = *(const float4*)&Bs[buf][kk][tx * 8];
            float4 br1 = *(const float4*)&Bs[buf][kk][tx * 8 + 4];
            float ar[8] = {ar0.x, ar0.y, ar0.z, ar0.w, ar1.x, ar1.y, ar1.z, ar1.w};
            float br[8] = {br0.x, br0.y, br0.z, br0.w, br1.x, br1.y, br1.z, br1.w};
            #pragma unroll
            for (int i = 0; i < 8; i++)
                #pragma unroll
                for (int j = 0; j < 8; j++)
                    acc[i][j] = fmaf(ar[i], br[j], acc[i][j]);
        }
        if (kb + 1 < nk) {
            const int nb = buf ^ 1;
            As[nb][lk4 + 0][lrow] = a4n.x; As[nb][lk4 + 1][lrow] = a4n.y;
            As[nb][lk4 + 2][lrow] = a4n.z; As[nb][lk4 + 3][lrow] = a4n.w;
            Bs[nb][lk4 + 0][lrow] = b4n.x; Bs[nb][lk4 + 1][lrow] = b4n.y;
            Bs[nb][lk4 + 2][lrow] = b4n.z; Bs[nb][lk4 + 3][lrow] = b4n.w;
            __syncthreads();
            buf = nb;
        }
    }

    // epilogue with bias
    const int ncol = bn * BN + tx * 8;
    #pragma unroll
    for (int i = 0; i < 8; i++) {
        const size_t row = (size_t)(bm * BM + ty * 8 + i);
        float* crow = C + row * Nc + ncol;
        #pragma unroll
        for (int j = 0; j < 8; j += 4) {
            float4 o;
            o.x = acc[i][j + 0] + bias[ncol + j + 0];
            o.y = acc[i][j + 1] + bias[ncol + j + 1];
            o.z = acc[i][j + 2] + bias[ncol + j + 2];
            o.w = acc[i][j + 3] + bias[ncol + j + 3];
            *(float4*)(crow + j) = o;
        }
    }
}

// ---------------------------------------------------------------------------
// Attention logits + softmax, one block per (b,h).
// attn[d,e] = softmax_e( (1/64) * sum_n q[n,d] k[n,e] ),  96x96, K=4096.
// 256 thr: 16x16 grid of 6x6 microtiles. Q/K tiles of 32 rows staged in smem.
// ---------------------------------------------------------------------------
__global__ __launch_bounds__(256)
void attn_softmax_kernel()
{
    const int bh = blockIdx.x;            // 0..127
    const int b  = bh >> 3, h = bh & 7;

    __shared__ float sm[96 * 96];         // Q tile | K tile, then reused as logits
    float* Qs = sm;                       // [32][96]
    float* Ks = sm + 32 * 96;

    const int tid = threadIdx.x;
    const int tx  = tid & 15;
    const int ty  = tid >> 4;

    float acc[6][6];
    #pragma unroll
    for (int i = 0; i < 6; i++)
        #pragma unroll
        for (int j = 0; j < 6; j++) acc[i][j] = 0.f;

    const float* qbase = g_qkv + (size_t)(b * NN) * C3 + h * DD;  // +n*C3 +d
    // k is at +CC within a row

    for (int n0 = 0; n0 < NN; n0 += 32) {
        #pragma unroll
        for (int t = 0; t < 3; ++t) {
            const int id = tid + t * 256;          // 0..767  (32 rows x 24 f4)
            const int r  = id / 24;
            const int c4 = (id % 24) * 4;
            const float* qp = qbase + (size_t)(n0 + r) * C3 + c4;
            *(float4*)&Qs[r * 96 + c4] = *(const float4*)qp;
            *(float4*)&Ks[r * 96 + c4] = *(const float4*)(qp + CC);
        }
        __syncthreads();
        #pragma unroll 8
        for (int kk = 0; kk < 32; ++kk) {
            float qr[6], kr[6];
            #pragma unroll
            for (int i = 0; i < 6; i++) qr[i] = Qs[kk * 96 + ty * 6 + i];
            #pragma unroll
            for (int j = 0; j < 6; j++) kr[j] = Ks[kk * 96 + tx * 6 + j];
            #pragma unroll
            for (int i = 0; i < 6; i++)
                #pragma unroll
                for (int j = 0; j < 6; j++)
                    acc[i][j] = fmaf(qr[i], kr[j], acc[i][j]);
        }
        __syncthreads();
    }

    // scaled logits -> smem (reuse)
    const float scale = 0.015625f;   // 4096^-0.5
    #pragma unroll
    for (int i = 0; i < 6; i++)
        #pragma unroll
        for (int j = 0; j < 6; j++)
            sm[(ty * 6 + i) * 96 + tx * 6 + j] = acc[i][j] * scale;
    __syncthreads();

    // row softmax: 8 warps x 12 rows, 3 cols/lane
    const int wid = tid >> 5, lane = tid & 31;
    for (int r = wid; r < 96; r += 8) {
        float v0 = sm[r * 96 + lane];
        float v1 = sm[r * 96 + 32 + lane];
        float v2 = sm[r * 96 + 64 + lane];
        float m = fmaxf(v0, fmaxf(v1, v2));
        #pragma unroll
        for (int off = 16; off > 0; off >>= 1)
            m = fmaxf(m, __shfl_xor_sync(0xffffffffu, m, off));
        float e0 = expf(v0 - m), e1 = expf(v1 - m), e2 = expf(v2 - m);
        float s = e0 + e1 + e2;
        #pragma unroll
        for (int off = 16; off > 0; off >>= 1)
            s += __shfl_xor_sync(0xffffffffu, s, off);
        const float inv = 1.f / s;
        float* arow = g_attn + ((size_t)bh * 96 + r) * 96;
        arow[lane]      = e0 * inv;
        arow[lane + 32] = e1 * inv;
        arow[lane + 64] = e2 * inv;
    }
}

// ---------------------------------------------------------------------------
// out[n,d] = sum_e attn[d,e] v[n,e], per (b,h), n tiled by 128.
// grid (32, 128). attn staged in smem (pad 97), v staged in 16-wide e chunks.
// ---------------------------------------------------------------------------
__global__ __launch_bounds__(256)
void av_kernel()
{
    const int nt = blockIdx.x;    // 0..31
    const int bh = blockIdx.y;    // 0..127
    const int b  = bh >> 3, h = bh & 7;

    __shared__ float at[96 * 97];     // attn, padded
    __shared__ float Vs[128 * 20];    // 128 rows x 16-e chunk, pad 20 (16B align)

    const int tid = threadIdx.x;
    const int tx  = tid & 15;     // d dir (6 each)
    const int ty  = tid >> 4;     // n dir (8 each)

    const float* asrc = g_attn + (size_t)bh * 9216;
    for (int id = tid; id < 96 * 96; id += 256) {
        const int r = id / 96, c = id - r * 96;
        at[r * 97 + c] = asrc[id];
    }

    float acc[8][6];
    #pragma unroll
    for (int i = 0; i < 8; i++)
        #pragma unroll
        for (int j = 0; j < 6; j++) acc[i][j] = 0.f;

    const float* vbase = g_qkv + (size_t)(b * NN + nt * 128) * C3 + 2 * CC + h * DD;

    for (int e0 = 0; e0 < 96; e0 += 16) {
        __syncthreads();   // attn visible (first iter) / prev-iter reads done
        #pragma unroll
        for (int t = 0; t < 2; ++t) {
            const int id = tid + t * 256;       // 0..511 (128 rows x 4 f4)
            const int r  = id >> 2;
            const int c4 = (id & 3) * 4;
            *(float4*)&Vs[r * 20 + c4] =
                *(const float4*)(vbase + (size_t)r * C3 + e0 + c4);
        }
        __syncthreads();
        #pragma unroll
        for (int e = 0; e < 16; ++e) {
            float av[6], vv[8];
            #pragma unroll
            for (int j = 0; j < 6; j++) av[j] = at[(tx * 6 + j) * 97 + e0 + e];
            #pragma unroll
            for (int i = 0; i < 8; i++) vv[i] = Vs[(ty * 8 + i) * 20 + e];
            #pragma unroll
            for (int i = 0; i < 8; i++)
                #pragma unroll
                for (int j = 0; j < 6; j++)
                    acc[i][j] = fmaf(vv[i], av[j], acc[i][j]);
        }
    }

    #pragma unroll
    for (int i = 0; i < 8; i++) {
        const size_t row = (size_t)(b * NN + nt * 128 + ty * 8 + i);
        float* orow = g_ao + row * CC + h * DD + tx * 6;
        #pragma unroll
        for (int j = 0; j < 6; j++) orow[j] = acc[i][j];
    }
}

// ---------------------------------------------------------------------------
extern "C" void kernel_launch(void* const* d_in, const int* in_sizes, int n_in,
                              void* d_out, int out_size)
{
    const float* x      = (const float*)d_in[0];
    const float* w_qkv  = (const float*)d_in[1];
    const float* b_qkv  = (const float*)d_in[2];
    const float* w_proj = (const float*)d_in[3];
    const float* b_proj = (const float*)d_in[4];
    float*       out    = (float*)d_out;

    // 1) qkv = x @ w_qkv^T + b_qkv  -> g_qkv
    {
        dim3 grid(C3 / BN, MM / BM);
        sgemm_nt_bias<<<grid, 256>>>(x, w_qkv, b_qkv, nullptr, MM, C3, CC, 0);
    }
    // 2) logits + softmax -> g_attn
    attn_softmax_kernel<<<BB * HH, 256>>>();
    // 3) attn-weighted v -> g_ao
    {
        dim3 grid(NN / 128, BB * HH);
        av_kernel<<<grid, 256>>>();
    }
    // 4) out = g_ao @ w_proj^T + b_proj
    {
        dim3 grid(CC / BN, MM / BM);
        sgemm_nt_bias<<<grid, 256>>>(nullptr, w_proj, b_proj, out, MM, CC, CC, 1);
    }
}

// round 3
// speedup vs baseline: 2.0304x; 2.0304x over previous
#include <cuda_runtime.h>
#include <cuda_bf16.h>
#include <cstdint>

// Problem constants
#define BB   16
#define NN   4096
#define CC   768
#define HH   8
#define DD   96
#define C3   2304
#define MM   (BB * NN)          // 65536
#define KK   768

// ---------------------------------------------------------------------------
// Scratch (__device__ globals; allocation-free rule)
// ---------------------------------------------------------------------------
__device__ float g_qkv[(size_t)MM * C3];        // [B*N, 3C] fp32
__device__ float g_attn[BB * HH * DD * DD];     // [b,h,d,e]
__device__ __nv_bfloat16 g_xhi[(size_t)MM * CC];
__device__ __nv_bfloat16 g_xlo[(size_t)MM * CC];
__device__ __nv_bfloat16 g_aohi[(size_t)MM * CC];
__device__ __nv_bfloat16 g_aolo[(size_t)MM * CC];
__device__ __nv_bfloat16 g_wqh[C3 * CC];
__device__ __nv_bfloat16 g_wql[C3 * CC];
__device__ __nv_bfloat16 g_wph[CC * CC];
__device__ __nv_bfloat16 g_wpl[CC * CC];

// ---------------------------------------------------------------------------
// PTX helpers (target-agnostic: ldmatrix + mma.sync, sm_80+)
// ---------------------------------------------------------------------------
__device__ __forceinline__ uint32_t smem_u32(const void* p) {
    uint32_t a;
    asm("{ .reg .u64 t; cvta.to.shared.u64 t, %1; cvt.u32.u64 %0, t; }"
        : "=r"(a) : "l"(p));
    return a;
}
__device__ __forceinline__ void ldsm_x4(uint32_t* r, uint32_t addr) {
    asm volatile("ldmatrix.sync.aligned.m8n8.x4.shared.b16 {%0,%1,%2,%3}, [%4];"
                 : "=r"(r[0]), "=r"(r[1]), "=r"(r[2]), "=r"(r[3]) : "r"(addr));
}
__device__ __forceinline__ void ldsm_x2(uint32_t* r, uint32_t addr) {
    asm volatile("ldmatrix.sync.aligned.m8n8.x2.shared.b16 {%0,%1}, [%2];"
                 : "=r"(r[0]), "=r"(r[1]) : "r"(addr));
}
__device__ __forceinline__ void mma16816(float* c, const uint32_t* a, const uint32_t* b) {
    asm volatile(
        "mma.sync.aligned.m16n8k16.row.col.f32.bf16.bf16.f32 "
        "{%0,%1,%2,%3}, {%4,%5,%6,%7}, {%8,%9}, {%0,%1,%2,%3};"
        : "+f"(c[0]), "+f"(c[1]), "+f"(c[2]), "+f"(c[3])
        : "r"(a[0]), "r"(a[1]), "r"(a[2]), "r"(a[3]), "r"(b[0]), "r"(b[1]));
}
#define STS128(a, v) \
    asm volatile("st.shared.v4.b32 [%0], {%1, %2, %3, %4};" \
                 :: "r"(a), "r"((v).x), "r"((v).y), "r"((v).z), "r"((v).w) : "memory")

// ---------------------------------------------------------------------------
// split: hi = bf16(x), lo = bf16(x - hi)
// ---------------------------------------------------------------------------
__global__ __launch_bounds__(256)
void split_kernel(const float4* __restrict__ src, int mode, int n4)
{
    int i = blockIdx.x * 256 + threadIdx.x;
    if (i >= n4) return;
    __nv_bfloat16 *hi, *lo;
    if (mode == 0)      { hi = g_xhi; lo = g_xlo; }
    else if (mode == 1) { hi = g_wqh; lo = g_wql; }
    else                { hi = g_wph; lo = g_wpl; }
    float4 v = src[i];
    float a[4] = {v.x, v.y, v.z, v.w};
    ushort h[4], l[4];
    #pragma unroll
    for (int t = 0; t < 4; t++) {
        __nv_bfloat16 hb = __float2bfloat16(a[t]);
        float r = a[t] - __bfloat162float(hb);
        h[t] = __bfloat16_as_ushort(hb);
        l[t] = __bfloat16_as_ushort(__float2bfloat16(r));
    }
    ((ushort4*)hi)[i] = make_ushort4(h[0], h[1], h[2], h[3]);
    ((ushort4*)lo)[i] = make_ushort4(l[0], l[1], l[2], l[3]);
}

// ---------------------------------------------------------------------------
// HMMA bf16-split GEMM: C[m,n] = sum_k A[m,k]*W[n,k] + bias[n]
// 128x128 tile, BK=32, 8 warps as 2(m)x4(n), warp tile 64x32.
// 3 passes: Ah*Bh + Ah*Bl + Al*Bh, fp32 accum.
// SMEM tiles: row stride 80B (conflict-free ldmatrix), 4 tiles x 2 stages.
// mode 0: A = x splits,  W = w_qkv splits, C = g_qkv
// mode 1: A = ao splits, W = w_proj splits, C = Cp
// ---------------------------------------------------------------------------
#define SROW 80
#define TILE_B (128 * SROW)          // 10240
#define STAGE_B (4 * TILE_B)         // 40960
#define SMEM_ASK (2 * STAGE_B)       // 81920

__global__ __launch_bounds__(256)
void tgemm_kernel(const float* __restrict__ bias, float* __restrict__ Cp,
                  int Nc, int mode)
{
    const __nv_bfloat16 *Ahi, *Alo, *Bhi, *Blo;
    float* C;
    if (mode == 0) { Ahi = g_xhi;  Alo = g_xlo;  Bhi = g_wqh; Blo = g_wql; C = g_qkv; }
    else           { Ahi = g_aohi; Alo = g_aolo; Bhi = g_wph; Blo = g_wpl; C = Cp;    }

    extern __shared__ char smem[];
    const uint32_t ubase = smem_u32(smem);

    const int tid  = threadIdx.x;
    const int wid  = tid >> 5;
    const int lane = tid & 31;
    const int bn   = blockIdx.x;
    const int bm   = blockIdx.y;
    const int wm   = wid & 1;        // 0..1 (m, 64 rows each)
    const int wn   = wid >> 1;       // 0..3 (n, 32 cols each)

    // gmem bases
    const __nv_bfloat16* Ah = Ahi + (size_t)(bm * 128) * KK;
    const __nv_bfloat16* Al = Alo + (size_t)(bm * 128) * KK;
    const __nv_bfloat16* Bh = Bhi + (size_t)(bn * 128) * KK;
    const __nv_bfloat16* Bl = Blo + (size_t)(bn * 128) * KK;

    // staging regs: 2 granules per tile per thread
    uint4 va[2], vb[2], vc[2], vd[2];
    const int r0 = (tid) >> 2,        g0 = (tid) & 3;
    const int r1 = (tid + 256) >> 2,  g1 = (tid + 256) & 3;

    #define GLOAD(kof) do { \
        size_t o0 = (size_t)r0 * KK + (kof) + g0 * 8; \
        size_t o1 = (size_t)r1 * KK + (kof) + g1 * 8; \
        va[0] = *(const uint4*)(Ah + o0); va[1] = *(const uint4*)(Ah + o1); \
        vb[0] = *(const uint4*)(Al + o0); vb[1] = *(const uint4*)(Al + o1); \
        vc[0] = *(const uint4*)(Bh + o0); vc[1] = *(const uint4*)(Bh + o1); \
        vd[0] = *(const uint4*)(Bl + o0); vd[1] = *(const uint4*)(Bl + o1); \
    } while (0)

    #define SSTORE(buf) do { \
        uint32_t sb = ubase + (buf) * STAGE_B; \
        uint32_t a0 = sb + r0 * SROW + g0 * 16; \
        uint32_t a1 = sb + r1 * SROW + g1 * 16; \
        STS128(a0 + 0 * TILE_B, va[0]); STS128(a1 + 0 * TILE_B, va[1]); \
        STS128(a0 + 1 * TILE_B, vb[0]); STS128(a1 + 1 * TILE_B, vb[1]); \
        STS128(a0 + 2 * TILE_B, vc[0]); STS128(a1 + 2 * TILE_B, vc[1]); \
        STS128(a0 + 3 * TILE_B, vd[0]); STS128(a1 + 3 * TILE_B, vd[1]); \
    } while (0)

    float acc[4][4][4];
    #pragma unroll
    for (int i = 0; i < 4; i++)
        #pragma unroll
        for (int j = 0; j < 4; j++)
            #pragma unroll
            for (int q = 0; q < 4; q++) acc[i][j][q] = 0.f;

    // ldmatrix lane addressing
    const int laneRA = lane & 15;            // A: rows (x4)
    const int laneGA = lane >> 4;            // A: k-granule select
    const int laneRB = lane & 7;             // B: rows (x2)
    const int laneGB = (lane >> 3) & 1;      // B: k-granule select

    const int NK = KK / 32;                  // 24 chunks

    GLOAD(0);
    SSTORE(0);
    GLOAD(32);
    __syncthreads();

    for (int kb = 0; kb < NK; ++kb) {
        const uint32_t sb = ubase + (kb & 1) * STAGE_B;
        const uint32_t aBase = sb + (wm * 64 + laneRA) * SROW + laneGA * 16;
        const uint32_t bBase = sb + 2 * TILE_B + (wn * 32 + laneRB) * SROW + laneGB * 16;

        #pragma unroll
        for (int ks = 0; ks < 2; ++ks) {
            const uint32_t ko = ks * 32;     // byte offset of k-granule pair
            uint32_t ah[4][4], al[4][4], bh[4][2], bl[4][2];
            #pragma unroll
            for (int fm = 0; fm < 4; fm++) {
                ldsm_x4(ah[fm], aBase + fm * (16 * SROW) + ko);
                ldsm_x4(al[fm], aBase + TILE_B + fm * (16 * SROW) + ko);
            }
            #pragma unroll
            for (int fn = 0; fn < 4; fn++) {
                ldsm_x2(bh[fn], bBase + fn * (8 * SROW) + ko);
                ldsm_x2(bl[fn], bBase + TILE_B + fn * (8 * SROW) + ko);
            }
            #pragma unroll
            for (int fm = 0; fm < 4; fm++)
                #pragma unroll
                for (int fn = 0; fn < 4; fn++) {
                    mma16816(acc[fm][fn], ah[fm], bh[fn]);
                    mma16816(acc[fm][fn], ah[fm], bl[fn]);
                    mma16816(acc[fm][fn], al[fm], bh[fn]);
                }
        }

        if (kb + 1 < NK) {
            __syncthreads();
            SSTORE((kb + 1) & 1);
            if (kb + 2 < NK) GLOAD((kb + 2) * 32);
            __syncthreads();
        }
    }

    // epilogue: add bias, store fp32
    const int gid4 = lane >> 2;              // 0..7
    const int tig  = lane & 3;               // 0..3
    #pragma unroll
    for (int fm = 0; fm < 4; fm++) {
        const int m0 = bm * 128 + wm * 64 + fm * 16 + gid4;
        #pragma unroll
        for (int fn = 0; fn < 4; fn++) {
            const int col = bn * 128 + wn * 32 + fn * 8 + tig * 2;
            const float bx = bias[col], by = bias[col + 1];
            float2 o;
            o.x = acc[fm][fn][0] + bx; o.y = acc[fm][fn][1] + by;
            *(float2*)(C + (size_t)m0 * Nc + col) = o;
            o.x = acc[fm][fn][2] + bx; o.y = acc[fm][fn][3] + by;
            *(float2*)(C + (size_t)(m0 + 8) * Nc + col) = o;
        }
    }
    #undef GLOAD
    #undef SSTORE
}

// ---------------------------------------------------------------------------
// Attention logits + softmax, one block per (b,h).
// ---------------------------------------------------------------------------
__global__ __launch_bounds__(256)
void attn_softmax_kernel()
{
    const int bh = blockIdx.x;
    const int b  = bh >> 3, h = bh & 7;

    __shared__ float sm[96 * 96];
    float* Qs = sm;
    float* Ks = sm + 32 * 96;

    const int tid = threadIdx.x;
    const int tx  = tid & 15;
    const int ty  = tid >> 4;

    float acc[6][6];
    #pragma unroll
    for (int i = 0; i < 6; i++)
        #pragma unroll
        for (int j = 0; j < 6; j++) acc[i][j] = 0.f;

    const float* qbase = g_qkv + (size_t)(b * NN) * C3 + h * DD;

    for (int n0 = 0; n0 < NN; n0 += 32) {
        #pragma unroll
        for (int t = 0; t < 3; ++t) {
            const int id = tid + t * 256;
            const int r  = id / 24;
            const int c4 = (id % 24) * 4;
            const float* qp = qbase + (size_t)(n0 + r) * C3 + c4;
            *(float4*)&Qs[r * 96 + c4] = *(const float4*)qp;
            *(float4*)&Ks[r * 96 + c4] = *(const float4*)(qp + CC);
        }
        __syncthreads();
        #pragma unroll 8
        for (int kk = 0; kk < 32; ++kk) {
            float qr[6], kr[6];
            #pragma unroll
            for (int i = 0; i < 6; i++) qr[i] = Qs[kk * 96 + ty * 6 + i];
            #pragma unroll
            for (int j = 0; j < 6; j++) kr[j] = Ks[kk * 96 + tx * 6 + j];
            #pragma unroll
            for (int i = 0; i < 6; i++)
                #pragma unroll
                for (int j = 0; j < 6; j++)
                    acc[i][j] = fmaf(qr[i], kr[j], acc[i][j]);
        }
        __syncthreads();
    }

    const float scale = 0.015625f;
    #pragma unroll
    for (int i = 0; i < 6; i++)
        #pragma unroll
        for (int j = 0; j < 6; j++)
            sm[(ty * 6 + i) * 96 + tx * 6 + j] = acc[i][j] * scale;
    __syncthreads();

    const int wid = tid >> 5, lane = tid & 31;
    for (int r = wid; r < 96; r += 8) {
        float v0 = sm[r * 96 + lane];
        float v1 = sm[r * 96 + 32 + lane];
        float v2 = sm[r * 96 + 64 + lane];
        float m = fmaxf(v0, fmaxf(v1, v2));
        #pragma unroll
        for (int off = 16; off > 0; off >>= 1)
            m = fmaxf(m, __shfl_xor_sync(0xffffffffu, m, off));
        float e0 = expf(v0 - m), e1 = expf(v1 - m), e2 = expf(v2 - m);
        float s = e0 + e1 + e2;
        #pragma unroll
        for (int off = 16; off > 0; off >>= 1)
            s += __shfl_xor_sync(0xffffffffu, s, off);
        const float inv = 1.f / s;
        float* arow = g_attn + ((size_t)bh * 96 + r) * 96;
        arow[lane]      = e0 * inv;
        arow[lane + 32] = e1 * inv;
        arow[lane + 64] = e2 * inv;
    }
}

// ---------------------------------------------------------------------------
// out[n,d] = sum_e attn[d,e] v[n,e]; epilogue emits bf16 hi/lo splits.
// ---------------------------------------------------------------------------
__global__ __launch_bounds__(256)
void av_kernel()
{
    const int nt = blockIdx.x;
    const int bh = blockIdx.y;
    const int b  = bh >> 3, h = bh & 7;

    __shared__ float at[96 * 97];
    __shared__ float Vs[128 * 20];

    const int tid = threadIdx.x;
    const int tx  = tid & 15;
    const int ty  = tid >> 4;

    const float* asrc = g_attn + (size_t)bh * 9216;
    for (int id = tid; id < 96 * 96; id += 256) {
        const int r = id / 96, c = id - r * 96;
        at[r * 97 + c] = asrc[id];
    }

    float acc[8][6];
    #pragma unroll
    for (int i = 0; i < 8; i++)
        #pragma unroll
        for (int j = 0; j < 6; j++) acc[i][j] = 0.f;

    const float* vbase = g_qkv + (size_t)(b * NN + nt * 128) * C3 + 2 * CC + h * DD;

    for (int e0 = 0; e0 < 96; e0 += 16) {
        __syncthreads();
        #pragma unroll
        for (int t = 0; t < 2; ++t) {
            const int id = tid + t * 256;
            const int r  = id >> 2;
            const int c4 = (id & 3) * 4;
            *(float4*)&Vs[r * 20 + c4] =
                *(const float4*)(vbase + (size_t)r * C3 + e0 + c4);
        }
        __syncthreads();
        #pragma unroll
        for (int e = 0; e < 16; ++e) {
            float av[6], vv[8];
            #pragma unroll
            for (int j = 0; j < 6; j++) av[j] = at[(tx * 6 + j) * 97 + e0 + e];
            #pragma unroll
            for (int i = 0; i < 8; i++) vv[i] = Vs[(ty * 8 + i) * 20 + e];
            #pragma unroll
            for (int i = 0; i < 8; i++)
                #pragma unroll
                for (int j = 0; j < 6; j++)
                    acc[i][j] = fmaf(vv[i], av[j], acc[i][j]);
        }
    }

    #pragma unroll
    for (int i = 0; i < 8; i++) {
        const size_t row = (size_t)(b * NN + nt * 128 + ty * 8 + i);
        const size_t obase = row * CC + h * DD + tx * 6;
        #pragma unroll
        for (int j = 0; j < 6; j++) {
            float v = acc[i][j];
            __nv_bfloat16 hb = __float2bfloat16(v);
            float r = v - __bfloat162float(hb);
            g_aohi[obase + j] = hb;
            g_aolo[obase + j] = __float2bfloat16(r);
        }
    }
}

// ---------------------------------------------------------------------------
extern "C" void kernel_launch(void* const* d_in, const int* in_sizes, int n_in,
                              void* d_out, int out_size)
{
    const float* x      = (const float*)d_in[0];
    const float* w_qkv  = (const float*)d_in[1];
    const float* b_qkv  = (const float*)d_in[2];
    const float* w_proj = (const float*)d_in[3];
    const float* b_proj = (const float*)d_in[4];
    float*       out    = (float*)d_out;

    cudaFuncSetAttribute(tgemm_kernel,
                         cudaFuncAttributeMaxDynamicSharedMemorySize, SMEM_ASK);

    // 0) bf16 hi/lo splits
    split_kernel<<<(MM * CC / 4) / 256, 256>>>((const float4*)x, 0, MM * CC / 4);
    split_kernel<<<(C3 * CC / 4) / 256, 256>>>((const float4*)w_qkv, 1, C3 * CC / 4);
    split_kernel<<<(CC * CC / 4) / 256, 256>>>((const float4*)w_proj, 2, CC * CC / 4);

    // 1) qkv = x @ w_qkv^T + b_qkv -> g_qkv (HMMA bf16-split)
    {
        dim3 grid(C3 / 128, MM / 128);
        tgemm_kernel<<<grid, 256, SMEM_ASK>>>(b_qkv, nullptr, C3, 0);
    }
    // 2) logits + softmax -> g_attn
    attn_softmax_kernel<<<BB * HH, 256>>>();
    // 3) attn-weighted v -> ao splits
    {
        dim3 grid(NN / 128, BB * HH);
        av_kernel<<<grid, 256>>>();
    }
    // 4) out = ao @ w_proj^T + b_proj (HMMA bf16-split)
    {
        dim3 grid(CC / 128, MM / 128);
        tgemm_kernel<<<grid, 256, SMEM_ASK>>>(b_proj, out, CC, 1);
    }
}

// round 4
// speedup vs baseline: 2.3254x; 1.1453x over previous
#include <cuda_runtime.h>
#include <cuda_bf16.h>
#include <cstdint>

// Problem constants
#define BB   16
#define NN   4096
#define CC   768
#define HH   8
#define DD   96
#define C3   2304
#define MM   (BB * NN)          // 65536
#define KK   768

// ---------------------------------------------------------------------------
// Scratch (__device__ globals; allocation-free rule)
// ---------------------------------------------------------------------------
__device__ float g_qkv[(size_t)MM * C3];        // [B*N, 3C] fp32
__device__ float g_attn[BB * HH * DD * DD];     // [b,h,d,e]
__device__ __nv_bfloat16 g_xhi[(size_t)MM * CC];
__device__ __nv_bfloat16 g_xlo[(size_t)MM * CC];
__device__ __nv_bfloat16 g_aohi[(size_t)MM * CC];
__device__ __nv_bfloat16 g_aolo[(size_t)MM * CC];
__device__ __nv_bfloat16 g_wqh[C3 * CC];
__device__ __nv_bfloat16 g_wql[C3 * CC];
__device__ __nv_bfloat16 g_wph[CC * CC];
__device__ __nv_bfloat16 g_wpl[CC * CC];

// ---------------------------------------------------------------------------
// PTX helpers (target-agnostic: ldmatrix + mma.sync + cp.async, sm_80+)
// ---------------------------------------------------------------------------
__device__ __forceinline__ uint32_t smem_u32(const void* p) {
    uint32_t a;
    asm("{ .reg .u64 t; cvta.to.shared.u64 t, %1; cvt.u32.u64 %0, t; }"
        : "=r"(a) : "l"(p));
    return a;
}
__device__ __forceinline__ void ldsm_x4(uint32_t* r, uint32_t addr) {
    asm volatile("ldmatrix.sync.aligned.m8n8.x4.shared.b16 {%0,%1,%2,%3}, [%4];"
                 : "=r"(r[0]), "=r"(r[1]), "=r"(r[2]), "=r"(r[3]) : "r"(addr));
}
__device__ __forceinline__ void ldsm_x2(uint32_t* r, uint32_t addr) {
    asm volatile("ldmatrix.sync.aligned.m8n8.x2.shared.b16 {%0,%1}, [%2];"
                 : "=r"(r[0]), "=r"(r[1]) : "r"(addr));
}
__device__ __forceinline__ void mma16816(float* c, const uint32_t* a, const uint32_t* b) {
    asm volatile(
        "mma.sync.aligned.m16n8k16.row.col.f32.bf16.bf16.f32 "
        "{%0,%1,%2,%3}, {%4,%5,%6,%7}, {%8,%9}, {%0,%1,%2,%3};"
        : "+f"(c[0]), "+f"(c[1]), "+f"(c[2]), "+f"(c[3])
        : "r"(a[0]), "r"(a[1]), "r"(a[2]), "r"(a[3]), "r"(b[0]), "r"(b[1]));
}
__device__ __forceinline__ void cp16(uint32_t dst, const void* src) {
    asm volatile("cp.async.cg.shared.global [%0], [%1], 16;"
                 :: "r"(dst), "l"(src) : "memory");
}
__device__ __forceinline__ void cp_commit() {
    asm volatile("cp.async.commit_group;" ::: "memory");
}
template <int N>
__device__ __forceinline__ void cp_wait() {
    asm volatile("cp.async.wait_group %0;" :: "n"(N) : "memory");
}

// ---------------------------------------------------------------------------
// split: hi = bf16(x), lo = bf16(x - hi)
// ---------------------------------------------------------------------------
__global__ __launch_bounds__(256)
void split_kernel(const float4* __restrict__ src, int mode, int n4)
{
    int i = blockIdx.x * 256 + threadIdx.x;
    if (i >= n4) return;
    __nv_bfloat16 *hi, *lo;
    if (mode == 0)      { hi = g_xhi; lo = g_xlo; }
    else if (mode == 1) { hi = g_wqh; lo = g_wql; }
    else                { hi = g_wph; lo = g_wpl; }
    float4 v = src[i];
    float a[4] = {v.x, v.y, v.z, v.w};
    ushort h[4], l[4];
    #pragma unroll
    for (int t = 0; t < 4; t++) {
        __nv_bfloat16 hb = __float2bfloat16(a[t]);
        float r = a[t] - __bfloat162float(hb);
        h[t] = __bfloat16_as_ushort(hb);
        l[t] = __bfloat16_as_ushort(__float2bfloat16(r));
    }
    ((ushort4*)hi)[i] = make_ushort4(h[0], h[1], h[2], h[3]);
    ((ushort4*)lo)[i] = make_ushort4(l[0], l[1], l[2], l[3]);
}

// ---------------------------------------------------------------------------
// HMMA bf16-split GEMM with cp.async double-buffered pipeline.
// C[m,n] = sum_k A[m,k]*W[n,k] + bias[n]
// 128x128 tile, BK=32, 8 warps as 2(m)x4(n), warp tile 64x32.
// 3 passes: Ah*Bh + Ah*Bl + Al*Bh, fp32 accum.
// __launch_bounds__(256,2) -> <=128 regs -> 2 CTAs/SM (2x80KB smem).
// ---------------------------------------------------------------------------
#define SROW 80
#define TILE_B (128 * SROW)          // 10240
#define STAGE_B (4 * TILE_B)         // 40960
#define SMEM_ASK (2 * STAGE_B)       // 81920

__global__ __launch_bounds__(256, 2)
void tgemm_kernel(const float* __restrict__ bias, float* __restrict__ Cp,
                  int Nc, int mode)
{
    const __nv_bfloat16 *Ahi, *Alo, *Bhi, *Blo;
    float* C;
    if (mode == 0) { Ahi = g_xhi;  Alo = g_xlo;  Bhi = g_wqh; Blo = g_wql; C = g_qkv; }
    else           { Ahi = g_aohi; Alo = g_aolo; Bhi = g_wph; Blo = g_wpl; C = Cp;    }

    extern __shared__ char smem[];
    const uint32_t ubase = smem_u32(smem);

    const int tid  = threadIdx.x;
    const int wid  = tid >> 5;
    const int lane = tid & 31;
    const int bn   = blockIdx.x;
    const int bm   = blockIdx.y;
    const int wm   = wid & 1;        // 0..1 (m, 64 rows each)
    const int wn   = wid >> 1;       // 0..3 (n, 32 cols each)

    // gmem bases
    const __nv_bfloat16* Ah = Ahi + (size_t)(bm * 128) * KK;
    const __nv_bfloat16* Al = Alo + (size_t)(bm * 128) * KK;
    const __nv_bfloat16* Bh = Bhi + (size_t)(bn * 128) * KK;
    const __nv_bfloat16* Bl = Blo + (size_t)(bn * 128) * KK;

    // cp.async mapping: 256 thr = 64 rows x 4 granules; 2 row-halves per tile
    const int cr = tid >> 2;         // 0..63
    const int cg = tid & 3;          // 0..3

    #define ISSUE(s) do { \
        const uint32_t sb_ = ubase + ((s) & 1) * STAGE_B; \
        const int kof_ = (s) * 32; \
        _Pragma("unroll") \
        for (int t_ = 0; t_ < 2; ++t_) { \
            const int r_ = cr + t_ * 64; \
            const size_t off_ = (size_t)r_ * KK + kof_ + cg * 8; \
            const uint32_t d_ = sb_ + r_ * SROW + cg * 16; \
            cp16(d_ + 0 * TILE_B, Ah + off_); \
            cp16(d_ + 1 * TILE_B, Al + off_); \
            cp16(d_ + 2 * TILE_B, Bh + off_); \
            cp16(d_ + 3 * TILE_B, Bl + off_); \
        } \
        cp_commit(); \
    } while (0)

    float acc[4][4][4];
    #pragma unroll
    for (int i = 0; i < 4; i++)
        #pragma unroll
        for (int j = 0; j < 4; j++)
            #pragma unroll
            for (int q = 0; q < 4; q++) acc[i][j][q] = 0.f;

    // ldmatrix lane addressing
    const int laneRA = lane & 15;            // A: rows (x4)
    const int laneGA = lane >> 4;            // A: k-granule select
    const int laneRB = lane & 7;             // B: rows (x2)
    const int laneGB = (lane >> 3) & 1;      // B: k-granule select

    const int NK = KK / 32;                  // 24 chunks

    ISSUE(0);
    ISSUE(1);

    for (int kb = 0; kb < NK; ++kb) {
        if (kb + 1 < NK) cp_wait<1>(); else cp_wait<0>();
        __syncthreads();

        const uint32_t sb = ubase + (kb & 1) * STAGE_B;
        const uint32_t aBase = sb + (wm * 64 + laneRA) * SROW + laneGA * 16;
        const uint32_t bBase = sb + 2 * TILE_B + (wn * 32 + laneRB) * SROW + laneGB * 16;

        #pragma unroll
        for (int ks = 0; ks < 2; ++ks) {
            const uint32_t ko = ks * 32;
            uint32_t bh[4][2], bl[4][2];
            #pragma unroll
            for (int fn = 0; fn < 4; fn++) {
                ldsm_x2(bh[fn], bBase + fn * (8 * SROW) + ko);
                ldsm_x2(bl[fn], bBase + TILE_B + fn * (8 * SROW) + ko);
            }
            #pragma unroll
            for (int fm = 0; fm < 4; fm++) {
                uint32_t ah[4], al[4];
                ldsm_x4(ah, aBase + fm * (16 * SROW) + ko);
                ldsm_x4(al, aBase + TILE_B + fm * (16 * SROW) + ko);
                #pragma unroll
                for (int fn = 0; fn < 4; fn++) {
                    mma16816(acc[fm][fn], ah, bh[fn]);
                    mma16816(acc[fm][fn], ah, bl[fn]);
                    mma16816(acc[fm][fn], al, bh[fn]);
                }
            }
        }

        if (kb + 2 < NK) {
            __syncthreads();      // all warps done reading this buffer
            ISSUE(kb + 2);        // refill it
        }
    }

    // epilogue: add bias, store fp32
    const int gid4 = lane >> 2;              // 0..7
    const int tig  = lane & 3;               // 0..3
    #pragma unroll
    for (int fm = 0; fm < 4; fm++) {
        const int m0 = bm * 128 + wm * 64 + fm * 16 + gid4;
        #pragma unroll
        for (int fn = 0; fn < 4; fn++) {
            const int col = bn * 128 + wn * 32 + fn * 8 + tig * 2;
            const float bx = bias[col], by = bias[col + 1];
            float2 o;
            o.x = acc[fm][fn][0] + bx; o.y = acc[fm][fn][1] + by;
            *(float2*)(C + (size_t)m0 * Nc + col) = o;
            o.x = acc[fm][fn][2] + bx; o.y = acc[fm][fn][3] + by;
            *(float2*)(C + (size_t)(m0 + 8) * Nc + col) = o;
        }
    }
    #undef ISSUE
}

// ---------------------------------------------------------------------------
// Attention logits + softmax, one block per (b,h).
// ---------------------------------------------------------------------------
__global__ __launch_bounds__(256)
void attn_softmax_kernel()
{
    const int bh = blockIdx.x;
    const int b  = bh >> 3, h = bh & 7;

    __shared__ float sm[96 * 96];
    float* Qs = sm;
    float* Ks = sm + 32 * 96;

    const int tid = threadIdx.x;
    const int tx  = tid & 15;
    const int ty  = tid >> 4;

    float acc[6][6];
    #pragma unroll
    for (int i = 0; i < 6; i++)
        #pragma unroll
        for (int j = 0; j < 6; j++) acc[i][j] = 0.f;

    const float* qbase = g_qkv + (size_t)(b * NN) * C3 + h * DD;

    for (int n0 = 0; n0 < NN; n0 += 32) {
        #pragma unroll
        for (int t = 0; t < 3; ++t) {
            const int id = tid + t * 256;
            const int r  = id / 24;
            const int c4 = (id % 24) * 4;
            const float* qp = qbase + (size_t)(n0 + r) * C3 + c4;
            *(float4*)&Qs[r * 96 + c4] = *(const float4*)qp;
            *(float4*)&Ks[r * 96 + c4] = *(const float4*)(qp + CC);
        }
        __syncthreads();
        #pragma unroll 8
        for (int kk = 0; kk < 32; ++kk) {
            float qr[6], kr[6];
            #pragma unroll
            for (int i = 0; i < 6; i++) qr[i] = Qs[kk * 96 + ty * 6 + i];
            #pragma unroll
            for (int j = 0; j < 6; j++) kr[j] = Ks[kk * 96 + tx * 6 + j];
            #pragma unroll
            for (int i = 0; i < 6; i++)
                #pragma unroll
                for (int j = 0; j < 6; j++)
                    acc[i][j] = fmaf(qr[i], kr[j], acc[i][j]);
        }
        __syncthreads();
    }

    const float scale = 0.015625f;
    #pragma unroll
    for (int i = 0; i < 6; i++)
        #pragma unroll
        for (int j = 0; j < 6; j++)
            sm[(ty * 6 + i) * 96 + tx * 6 + j] = acc[i][j] * scale;
    __syncthreads();

    const int wid = tid >> 5, lane = tid & 31;
    for (int r = wid; r < 96; r += 8) {
        float v0 = sm[r * 96 + lane];
        float v1 = sm[r * 96 + 32 + lane];
        float v2 = sm[r * 96 + 64 + lane];
        float m = fmaxf(v0, fmaxf(v1, v2));
        #pragma unroll
        for (int off = 16; off > 0; off >>= 1)
            m = fmaxf(m, __shfl_xor_sync(0xffffffffu, m, off));
        float e0 = expf(v0 - m), e1 = expf(v1 - m), e2 = expf(v2 - m);
        float s = e0 + e1 + e2;
        #pragma unroll
        for (int off = 16; off > 0; off >>= 1)
            s += __shfl_xor_sync(0xffffffffu, s, off);
        const float inv = 1.f / s;
        float* arow = g_attn + ((size_t)bh * 96 + r) * 96;
        arow[lane]      = e0 * inv;
        arow[lane + 32] = e1 * inv;
        arow[lane + 64] = e2 * inv;
    }
}

// ---------------------------------------------------------------------------
// out[n,d] = sum_e attn[d,e] v[n,e]; epilogue emits bf16 hi/lo splits.
// ---------------------------------------------------------------------------
__global__ __launch_bounds__(256)
void av_kernel()
{
    const int nt = blockIdx.x;
    const int bh = blockIdx.y;
    const int b  = bh >> 3, h = bh & 7;

    __shared__ float at[96 * 97];
    __shared__ float Vs[128 * 20];

    const int tid = threadIdx.x;
    const int tx  = tid & 15;
    const int ty  = tid >> 4;

    const float* asrc = g_attn + (size_t)bh * 9216;
    for (int id = tid; id < 96 * 96; id += 256) {
        const int r = id / 96, c = id - r * 96;
        at[r * 97 + c] = asrc[id];
    }

    float acc[8][6];
    #pragma unroll
    for (int i = 0; i < 8; i++)
        #pragma unroll
        for (int j = 0; j < 6; j++) acc[i][j] = 0.f;

    const float* vbase = g_qkv + (size_t)(b * NN + nt * 128) * C3 + 2 * CC + h * DD;

    for (int e0 = 0; e0 < 96; e0 += 16) {
        __syncthreads();
        #pragma unroll
        for (int t = 0; t < 2; ++t) {
            const int id = tid + t * 256;
            const int r  = id >> 2;
            const int c4 = (id & 3) * 4;
            *(float4*)&Vs[r * 20 + c4] =
                *(const float4*)(vbase + (size_t)r * C3 + e0 + c4);
        }
        __syncthreads();
        #pragma unroll
        for (int e = 0; e < 16; ++e) {
            float av[6], vv[8];
            #pragma unroll
            for (int j = 0; j < 6; j++) av[j] = at[(tx * 6 + j) * 97 + e0 + e];
            #pragma unroll
            for (int i = 0; i < 8; i++) vv[i] = Vs[(ty * 8 + i) * 20 + e];
            #pragma unroll
            for (int i = 0; i < 8; i++)
                #pragma unroll
                for (int j = 0; j < 6; j++)
                    acc[i][j] = fmaf(vv[i], av[j], acc[i][j]);
        }
    }

    #pragma unroll
    for (int i = 0; i < 8; i++) {
        const size_t row = (size_t)(b * NN + nt * 128 + ty * 8 + i);
        const size_t obase = row * CC + h * DD + tx * 6;
        #pragma unroll
        for (int j = 0; j < 6; j++) {
            float v = acc[i][j];
            __nv_bfloat16 hb = __float2bfloat16(v);
            float r = v - __bfloat162float(hb);
            g_aohi[obase + j] = hb;
            g_aolo[obase + j] = __float2bfloat16(r);
        }
    }
}

// ---------------------------------------------------------------------------
extern "C" void kernel_launch(void* const* d_in, const int* in_sizes, int n_in,
                              void* d_out, int out_size)
{
    const float* x      = (const float*)d_in[0];
    const float* w_qkv  = (const float*)d_in[1];
    const float* b_qkv  = (const float*)d_in[2];
    const float* w_proj = (const float*)d_in[3];
    const float* b_proj = (const float*)d_in[4];
    float*       out    = (float*)d_out;

    cudaFuncSetAttribute(tgemm_kernel,
                         cudaFuncAttributeMaxDynamicSharedMemorySize, SMEM_ASK);

    // 0) bf16 hi/lo splits
    split_kernel<<<(MM * CC / 4) / 256, 256>>>((const float4*)x, 0, MM * CC / 4);
    split_kernel<<<(C3 * CC / 4) / 256, 256>>>((const float4*)w_qkv, 1, C3 * CC / 4);
    split_kernel<<<(CC * CC / 4) / 256, 256>>>((const float4*)w_proj, 2, CC * CC / 4);

    // 1) qkv = x @ w_qkv^T + b_qkv -> g_qkv (HMMA bf16-split)
    {
        dim3 grid(C3 / 128, MM / 128);
        tgemm_kernel<<<grid, 256, SMEM_ASK>>>(b_qkv, nullptr, C3, 0);
    }
    // 2) logits + softmax -> g_attn
    attn_softmax_kernel<<<BB * HH, 256>>>();
    // 3) attn-weighted v -> ao splits
    {
        dim3 grid(NN / 128, BB * HH);
        av_kernel<<<grid, 256>>>();
    }
    // 4) out = ao @ w_proj^T + b_proj (HMMA bf16-split)
    {
        dim3 grid(CC / 128, MM / 128);
        tgemm_kernel<<<grid, 256, SMEM_ASK>>>(b_proj, out, CC, 1);
    }
}

// round 5
// speedup vs baseline: 4.1840x; 1.7992x over previous
#include <cuda_runtime.h>
#include <cuda_bf16.h>
#include <cstdint>

// Problem constants
#define BB   16
#define NT   4096
#define CC   768
#define HH   8
#define DD   96
#define MM   (BB * NT)          // 65536
#define GSZ  (768 * 768)        // 589824

// ---------------------------------------------------------------------------
// Scratch (__device__ globals)
// ---------------------------------------------------------------------------
__device__ __nv_bfloat16 g_xhi[(size_t)MM * CC], g_xlo[(size_t)MM * CC];
__device__ __nv_bfloat16 g_xThi[(size_t)MM * CC], g_xTlo[(size_t)MM * CC]; // [b,c,n]
__device__ float g_G[BB * GSZ];
__device__ __nv_bfloat16 g_Ghi[BB * GSZ], g_Glo[BB * GSZ];
__device__ float g_T[BB * GSZ];
__device__ float g_attn[BB * HH * DD * DD];
__device__ float g_MT[BB * GSZ];                 // [b, c, h*96+d]
__device__ __nv_bfloat16 g_MThi[BB * GSZ], g_MTlo[BB * GSZ];
__device__ float g_P[BB * GSZ];
__device__ __nv_bfloat16 g_Phi[BB * GSZ], g_Plo[BB * GSZ];
__device__ __nv_bfloat16 g_wqh[GSZ], g_wql[GSZ]; // Wq rows only
__device__ __nv_bfloat16 g_wph[GSZ], g_wpl[GSZ];
__device__ float g_s[BB * CC];
__device__ float g_part[BB * 32 * CC];
__device__ float g_U[BB * 1536];
__device__ float g_r[BB * CC];
__device__ float g_biasf[BB * CC];

// ---------------------------------------------------------------------------
// PTX helpers (target-agnostic)
// ---------------------------------------------------------------------------
__device__ __forceinline__ uint32_t smem_u32(const void* p) {
    uint32_t a;
    asm("{ .reg .u64 t; cvta.to.shared.u64 t, %1; cvt.u32.u64 %0, t; }"
        : "=r"(a) : "l"(p));
    return a;
}
__device__ __forceinline__ void ldsm_x4(uint32_t* r, uint32_t addr) {
    asm volatile("ldmatrix.sync.aligned.m8n8.x4.shared.b16 {%0,%1,%2,%3}, [%4];"
                 : "=r"(r[0]), "=r"(r[1]), "=r"(r[2]), "=r"(r[3]) : "r"(addr));
}
__device__ __forceinline__ void ldsm_x2(uint32_t* r, uint32_t addr) {
    asm volatile("ldmatrix.sync.aligned.m8n8.x2.shared.b16 {%0,%1}, [%2];"
                 : "=r"(r[0]), "=r"(r[1]) : "r"(addr));
}
__device__ __forceinline__ void mma16816(float* c, const uint32_t* a, const uint32_t* b) {
    asm volatile(
        "mma.sync.aligned.m16n8k16.row.col.f32.bf16.bf16.f32 "
        "{%0,%1,%2,%3}, {%4,%5,%6,%7}, {%8,%9}, {%0,%1,%2,%3};"
        : "+f"(c[0]), "+f"(c[1]), "+f"(c[2]), "+f"(c[3])
        : "r"(a[0]), "r"(a[1]), "r"(a[2]), "r"(a[3]), "r"(b[0]), "r"(b[1]));
}
__device__ __forceinline__ void cp16(uint32_t dst, const void* src) {
    asm volatile("cp.async.cg.shared.global [%0], [%1], 16;"
                 :: "r"(dst), "l"(src) : "memory");
}
__device__ __forceinline__ void cp_commit() {
    asm volatile("cp.async.commit_group;" ::: "memory");
}
template <int N>
__device__ __forceinline__ void cp_wait() {
    asm volatile("cp.async.wait_group %0;" :: "n"(N) : "memory");
}
__device__ __forceinline__ void split1(float v, __nv_bfloat16& h, __nv_bfloat16& l) {
    h = __float2bfloat16(v);
    l = __float2bfloat16(v - __bfloat162float(h));
}

// ---------------------------------------------------------------------------
// transpose_split: x -> row-major hi/lo AND per-batch transposed hi/lo
// grid (12, 1024), block 256. tile 64n x 64c.
// ---------------------------------------------------------------------------
__global__ __launch_bounds__(256)
void transpose_split_kernel(const float* __restrict__ x)
{
    __shared__ float tile[64 * 65];
    const int tid = threadIdx.x;
    const int C0 = blockIdx.x * 64;
    const int R0 = blockIdx.y * 64;

    #pragma unroll
    for (int t = 0; t < 4; ++t) {
        const int id = tid + t * 256;        // 0..1023
        const int r = id >> 4, f4 = id & 15;
        float4 v = *(const float4*)(x + (size_t)(R0 + r) * CC + C0 + f4 * 4);
        tile[r * 65 + f4 * 4 + 0] = v.x;
        tile[r * 65 + f4 * 4 + 1] = v.y;
        tile[r * 65 + f4 * 4 + 2] = v.z;
        tile[r * 65 + f4 * 4 + 3] = v.w;
    }
    __syncthreads();

    // row-major hi/lo
    #pragma unroll
    for (int t = 0; t < 2; ++t) {
        const int id = tid + t * 256;        // 0..511
        const int r = id >> 3, g = id & 7;
        ushort h[8], l[8];
        #pragma unroll
        for (int j = 0; j < 8; j++) {
            float v = tile[r * 65 + g * 8 + j];
            __nv_bfloat16 hb, lb; split1(v, hb, lb);
            h[j] = __bfloat16_as_ushort(hb); l[j] = __bfloat16_as_ushort(lb);
        }
        uint4 uh, ul;
        uh.x = h[0] | (h[1] << 16); uh.y = h[2] | (h[3] << 16);
        uh.z = h[4] | (h[5] << 16); uh.w = h[6] | (h[7] << 16);
        ul.x = l[0] | (l[1] << 16); ul.y = l[2] | (l[3] << 16);
        ul.z = l[4] | (l[5] << 16); ul.w = l[6] | (l[7] << 16);
        const size_t off = (size_t)(R0 + r) * CC + C0 + g * 8;
        *(uint4*)(g_xhi + off) = uh;
        *(uint4*)(g_xlo + off) = ul;
    }

    // transposed hi/lo: [b, c, n]
    const int bb = R0 >> 12;
    const int n0 = R0 & 4095;
    #pragma unroll
    for (int t = 0; t < 2; ++t) {
        const int id = tid + t * 256;
        const int c = id >> 3, g = id & 7;
        ushort h[8], l[8];
        #pragma unroll
        for (int j = 0; j < 8; j++) {
            float v = tile[(g * 8 + j) * 65 + c];
            __nv_bfloat16 hb, lb; split1(v, hb, lb);
            h[j] = __bfloat16_as_ushort(hb); l[j] = __bfloat16_as_ushort(lb);
        }
        uint4 uh, ul;
        uh.x = h[0] | (h[1] << 16); uh.y = h[2] | (h[3] << 16);
        uh.z = h[4] | (h[5] << 16); uh.w = h[6] | (h[7] << 16);
        ul.x = l[0] | (l[1] << 16); ul.y = l[2] | (l[3] << 16);
        ul.z = l[4] | (l[5] << 16); ul.w = l[6] | (l[7] << 16);
        const size_t off = ((size_t)bb * CC + C0 + c) * NT + n0 + g * 8;
        *(uint4*)(g_xThi + off) = uh;
        *(uint4*)(g_xTlo + off) = ul;
    }
}

// ---------------------------------------------------------------------------
// split: generic hi/lo splitter. mode 1: wq, 2: wp, 3: G, 4: MT, 5: P
// ---------------------------------------------------------------------------
__global__ __launch_bounds__(256)
void split_kernel(const float4* __restrict__ srcp, int mode, int n4)
{
    int i = blockIdx.x * 256 + threadIdx.x;
    if (i >= n4) return;
    const float4* src = srcp;
    __nv_bfloat16 *hi, *lo;
    if (mode == 1)      { hi = g_wqh;  lo = g_wql; }
    else if (mode == 2) { hi = g_wph;  lo = g_wpl; }
    else if (mode == 3) { hi = g_Ghi;  lo = g_Glo;  src = (const float4*)g_G; }
    else if (mode == 4) { hi = g_MThi; lo = g_MTlo; src = (const float4*)g_MT; }
    else                { hi = g_Phi;  lo = g_Plo;  src = (const float4*)g_P; }
    float4 v = src[i];
    float a[4] = {v.x, v.y, v.z, v.w};
    ushort h[4], l[4];
    #pragma unroll
    for (int t = 0; t < 4; t++) {
        __nv_bfloat16 hb, lb; split1(a[t], hb, lb);
        h[t] = __bfloat16_as_ushort(hb); l[t] = __bfloat16_as_ushort(lb);
    }
    ((ushort4*)hi)[i] = make_ushort4(h[0], h[1], h[2], h[3]);
    ((ushort4*)lo)[i] = make_ushort4(l[0], l[1], l[2], l[3]);
}

// ---------------------------------------------------------------------------
// column sums of x per batch (2-stage, deterministic)
// ---------------------------------------------------------------------------
__global__ __launch_bounds__(256)
void colsum_part_kernel(const float* __restrict__ x)
{
    const int blk = blockIdx.x, b = blockIdx.y, tid = threadIdx.x;
    const size_t base = ((size_t)b * NT + blk * 128) * CC;
    float acc[3] = {0.f, 0.f, 0.f};
    for (int r = 0; r < 128; ++r) {
        const float* row = x + base + (size_t)r * CC;
        #pragma unroll
        for (int p = 0; p < 3; ++p) acc[p] += row[p * 256 + tid];
    }
    #pragma unroll
    for (int p = 0; p < 3; ++p)
        g_part[((size_t)(b * 32 + blk)) * CC + p * 256 + tid] = acc[p];
}
__global__ void colsum_red_kernel()
{
    const int b = blockIdx.x, tid = threadIdx.x;   // block 768
    float s = 0.f;
    for (int k = 0; k < 32; ++k) s += g_part[((size_t)(b * 32 + k)) * CC + tid];
    g_s[b * CC + tid] = s;
}

// ---------------------------------------------------------------------------
// U[b][row] = dot(w_qkv[row], s_b) for rows 0..1535 (Wq|Wk blocks)
// grid (192, 16), block 256 (8 warps = 8 rows)
// ---------------------------------------------------------------------------
__global__ __launch_bounds__(256)
void uw_kernel(const float* __restrict__ w_qkv)
{
    __shared__ float ss[CC];
    const int b = blockIdx.y, tid = threadIdx.x;
    #pragma unroll
    for (int p = 0; p < 3; ++p) ss[p * 256 + tid] = g_s[b * CC + p * 256 + tid];
    __syncthreads();
    const int row = blockIdx.x * 8 + (tid >> 5);
    const int lane = tid & 31;
    const float* wr = w_qkv + (size_t)row * CC;
    float acc = 0.f;
    #pragma unroll
    for (int k = 0; k < 24; ++k) acc += wr[lane + k * 32] * ss[lane + k * 32];
    #pragma unroll
    for (int off = 16; off > 0; off >>= 1)
        acc += __shfl_xor_sync(0xffffffffu, acc, off);
    if (lane == 0) g_U[b * 1536 + row] = acc;
}

// ---------------------------------------------------------------------------
// biasf[b][j] = b_proj[j] + dot(w_proj[j], r_b).  grid (96, 16), block 256.
// ---------------------------------------------------------------------------
__global__ __launch_bounds__(256)
void biasf_kernel(const float* __restrict__ w_proj, const float* __restrict__ b_proj)
{
    __shared__ float rr[CC];
    const int b = blockIdx.y, tid = threadIdx.x;
    #pragma unroll
    for (int p = 0; p < 3; ++p) rr[p * 256 + tid] = g_r[b * CC + p * 256 + tid];
    __syncthreads();
    const int j = blockIdx.x * 8 + (tid >> 5);
    const int lane = tid & 31;
    const float* wr = w_proj + (size_t)j * CC;
    float acc = 0.f;
    #pragma unroll
    for (int k = 0; k < 24; ++k) acc += wr[lane + k * 32] * rr[lane + k * 32];
    #pragma unroll
    for (int off = 16; off > 0; off >>= 1)
        acc += __shfl_xor_sync(0xffffffffu, acc, off);
    if (lane == 0) g_biasf[b * CC + j] = b_proj[j] + acc;
}

// ---------------------------------------------------------------------------
// HMMA bf16-split GEMM, parameterized.
//   mode 0: G_b = Xt_b @ Xt_b^T      (K=4096, per-batch z)
//   mode 1: T_b = Wq @ G_b           (K=768, G symmetric)
//   mode 2: P_b = Wp @ MT_b          (K=768)
//   mode 3: out = X @ P_b^T + biasf  (K=768, grid (6, 512))
// ---------------------------------------------------------------------------
#define SROW 80
#define TILE_B (128 * SROW)
#define STAGE_B (4 * TILE_B)
#define SMEM_ASK (2 * STAGE_B)

__global__ __launch_bounds__(256, 2)
void tgemm_kernel(float* __restrict__ Cp, int mode)
{
    const int bn = blockIdx.x;
    const int bm = blockIdx.y;
    int b = blockIdx.z;

    const __nv_bfloat16 *Ah, *Al, *Wh, *Wl;
    float* C;
    const float* bias = nullptr;
    int K;

    if (mode == 0) {
        K = 4096;
        const size_t ab = ((size_t)b * CC + bm * 128) * NT;
        const size_t wb = ((size_t)b * CC + bn * 128) * NT;
        Ah = g_xThi + ab; Al = g_xTlo + ab;
        Wh = g_xThi + wb; Wl = g_xTlo + wb;
        C = g_G + (size_t)b * GSZ;
    } else if (mode == 1) {
        K = 768;
        Ah = g_wqh + (size_t)bm * 128 * CC; Al = g_wql + (size_t)bm * 128 * CC;
        const size_t wb = (size_t)b * GSZ + (size_t)bn * 128 * CC;
        Wh = g_Ghi + wb; Wl = g_Glo + wb;
        C = g_T + (size_t)b * GSZ;
    } else if (mode == 2) {
        K = 768;
        Ah = g_wph + (size_t)bm * 128 * CC; Al = g_wpl + (size_t)bm * 128 * CC;
        const size_t wb = (size_t)b * GSZ + (size_t)bn * 128 * CC;
        Wh = g_MThi + wb; Wl = g_MTlo + wb;
        C = g_P + (size_t)b * GSZ;
    } else {
        K = 768;
        b = bm >> 5;
        const size_t ab = (size_t)bm * 128 * CC;
        Ah = g_xhi + ab; Al = g_xlo + ab;
        const size_t wb = (size_t)b * GSZ + (size_t)bn * 128 * CC;
        Wh = g_Phi + wb; Wl = g_Plo + wb;
        bias = g_biasf + b * CC;
        C = Cp;
    }

    extern __shared__ char smem[];
    const uint32_t ubase = smem_u32(smem);

    const int tid  = threadIdx.x;
    const int wid  = tid >> 5;
    const int lane = tid & 31;
    const int wm   = wid & 1;
    const int wn   = wid >> 1;

    const int cr = tid >> 2;
    const int cg = tid & 3;

    #define ISSUE(s) do { \
        const uint32_t sb_ = ubase + ((s) & 1) * STAGE_B; \
        const int kof_ = (s) * 32; \
        _Pragma("unroll") \
        for (int t_ = 0; t_ < 2; ++t_) { \
            const int r_ = cr + t_ * 64; \
            const size_t off_ = (size_t)r_ * K + kof_ + cg * 8; \
            const uint32_t d_ = sb_ + r_ * SROW + cg * 16; \
            cp16(d_ + 0 * TILE_B, Ah + off_); \
            cp16(d_ + 1 * TILE_B, Al + off_); \
            cp16(d_ + 2 * TILE_B, Wh + off_); \
            cp16(d_ + 3 * TILE_B, Wl + off_); \
        } \
        cp_commit(); \
    } while (0)

    float acc[4][4][4];
    #pragma unroll
    for (int i = 0; i < 4; i++)
        #pragma unroll
        for (int j = 0; j < 4; j++)
            #pragma unroll
            for (int q = 0; q < 4; q++) acc[i][j][q] = 0.f;

    const int laneRA = lane & 15;
    const int laneGA = lane >> 4;
    const int laneRB = lane & 7;
    const int laneGB = (lane >> 3) & 1;

    const int NK = K >> 5;

    ISSUE(0);
    ISSUE(1);

    for (int kb = 0; kb < NK; ++kb) {
        if (kb + 1 < NK) cp_wait<1>(); else cp_wait<0>();
        __syncthreads();

        const uint32_t sb = ubase + (kb & 1) * STAGE_B;
        const uint32_t aBase = sb + (wm * 64 + laneRA) * SROW + laneGA * 16;
        const uint32_t bBase = sb + 2 * TILE_B + (wn * 32 + laneRB) * SROW + laneGB * 16;

        #pragma unroll
        for (int ks = 0; ks < 2; ++ks) {
            const uint32_t ko = ks * 32;
            uint32_t bh[4][2], bl[4][2];
            #pragma unroll
            for (int fn = 0; fn < 4; fn++) {
                ldsm_x2(bh[fn], bBase + fn * (8 * SROW) + ko);
                ldsm_x2(bl[fn], bBase + TILE_B + fn * (8 * SROW) + ko);
            }
            #pragma unroll
            for (int fm = 0; fm < 4; fm++) {
                uint32_t ah[4], al[4];
                ldsm_x4(ah, aBase + fm * (16 * SROW) + ko);
                ldsm_x4(al, aBase + TILE_B + fm * (16 * SROW) + ko);
                #pragma unroll
                for (int fn = 0; fn < 4; fn++) {
                    mma16816(acc[fm][fn], ah, bh[fn]);
                    mma16816(acc[fm][fn], ah, bl[fn]);
                    mma16816(acc[fm][fn], al, bh[fn]);
                }
            }
        }

        if (kb + 2 < NK) {
            __syncthreads();
            ISSUE(kb + 2);
        }
    }

    const int gid4 = lane >> 2;
    const int tig  = lane & 3;
    #pragma unroll
    for (int fm = 0; fm < 4; fm++) {
        const int m0 = bm * 128 + wm * 64 + fm * 16 + gid4;
        #pragma unroll
        for (int fn = 0; fn < 4; fn++) {
            const int col = bn * 128 + wn * 32 + fn * 8 + tig * 2;
            float bx = 0.f, by = 0.f;
            if (bias) { bx = bias[col]; by = bias[col + 1]; }
            float2 o;
            o.x = acc[fm][fn][0] + bx; o.y = acc[fm][fn][1] + by;
            *(float2*)(C + (size_t)m0 * CC + col) = o;
            o.x = acc[fm][fn][2] + bx; o.y = acc[fm][fn][3] + by;
            *(float2*)(C + (size_t)(m0 + 8) * CC + col) = o;
        }
    }
    #undef ISSUE
}

// ---------------------------------------------------------------------------
// logits + softmax per (b,h):
// logits[d,e] = (T_bh[d,:]·Wk_h[e,:] + bq_d·u_e + bk_e·w_d + N·bq_d·bk_e)/64
// attn = softmax_e(logits). grid 128, block 256.
// ---------------------------------------------------------------------------
__global__ __launch_bounds__(256)
void logits_kernel(const float* __restrict__ w_qkv, const float* __restrict__ b_qkv)
{
    const int bh = blockIdx.x;
    const int b = bh >> 3, h = bh & 7;

    __shared__ float buf[9312];              // stage Ts/Ks, then logits 96x96
    __shared__ float bqs[96], bks[96], us_[96], ws_[96];

    const int tid = threadIdx.x;
    const int tx = tid & 15;
    const int ty = tid >> 4;

    if (tid < 96) {
        bqs[tid] = b_qkv[h * DD + tid];
        bks[tid] = b_qkv[CC + h * DD + tid];
        ws_[tid] = g_U[b * 1536 + h * DD + tid];
        us_[tid] = g_U[b * 1536 + CC + h * DD + tid];
    }

    const float* Tb = g_T + (size_t)b * GSZ + (size_t)(h * DD) * CC;
    const float* Wk = w_qkv + (size_t)(CC + h * DD) * CC;

    float acc[6][6];
    #pragma unroll
    for (int i = 0; i < 6; i++)
        #pragma unroll
        for (int j = 0; j < 6; j++) acc[i][j] = 0.f;

    for (int c0 = 0; c0 < CC; c0 += 32) {
        __syncthreads();
        #pragma unroll
        for (int t = 0; t < 3; ++t) {
            const int id = tid + t * 256;           // 0..767
            const int row = id >> 3, f4 = id & 7;
            float4 tv = *(const float4*)(Tb + (size_t)row * CC + c0 + f4 * 4);
            float4 kv = *(const float4*)(Wk + (size_t)row * CC + c0 + f4 * 4);
            buf[(f4 * 4 + 0) * 97 + row] = tv.x;
            buf[(f4 * 4 + 1) * 97 + row] = tv.y;
            buf[(f4 * 4 + 2) * 97 + row] = tv.z;
            buf[(f4 * 4 + 3) * 97 + row] = tv.w;
            buf[3104 + (f4 * 4 + 0) * 97 + row] = kv.x;
            buf[3104 + (f4 * 4 + 1) * 97 + row] = kv.y;
            buf[3104 + (f4 * 4 + 2) * 97 + row] = kv.z;
            buf[3104 + (f4 * 4 + 3) * 97 + row] = kv.w;
        }
        __syncthreads();
        #pragma unroll 8
        for (int kk = 0; kk < 32; ++kk) {
            float qr[6], kr[6];
            #pragma unroll
            for (int i = 0; i < 6; i++) qr[i] = buf[kk * 97 + ty * 6 + i];
            #pragma unroll
            for (int j = 0; j < 6; j++) kr[j] = buf[3104 + kk * 97 + tx * 6 + j];
            #pragma unroll
            for (int i = 0; i < 6; i++)
                #pragma unroll
                for (int j = 0; j < 6; j++)
                    acc[i][j] = fmaf(qr[i], kr[j], acc[i][j]);
        }
    }
    __syncthreads();

    const float scale = 0.015625f;           // 4096^-0.5
    #pragma unroll
    for (int i = 0; i < 6; i++) {
        const int d = ty * 6 + i;
        #pragma unroll
        for (int j = 0; j < 6; j++) {
            const int e = tx * 6 + j;
            float v = acc[i][j] + bqs[d] * us_[e] + bks[e] * ws_[d]
                      + 4096.f * bqs[d] * bks[e];
            buf[d * 96 + e] = v * scale;
        }
    }
    __syncthreads();

    const int wid = tid >> 5, lane = tid & 31;
    for (int r = wid; r < 96; r += 8) {
        float v0 = buf[r * 96 + lane];
        float v1 = buf[r * 96 + 32 + lane];
        float v2 = buf[r * 96 + 64 + lane];
        float m = fmaxf(v0, fmaxf(v1, v2));
        #pragma unroll
        for (int off = 16; off > 0; off >>= 1)
            m = fmaxf(m, __shfl_xor_sync(0xffffffffu, m, off));
        float e0 = expf(v0 - m), e1 = expf(v1 - m), e2 = expf(v2 - m);
        float s = e0 + e1 + e2;
        #pragma unroll
        for (int off = 16; off > 0; off >>= 1)
            s += __shfl_xor_sync(0xffffffffu, s, off);
        const float inv = 1.f / s;
        float* arow = g_attn + ((size_t)bh * 96 + r) * 96;
        arow[lane]      = e0 * inv;
        arow[lane + 32] = e1 * inv;
        arow[lane + 64] = e2 * inv;
    }
}

// ---------------------------------------------------------------------------
// MT_b[c, h*96+d] = sum_e A_bh[d,e] * Wv[h*96+e, c];  r_bh = A_bh @ bv_h
// grid 128, block 256.
// ---------------------------------------------------------------------------
__global__ __launch_bounds__(256)
void mt_kernel(const float* __restrict__ w_qkv, const float* __restrict__ b_qkv)
{
    const int bh = blockIdx.x;
    const int b = bh >> 3, h = bh & 7;

    __shared__ float As[96 * 97];
    __shared__ float Ws[16 * 132];
    __shared__ float bvs[96];

    const int tid = threadIdx.x;
    const int tx = tid & 15;     // d (6 each)
    const int ty = tid >> 4;     // c (8 each)

    const float* asrc = g_attn + (size_t)bh * 9216;
    for (int id = tid; id < 9216; id += 256) {
        const int r = id / 96, c = id - r * 96;
        As[r * 97 + c] = asrc[id];
    }
    if (tid < 96) bvs[tid] = b_qkv[2 * CC + h * DD + tid];
    __syncthreads();

    if (tid < 96) {
        float rv = 0.f;
        #pragma unroll 4
        for (int e = 0; e < 96; ++e) rv += As[tid * 97 + e] * bvs[e];
        g_r[b * CC + h * DD + tid] = rv;
    }

    const float* Wv = w_qkv + (size_t)(2 * CC + h * DD) * CC;
    float* MTb = g_MT + (size_t)b * GSZ;

    for (int c0 = 0; c0 < CC; c0 += 128) {
        float acc[8][6];
        #pragma unroll
        for (int i = 0; i < 8; i++)
            #pragma unroll
            for (int j = 0; j < 6; j++) acc[i][j] = 0.f;

        for (int e0 = 0; e0 < 96; e0 += 16) {
            __syncthreads();
            #pragma unroll
            for (int t = 0; t < 2; ++t) {
                const int id = tid + t * 256;       // 0..511
                const int e = id >> 5, f4 = id & 31;
                float4 v = *(const float4*)(Wv + (size_t)(e0 + e) * CC + c0 + f4 * 4);
                *(float4*)&Ws[e * 132 + f4 * 4] = v;
            }
            __syncthreads();
            #pragma unroll
            for (int e = 0; e < 16; ++e) {
                float vv[8], aa[6];
                #pragma unroll
                for (int i = 0; i < 8; i++) vv[i] = Ws[e * 132 + ty * 8 + i];
                #pragma unroll
                for (int j = 0; j < 6; j++) aa[j] = As[(tx * 6 + j) * 97 + e0 + e];
                #pragma unroll
                for (int i = 0; i < 8; i++)
                    #pragma unroll
                    for (int j = 0; j < 6; j++)
                        acc[i][j] = fmaf(vv[i], aa[j], acc[i][j]);
            }
        }
        #pragma unroll
        for (int i = 0; i < 8; i++) {
            const int c = c0 + ty * 8 + i;
            float* orow = MTb + (size_t)c * CC + h * DD + tx * 6;
            #pragma unroll
            for (int j = 0; j < 6; j += 2)
                *(float2*)(orow + j) = make_float2(acc[i][j], acc[i][j + 1]);
        }
    }
}

// ---------------------------------------------------------------------------
extern "C" void kernel_launch(void* const* d_in, const int* in_sizes, int n_in,
                              void* d_out, int out_size)
{
    const float* x      = (const float*)d_in[0];
    const float* w_qkv  = (const float*)d_in[1];
    const float* b_qkv  = (const float*)d_in[2];
    const float* w_proj = (const float*)d_in[3];
    const float* b_proj = (const float*)d_in[4];
    float*       out    = (float*)d_out;

    cudaFuncSetAttribute(tgemm_kernel,
                         cudaFuncAttributeMaxDynamicSharedMemorySize, SMEM_ASK);

    // 0) splits + transposed splits + column sums
    transpose_split_kernel<<<dim3(12, 1024), 256>>>(x);
    colsum_part_kernel<<<dim3(32, BB), 256>>>(x);
    colsum_red_kernel<<<BB, 768>>>();
    split_kernel<<<576, 256>>>((const float4*)w_qkv, 1, GSZ / 4);
    split_kernel<<<576, 256>>>((const float4*)w_proj, 2, GSZ / 4);

    // 1) G_b = X_b^T X_b
    tgemm_kernel<<<dim3(6, 6, BB), 256, SMEM_ASK>>>(nullptr, 0);
    split_kernel<<<9216, 256>>>(nullptr, 3, BB * GSZ / 4);

    // 2) T_b = Wq @ G_b
    tgemm_kernel<<<dim3(6, 6, BB), 256, SMEM_ASK>>>(nullptr, 1);

    // 3) rank-1 correction dots, logits + softmax
    uw_kernel<<<dim3(192, BB), 256>>>(w_qkv);
    logits_kernel<<<BB * HH, 256>>>(w_qkv, b_qkv);

    // 4) MT_b = (A @ Wv)^T stacked; r_bh
    mt_kernel<<<BB * HH, 256>>>(w_qkv, b_qkv);
    split_kernel<<<9216, 256>>>(nullptr, 4, BB * GSZ / 4);

    // 5) P_b = Wp @ MT_b; fused output bias
    biasf_kernel<<<dim3(96, BB), 256>>>(w_proj, b_proj);
    tgemm_kernel<<<dim3(6, 6, BB), 256, SMEM_ASK>>>(nullptr, 2);
    split_kernel<<<9216, 256>>>(nullptr, 5, BB * GSZ / 4);

    // 6) out = X @ P_b^T + biasf
    tgemm_kernel<<<dim3(6, 512, 1), 256, SMEM_ASK>>>(out, 3);
}

// round 6
// speedup vs baseline: 4.6618x; 1.1142x over previous
#include <cuda_runtime.h>
#include <cuda_bf16.h>
#include <cstdint>

// Problem constants
#define BB   16
#define NT   4096
#define CC   768
#define HH   8
#define DD   96
#define MM   (BB * NT)          // 65536
#define GSZ  (768 * 768)        // 589824

// ---------------------------------------------------------------------------
// Scratch (__device__ globals)
// ---------------------------------------------------------------------------
__device__ __nv_bfloat16 g_xhi[(size_t)MM * CC], g_xlo[(size_t)MM * CC];
__device__ __nv_bfloat16 g_xThi[(size_t)MM * CC], g_xTlo[(size_t)MM * CC]; // [b,c,n]
__device__ __nv_bfloat16 g_Ghi[BB * GSZ], g_Glo[BB * GSZ];
__device__ float g_T[BB * GSZ];
__device__ float g_attn[BB * HH * DD * DD];
__device__ __nv_bfloat16 g_MThi[BB * GSZ], g_MTlo[BB * GSZ];   // [b, c, h*96+d]
__device__ __nv_bfloat16 g_Phi[BB * GSZ], g_Plo[BB * GSZ];
__device__ __nv_bfloat16 g_wqh[GSZ], g_wql[GSZ];
__device__ __nv_bfloat16 g_wph[GSZ], g_wpl[GSZ];
__device__ float g_s[BB * CC];
__device__ float g_part[BB * 32 * CC];
__device__ float g_U[BB * 1536];
__device__ float g_r[BB * CC];
__device__ float g_biasf[BB * CC];

// ---------------------------------------------------------------------------
// PTX helpers (target-agnostic)
// ---------------------------------------------------------------------------
__device__ __forceinline__ uint32_t smem_u32(const void* p) {
    uint32_t a;
    asm("{ .reg .u64 t; cvta.to.shared.u64 t, %1; cvt.u32.u64 %0, t; }"
        : "=r"(a) : "l"(p));
    return a;
}
__device__ __forceinline__ void ldsm_x4(uint32_t* r, uint32_t addr) {
    asm volatile("ldmatrix.sync.aligned.m8n8.x4.shared.b16 {%0,%1,%2,%3}, [%4];"
                 : "=r"(r[0]), "=r"(r[1]), "=r"(r[2]), "=r"(r[3]) : "r"(addr));
}
__device__ __forceinline__ void mma16816(float* c, const uint32_t* a, const uint32_t* b) {
    asm volatile(
        "mma.sync.aligned.m16n8k16.row.col.f32.bf16.bf16.f32 "
        "{%0,%1,%2,%3}, {%4,%5,%6,%7}, {%8,%9}, {%0,%1,%2,%3};"
        : "+f"(c[0]), "+f"(c[1]), "+f"(c[2]), "+f"(c[3])
        : "r"(a[0]), "r"(a[1]), "r"(a[2]), "r"(a[3]), "r"(b[0]), "r"(b[1]));
}
__device__ __forceinline__ void cp16(uint32_t dst, const void* src) {
    asm volatile("cp.async.cg.shared.global [%0], [%1], 16;"
                 :: "r"(dst), "l"(src) : "memory");
}
__device__ __forceinline__ void cp_commit() {
    asm volatile("cp.async.commit_group;" ::: "memory");
}
template <int N>
__device__ __forceinline__ void cp_wait() {
    asm volatile("cp.async.wait_group %0;" :: "n"(N) : "memory");
}
__device__ __forceinline__ void split1(float v, __nv_bfloat16& h, __nv_bfloat16& l) {
    h = __float2bfloat16(v);
    l = __float2bfloat16(v - __bfloat162float(h));
}
__device__ __forceinline__ ushort bfu(__nv_bfloat16 v) { return __bfloat16_as_ushort(v); }

// ---------------------------------------------------------------------------
// transpose_split: x -> row-major hi/lo AND per-batch transposed hi/lo
// ---------------------------------------------------------------------------
__global__ __launch_bounds__(256)
void transpose_split_kernel(const float* __restrict__ x)
{
    __shared__ float tile[64 * 65];
    const int tid = threadIdx.x;
    const int C0 = blockIdx.x * 64;
    const int R0 = blockIdx.y * 64;

    #pragma unroll
    for (int t = 0; t < 4; ++t) {
        const int id = tid + t * 256;
        const int r = id >> 4, f4 = id & 15;
        float4 v = *(const float4*)(x + (size_t)(R0 + r) * CC + C0 + f4 * 4);
        tile[r * 65 + f4 * 4 + 0] = v.x;
        tile[r * 65 + f4 * 4 + 1] = v.y;
        tile[r * 65 + f4 * 4 + 2] = v.z;
        tile[r * 65 + f4 * 4 + 3] = v.w;
    }
    __syncthreads();

    #pragma unroll
    for (int t = 0; t < 2; ++t) {
        const int id = tid + t * 256;
        const int r = id >> 3, g = id & 7;
        ushort h[8], l[8];
        #pragma unroll
        for (int j = 0; j < 8; j++) {
            __nv_bfloat16 hb, lb; split1(tile[r * 65 + g * 8 + j], hb, lb);
            h[j] = bfu(hb); l[j] = bfu(lb);
        }
        uint4 uh, ul;
        uh.x = h[0] | (h[1] << 16); uh.y = h[2] | (h[3] << 16);
        uh.z = h[4] | (h[5] << 16); uh.w = h[6] | (h[7] << 16);
        ul.x = l[0] | (l[1] << 16); ul.y = l[2] | (l[3] << 16);
        ul.z = l[4] | (l[5] << 16); ul.w = l[6] | (l[7] << 16);
        const size_t off = (size_t)(R0 + r) * CC + C0 + g * 8;
        *(uint4*)(g_xhi + off) = uh;
        *(uint4*)(g_xlo + off) = ul;
    }

    const int bb = R0 >> 12;
    const int n0 = R0 & 4095;
    #pragma unroll
    for (int t = 0; t < 2; ++t) {
        const int id = tid + t * 256;
        const int c = id >> 3, g = id & 7;
        ushort h[8], l[8];
        #pragma unroll
        for (int j = 0; j < 8; j++) {
            __nv_bfloat16 hb, lb; split1(tile[(g * 8 + j) * 65 + c], hb, lb);
            h[j] = bfu(hb); l[j] = bfu(lb);
        }
        uint4 uh, ul;
        uh.x = h[0] | (h[1] << 16); uh.y = h[2] | (h[3] << 16);
        uh.z = h[4] | (h[5] << 16); uh.w = h[6] | (h[7] << 16);
        ul.x = l[0] | (l[1] << 16); ul.y = l[2] | (l[3] << 16);
        ul.z = l[4] | (l[5] << 16); ul.w = l[6] | (l[7] << 16);
        const size_t off = ((size_t)bb * CC + C0 + c) * NT + n0 + g * 8;
        *(uint4*)(g_xThi + off) = uh;
        *(uint4*)(g_xTlo + off) = ul;
    }
}

// ---------------------------------------------------------------------------
// split: weights only. mode 1: wq, 2: wp
// ---------------------------------------------------------------------------
__global__ __launch_bounds__(256)
void split_kernel(const float4* __restrict__ src, int mode, int n4)
{
    int i = blockIdx.x * 256 + threadIdx.x;
    if (i >= n4) return;
    __nv_bfloat16 *hi = (mode == 1) ? g_wqh : g_wph;
    __nv_bfloat16 *lo = (mode == 1) ? g_wql : g_wpl;
    float4 v = src[i];
    float a[4] = {v.x, v.y, v.z, v.w};
    ushort h[4], l[4];
    #pragma unroll
    for (int t = 0; t < 4; t++) {
        __nv_bfloat16 hb, lb; split1(a[t], hb, lb);
        h[t] = bfu(hb); l[t] = bfu(lb);
    }
    ((ushort4*)hi)[i] = make_ushort4(h[0], h[1], h[2], h[3]);
    ((ushort4*)lo)[i] = make_ushort4(l[0], l[1], l[2], l[3]);
}

// ---------------------------------------------------------------------------
// column sums of x per batch
// ---------------------------------------------------------------------------
__global__ __launch_bounds__(256)
void colsum_part_kernel(const float* __restrict__ x)
{
    const int blk = blockIdx.x, b = blockIdx.y, tid = threadIdx.x;
    const size_t base = ((size_t)b * NT + blk * 128) * CC;
    float acc[3] = {0.f, 0.f, 0.f};
    for (int r = 0; r < 128; ++r) {
        const float* row = x + base + (size_t)r * CC;
        #pragma unroll
        for (int p = 0; p < 3; ++p) acc[p] += row[p * 256 + tid];
    }
    #pragma unroll
    for (int p = 0; p < 3; ++p)
        g_part[((size_t)(b * 32 + blk)) * CC + p * 256 + tid] = acc[p];
}
__global__ void colsum_red_kernel()
{
    const int b = blockIdx.x, tid = threadIdx.x;
    float s = 0.f;
    for (int k = 0; k < 32; ++k) s += g_part[((size_t)(b * 32 + k)) * CC + tid];
    g_s[b * CC + tid] = s;
}

// ---------------------------------------------------------------------------
// U[b][row] = dot(w_qkv[row], s_b), rows 0..1535
// ---------------------------------------------------------------------------
__global__ __launch_bounds__(256)
void uw_kernel(const float* __restrict__ w_qkv)
{
    __shared__ float ss[CC];
    const int b = blockIdx.y, tid = threadIdx.x;
    #pragma unroll
    for (int p = 0; p < 3; ++p) ss[p * 256 + tid] = g_s[b * CC + p * 256 + tid];
    __syncthreads();
    const int row = blockIdx.x * 8 + (tid >> 5);
    const int lane = tid & 31;
    const float* wr = w_qkv + (size_t)row * CC;
    float acc = 0.f;
    #pragma unroll
    for (int k = 0; k < 24; ++k) acc += wr[lane + k * 32] * ss[lane + k * 32];
    #pragma unroll
    for (int off = 16; off > 0; off >>= 1)
        acc += __shfl_xor_sync(0xffffffffu, acc, off);
    if (lane == 0) g_U[b * 1536 + row] = acc;
}

// ---------------------------------------------------------------------------
// biasf[b][j] = b_proj[j] + dot(w_proj[j], r_b)
// ---------------------------------------------------------------------------
__global__ __launch_bounds__(256)
void biasf_kernel(const float* __restrict__ w_proj, const float* __restrict__ b_proj)
{
    __shared__ float rr[CC];
    const int b = blockIdx.y, tid = threadIdx.x;
    #pragma unroll
    for (int p = 0; p < 3; ++p) rr[p * 256 + tid] = g_r[b * CC + p * 256 + tid];
    __syncthreads();
    const int j = blockIdx.x * 8 + (tid >> 5);
    const int lane = tid & 31;
    const float* wr = w_proj + (size_t)j * CC;
    float acc = 0.f;
    #pragma unroll
    for (int k = 0; k < 24; ++k) acc += wr[lane + k * 32] * rr[lane + k * 32];
    #pragma unroll
    for (int off = 16; off > 0; off >>= 1)
        acc += __shfl_xor_sync(0xffffffffu, acc, off);
    if (lane == 0) g_biasf[b * CC + j] = b_proj[j] + acc;
}

// ---------------------------------------------------------------------------
// HMMA bf16-split GEMM, parameterized.
//   mode 0: G_b = Xt_b @ Xt_b^T  (K=4096, symmetric: 21 upper tiles + mirror,
//           epilogue writes Ghi/Glo directly)
//   mode 1: T_b = Wq @ G_b       (K=768, fp32 out)
//   mode 2: P_b = Wp @ MT_b      (K=768, epilogue writes Phi/Plo)
//   mode 3: out = X @ P_b^T + biasf (K=768, fp32 out, grid (6, 512))
// ---------------------------------------------------------------------------
#define SROW 80
#define TILE_B (128 * SROW)
#define STAGE_B (4 * TILE_B)
#define SMEM_ASK (2 * STAGE_B)

__global__ __launch_bounds__(256, 2)
void tgemm_kernel(float* __restrict__ Cp, int mode)
{
    int bm = blockIdx.y, bn = blockIdx.x;
    int b = blockIdx.z;
    if (mode == 0) {                      // unrank upper-triangular tile
        int t = blockIdx.x;
        bm = 0;
        while (t >= 6 - bm) { t -= 6 - bm; bm++; }
        bn = bm + t;
    }

    const __nv_bfloat16 *Ah, *Al, *Wh, *Wl;
    int K;

    if (mode == 0) {
        K = 4096;
        const size_t ab = ((size_t)b * CC + bm * 128) * NT;
        const size_t wb = ((size_t)b * CC + bn * 128) * NT;
        Ah = g_xThi + ab; Al = g_xTlo + ab;
        Wh = g_xThi + wb; Wl = g_xTlo + wb;
    } else if (mode == 1) {
        K = 768;
        Ah = g_wqh + (size_t)bm * 128 * CC; Al = g_wql + (size_t)bm * 128 * CC;
        const size_t wb = (size_t)b * GSZ + (size_t)bn * 128 * CC;
        Wh = g_Ghi + wb; Wl = g_Glo + wb;
    } else if (mode == 2) {
        K = 768;
        Ah = g_wph + (size_t)bm * 128 * CC; Al = g_wpl + (size_t)bm * 128 * CC;
        const size_t wb = (size_t)b * GSZ + (size_t)bn * 128 * CC;
        Wh = g_MThi + wb; Wl = g_MTlo + wb;
    } else {
        K = 768;
        b = bm >> 5;
        const size_t ab = (size_t)bm * 128 * CC;
        Ah = g_xhi + ab; Al = g_xlo + ab;
        const size_t wb = (size_t)b * GSZ + (size_t)bn * 128 * CC;
        Wh = g_Phi + wb; Wl = g_Plo + wb;
    }

    extern __shared__ char smem[];
    const uint32_t ubase = smem_u32(smem);

    const int tid  = threadIdx.x;
    const int wid  = tid >> 5;
    const int lane = tid & 31;
    const int wm   = wid & 1;
    const int wn   = wid >> 1;

    const int cr = tid >> 2;
    const int cg = tid & 3;

    #define ISSUE(s) do { \
        const uint32_t sb_ = ubase + ((s) & 1) * STAGE_B; \
        const int kof_ = (s) * 32; \
        _Pragma("unroll") \
        for (int t_ = 0; t_ < 2; ++t_) { \
            const int r_ = cr + t_ * 64; \
            const size_t off_ = (size_t)r_ * K + kof_ + cg * 8; \
            const uint32_t d_ = sb_ + r_ * SROW + cg * 16; \
            cp16(d_ + 0 * TILE_B, Ah + off_); \
            cp16(d_ + 1 * TILE_B, Al + off_); \
            cp16(d_ + 2 * TILE_B, Wh + off_); \
            cp16(d_ + 3 * TILE_B, Wl + off_); \
        } \
        cp_commit(); \
    } while (0)

    float acc[4][4][4];
    #pragma unroll
    for (int i = 0; i < 4; i++)
        #pragma unroll
        for (int j = 0; j < 4; j++)
            #pragma unroll
            for (int q = 0; q < 4; q++) acc[i][j][q] = 0.f;

    // ldmatrix lane addressing
    const int laneRA = lane & 15;
    const int laneGA = lane >> 4;
    const int laneRB = (lane & 7) | ((lane >> 4) << 3);  // B x4: 2 n-steps per load
    const int laneGB = (lane >> 3) & 1;

    const int NK = K >> 5;

    ISSUE(0);
    ISSUE(1);

    for (int kb = 0; kb < NK; ++kb) {
        if (kb + 1 < NK) cp_wait<1>(); else cp_wait<0>();
        __syncthreads();

        const uint32_t sb = ubase + (kb & 1) * STAGE_B;
        const uint32_t aBase = sb + (wm * 64 + laneRA) * SROW + laneGA * 16;
        const uint32_t bBase = sb + 2 * TILE_B + (wn * 32 + laneRB) * SROW + laneGB * 16;

        #pragma unroll
        for (int ks = 0; ks < 2; ++ks) {
            const uint32_t ko = ks * 32;
            uint32_t bh[4][2], bl[4][2];
            #pragma unroll
            for (int fp = 0; fp < 2; fp++) {
                uint32_t q[4];
                ldsm_x4(q, bBase + fp * (16 * SROW) + ko);
                bh[2 * fp][0] = q[0]; bh[2 * fp][1] = q[1];
                bh[2 * fp + 1][0] = q[2]; bh[2 * fp + 1][1] = q[3];
                ldsm_x4(q, bBase + TILE_B + fp * (16 * SROW) + ko);
                bl[2 * fp][0] = q[0]; bl[2 * fp][1] = q[1];
                bl[2 * fp + 1][0] = q[2]; bl[2 * fp + 1][1] = q[3];
            }
            #pragma unroll
            for (int fm = 0; fm < 4; fm++) {
                uint32_t ah[4], al[4];
                ldsm_x4(ah, aBase + fm * (16 * SROW) + ko);
                ldsm_x4(al, aBase + TILE_B + fm * (16 * SROW) + ko);
                #pragma unroll
                for (int fn = 0; fn < 4; fn++) {
                    mma16816(acc[fm][fn], ah, bh[fn]);
                    mma16816(acc[fm][fn], ah, bl[fn]);
                    mma16816(acc[fm][fn], al, bh[fn]);
                }
            }
        }

        if (kb + 2 < NK) {
            __syncthreads();
            ISSUE(kb + 2);
        }
    }

    const int gid4 = lane >> 2;
    const int tig  = lane & 3;

    if (mode == 1 || mode == 3) {
        float* C = (mode == 1) ? (g_T + (size_t)b * GSZ) : Cp;
        const float* bias = (mode == 3) ? (g_biasf + b * CC) : nullptr;
        #pragma unroll
        for (int fm = 0; fm < 4; fm++) {
            const int m0 = bm * 128 + wm * 64 + fm * 16 + gid4;
            #pragma unroll
            for (int fn = 0; fn < 4; fn++) {
                const int col = bn * 128 + wn * 32 + fn * 8 + tig * 2;
                float bx = 0.f, by = 0.f;
                if (bias) { bx = bias[col]; by = bias[col + 1]; }
                float2 o;
                o.x = acc[fm][fn][0] + bx; o.y = acc[fm][fn][1] + by;
                *(float2*)(C + (size_t)m0 * CC + col) = o;
                o.x = acc[fm][fn][2] + bx; o.y = acc[fm][fn][3] + by;
                *(float2*)(C + (size_t)(m0 + 8) * CC + col) = o;
            }
        }
    } else {
        __nv_bfloat16* Hi = (mode == 0) ? (g_Ghi + (size_t)b * GSZ)
                                        : (g_Phi + (size_t)b * GSZ);
        __nv_bfloat16* Lo = (mode == 0) ? (g_Glo + (size_t)b * GSZ)
                                        : (g_Plo + (size_t)b * GSZ);
        const bool mirror = (mode == 0) && (bm < bn);
        #pragma unroll
        for (int fm = 0; fm < 4; fm++) {
            const int m0 = bm * 128 + wm * 64 + fm * 16 + gid4;
            #pragma unroll
            for (int fn = 0; fn < 4; fn++) {
                const int col = bn * 128 + wn * 32 + fn * 8 + tig * 2;
                __nv_bfloat16 h[4], l[4];
                #pragma unroll
                for (int q = 0; q < 4; q++) split1(acc[fm][fn][q], h[q], l[q]);
                // direct writes (rows m0, m0+8; cols col, col+1)
                *(ushort2*)(Hi + (size_t)m0 * CC + col) =
                    make_ushort2(bfu(h[0]), bfu(h[1]));
                *(ushort2*)(Lo + (size_t)m0 * CC + col) =
                    make_ushort2(bfu(l[0]), bfu(l[1]));
                *(ushort2*)(Hi + (size_t)(m0 + 8) * CC + col) =
                    make_ushort2(bfu(h[2]), bfu(h[3]));
                *(ushort2*)(Lo + (size_t)(m0 + 8) * CC + col) =
                    make_ushort2(bfu(l[2]), bfu(l[3]));
                if (mirror) {
                    Hi[(size_t)col * CC + m0] = h[0];
                    Hi[(size_t)(col + 1) * CC + m0] = h[1];
                    Hi[(size_t)col * CC + m0 + 8] = h[2];
                    Hi[(size_t)(col + 1) * CC + m0 + 8] = h[3];
                    Lo[(size_t)col * CC + m0] = l[0];
                    Lo[(size_t)(col + 1) * CC + m0] = l[1];
                    Lo[(size_t)col * CC + m0 + 8] = l[2];
                    Lo[(size_t)(col + 1) * CC + m0 + 8] = l[3];
                }
            }
        }
    }
    #undef ISSUE
}

// ---------------------------------------------------------------------------
// logits + softmax per (b,h)
// ---------------------------------------------------------------------------
__global__ __launch_bounds__(256)
void logits_kernel(const float* __restrict__ w_qkv, const float* __restrict__ b_qkv)
{
    const int bh = blockIdx.x;
    const int b = bh >> 3, h = bh & 7;

    __shared__ float buf[9312];
    __shared__ float bqs[96], bks[96], us_[96], ws_[96];

    const int tid = threadIdx.x;
    const int tx = tid & 15;
    const int ty = tid >> 4;

    if (tid < 96) {
        bqs[tid] = b_qkv[h * DD + tid];
        bks[tid] = b_qkv[CC + h * DD + tid];
        ws_[tid] = g_U[b * 1536 + h * DD + tid];
        us_[tid] = g_U[b * 1536 + CC + h * DD + tid];
    }

    const float* Tb = g_T + (size_t)b * GSZ + (size_t)(h * DD) * CC;
    const float* Wk = w_qkv + (size_t)(CC + h * DD) * CC;

    float acc[6][6];
    #pragma unroll
    for (int i = 0; i < 6; i++)
        #pragma unroll
        for (int j = 0; j < 6; j++) acc[i][j] = 0.f;

    for (int c0 = 0; c0 < CC; c0 += 32) {
        __syncthreads();
        #pragma unroll
        for (int t = 0; t < 3; ++t) {
            const int id = tid + t * 256;
            const int row = id >> 3, f4 = id & 7;
            float4 tv = *(const float4*)(Tb + (size_t)row * CC + c0 + f4 * 4);
            float4 kv = *(const float4*)(Wk + (size_t)row * CC + c0 + f4 * 4);
            buf[(f4 * 4 + 0) * 97 + row] = tv.x;
            buf[(f4 * 4 + 1) * 97 + row] = tv.y;
            buf[(f4 * 4 + 2) * 97 + row] = tv.z;
            buf[(f4 * 4 + 3) * 97 + row] = tv.w;
            buf[3104 + (f4 * 4 + 0) * 97 + row] = kv.x;
            buf[3104 + (f4 * 4 + 1) * 97 + row] = kv.y;
            buf[3104 + (f4 * 4 + 2) * 97 + row] = kv.z;
            buf[3104 + (f4 * 4 + 3) * 97 + row] = kv.w;
        }
        __syncthreads();
        #pragma unroll 8
        for (int kk = 0; kk < 32; ++kk) {
            float qr[6], kr[6];
            #pragma unroll
            for (int i = 0; i < 6; i++) qr[i] = buf[kk * 97 + ty * 6 + i];
            #pragma unroll
            for (int j = 0; j < 6; j++) kr[j] = buf[3104 + kk * 97 + tx * 6 + j];
            #pragma unroll
            for (int i = 0; i < 6; i++)
                #pragma unroll
                for (int j = 0; j < 6; j++)
                    acc[i][j] = fmaf(qr[i], kr[j], acc[i][j]);
        }
    }
    __syncthreads();

    const float scale = 0.015625f;
    #pragma unroll
    for (int i = 0; i < 6; i++) {
        const int d = ty * 6 + i;
        #pragma unroll
        for (int j = 0; j < 6; j++) {
            const int e = tx * 6 + j;
            float v = acc[i][j] + bqs[d] * us_[e] + bks[e] * ws_[d]
                      + 4096.f * bqs[d] * bks[e];
            buf[d * 96 + e] = v * scale;
        }
    }
    __syncthreads();

    const int wid = tid >> 5, lane = tid & 31;
    for (int r = wid; r < 96; r += 8) {
        float v0 = buf[r * 96 + lane];
        float v1 = buf[r * 96 + 32 + lane];
        float v2 = buf[r * 96 + 64 + lane];
        float m = fmaxf(v0, fmaxf(v1, v2));
        #pragma unroll
        for (int off = 16; off > 0; off >>= 1)
            m = fmaxf(m, __shfl_xor_sync(0xffffffffu, m, off));
        float e0 = expf(v0 - m), e1 = expf(v1 - m), e2 = expf(v2 - m);
        float s = e0 + e1 + e2;
        #pragma unroll
        for (int off = 16; off > 0; off >>= 1)
            s += __shfl_xor_sync(0xffffffffu, s, off);
        const float inv = 1.f / s;
        float* arow = g_attn + ((size_t)bh * 96 + r) * 96;
        arow[lane]      = e0 * inv;
        arow[lane + 32] = e1 * inv;
        arow[lane + 64] = e2 * inv;
    }
}

// ---------------------------------------------------------------------------
// MT_b[c, h*96+d] = sum_e A_bh[d,e] Wv[h*96+e, c]  (bf16 hi/lo direct);
// r_bh = A_bh @ bv_h
// ---------------------------------------------------------------------------
__global__ __launch_bounds__(256)
void mt_kernel(const float* __restrict__ w_qkv, const float* __restrict__ b_qkv)
{
    const int bh = blockIdx.x;
    const int b = bh >> 3, h = bh & 7;

    __shared__ float As[96 * 97];
    __shared__ float Ws[16 * 132];
    __shared__ float bvs[96];

    const int tid = threadIdx.x;
    const int tx = tid & 15;
    const int ty = tid >> 4;

    const float* asrc = g_attn + (size_t)bh * 9216;
    for (int id = tid; id < 9216; id += 256) {
        const int r = id / 96, c = id - r * 96;
        As[r * 97 + c] = asrc[id];
    }
    if (tid < 96) bvs[tid] = b_qkv[2 * CC + h * DD + tid];
    __syncthreads();

    if (tid < 96) {
        float rv = 0.f;
        #pragma unroll 4
        for (int e = 0; e < 96; ++e) rv += As[tid * 97 + e] * bvs[e];
        g_r[b * CC + h * DD + tid] = rv;
    }

    const float* Wv = w_qkv + (size_t)(2 * CC + h * DD) * CC;
    __nv_bfloat16* MTh = g_MThi + (size_t)b * GSZ;
    __nv_bfloat16* MTl = g_MTlo + (size_t)b * GSZ;

    for (int c0 = 0; c0 < CC; c0 += 128) {
        float acc[8][6];
        #pragma unroll
        for (int i = 0; i < 8; i++)
            #pragma unroll
            for (int j = 0; j < 6; j++) acc[i][j] = 0.f;

        for (int e0 = 0; e0 < 96; e0 += 16) {
            __syncthreads();
            #pragma unroll
            for (int t = 0; t < 2; ++t) {
                const int id = tid + t * 256;
                const int e = id >> 5, f4 = id & 31;
                float4 v = *(const float4*)(Wv + (size_t)(e0 + e) * CC + c0 + f4 * 4);
                *(float4*)&Ws[e * 132 + f4 * 4] = v;
            }
            __syncthreads();
            #pragma unroll
            for (int e = 0; e < 16; ++e) {
                float vv[8], aa[6];
                #pragma unroll
                for (int i = 0; i < 8; i++) vv[i] = Ws[e * 132 + ty * 8 + i];
                #pragma unroll
                for (int j = 0; j < 6; j++) aa[j] = As[(tx * 6 + j) * 97 + e0 + e];
                #pragma unroll
                for (int i = 0; i < 8; i++)
                    #pragma unroll
                    for (int j = 0; j < 6; j++)
                        acc[i][j] = fmaf(vv[i], aa[j], acc[i][j]);
            }
        }
        #pragma unroll
        for (int i = 0; i < 8; i++) {
            const int c = c0 + ty * 8 + i;
            const size_t base = (size_t)c * CC + h * DD + tx * 6;
            #pragma unroll
            for (int j = 0; j < 6; j += 2) {
                __nv_bfloat16 h0, l0, h1, l1;
                split1(acc[i][j], h0, l0);
                split1(acc[i][j + 1], h1, l1);
                *(ushort2*)(MTh + base + j) = make_ushort2(bfu(h0), bfu(h1));
                *(ushort2*)(MTl + base + j) = make_ushort2(bfu(l0), bfu(l1));
            }
        }
    }
}

// ---------------------------------------------------------------------------
extern "C" void kernel_launch(void* const* d_in, const int* in_sizes, int n_in,
                              void* d_out, int out_size)
{
    const float* x      = (const float*)d_in[0];
    const float* w_qkv  = (const float*)d_in[1];
    const float* b_qkv  = (const float*)d_in[2];
    const float* w_proj = (const float*)d_in[3];
    const float* b_proj = (const float*)d_in[4];
    float*       out    = (float*)d_out;

    cudaFuncSetAttribute(tgemm_kernel,
                         cudaFuncAttributeMaxDynamicSharedMemorySize, SMEM_ASK);

    // 0) splits + transposed splits + column sums
    transpose_split_kernel<<<dim3(12, 1024), 256>>>(x);
    colsum_part_kernel<<<dim3(32, BB), 256>>>(x);
    colsum_red_kernel<<<BB, 768>>>();
    split_kernel<<<576, 256>>>((const float4*)w_qkv, 1, GSZ / 4);
    split_kernel<<<576, 256>>>((const float4*)w_proj, 2, GSZ / 4);

    // 1) G_b = X_b^T X_b (symmetric: 21 tiles + mirrored epilogue, bf16 direct)
    tgemm_kernel<<<dim3(21, 1, BB), 256, SMEM_ASK>>>(nullptr, 0);

    // 2) T_b = Wq @ G_b
    tgemm_kernel<<<dim3(6, 6, BB), 256, SMEM_ASK>>>(nullptr, 1);

    // 3) rank-1 correction dots, logits + softmax
    uw_kernel<<<dim3(192, BB), 256>>>(w_qkv);
    logits_kernel<<<BB * HH, 256>>>(w_qkv, b_qkv);

    // 4) MT_b = (A @ Wv)^T stacked (bf16 direct); r_bh
    mt_kernel<<<BB * HH, 256>>>(w_qkv, b_qkv);

    // 5) P_b = Wp @ MT_b (bf16 direct); fused output bias
    biasf_kernel<<<dim3(96, BB), 256>>>(w_proj, b_proj);
    tgemm_kernel<<<dim3(6, 6, BB), 256, SMEM_ASK>>>(nullptr, 2);

    // 6) out = X @ P_b^T + biasf
    tgemm_kernel<<<dim3(6, 512, 1), 256, SMEM_ASK>>>(out, 3);
}

// round 7
// speedup vs baseline: 5.2797x; 1.1325x over previous
#include <cuda_runtime.h>
#include <cuda_fp16.h>
#include <cstdint>

// Problem constants
#define BB   16
#define NT   4096
#define CC   768
#define HH   8
#define DD   96
#define MM   (BB * NT)          // 65536
#define GSZ  (768 * 768)        // 589824

// ---------------------------------------------------------------------------
// Scratch (__device__ globals)
// ---------------------------------------------------------------------------
__device__ __half g_xhi[(size_t)MM * CC], g_xlo[(size_t)MM * CC];
__device__ __half g_xThi[(size_t)MM * CC], g_xTlo[(size_t)MM * CC]; // [b,c,n]
__device__ __half g_Ghi[BB * GSZ], g_Glo[BB * GSZ];
__device__ float g_T[BB * GSZ];
__device__ float g_attn[BB * HH * DD * DD];
__device__ __half g_MThi[BB * GSZ], g_MTlo[BB * GSZ];   // [b, c, h*96+d]
__device__ __half g_Phi[BB * GSZ];
__device__ __half g_wqh[GSZ], g_wql[GSZ];
__device__ __half g_wph[GSZ], g_wpl[GSZ];
__device__ float g_s[BB * CC];
__device__ float g_part[BB * 32 * CC];
__device__ float g_U[BB * 1536];
__device__ float g_r[BB * CC];
__device__ float g_biasf[BB * CC];

// ---------------------------------------------------------------------------
// PTX helpers (target-agnostic)
// ---------------------------------------------------------------------------
__device__ __forceinline__ uint32_t smem_u32(const void* p) {
    uint32_t a;
    asm("{ .reg .u64 t; cvta.to.shared.u64 t, %1; cvt.u32.u64 %0, t; }"
        : "=r"(a) : "l"(p));
    return a;
}
__device__ __forceinline__ void ldsm_x4(uint32_t* r, uint32_t addr) {
    asm volatile("ldmatrix.sync.aligned.m8n8.x4.shared.b16 {%0,%1,%2,%3}, [%4];"
                 : "=r"(r[0]), "=r"(r[1]), "=r"(r[2]), "=r"(r[3]) : "r"(addr));
}
__device__ __forceinline__ void mma16816(float* c, const uint32_t* a, const uint32_t* b) {
    asm volatile(
        "mma.sync.aligned.m16n8k16.row.col.f32.f16.f16.f32 "
        "{%0,%1,%2,%3}, {%4,%5,%6,%7}, {%8,%9}, {%0,%1,%2,%3};"
        : "+f"(c[0]), "+f"(c[1]), "+f"(c[2]), "+f"(c[3])
        : "r"(a[0]), "r"(a[1]), "r"(a[2]), "r"(a[3]), "r"(b[0]), "r"(b[1]));
}
__device__ __forceinline__ void cp16(uint32_t dst, const void* src) {
    asm volatile("cp.async.cg.shared.global [%0], [%1], 16;"
                 :: "r"(dst), "l"(src) : "memory");
}
__device__ __forceinline__ void cp_commit() {
    asm volatile("cp.async.commit_group;" ::: "memory");
}
template <int N>
__device__ __forceinline__ void cp_wait() {
    asm volatile("cp.async.wait_group %0;" :: "n"(N) : "memory");
}
__device__ __forceinline__ void split1(float v, __half& h, __half& l) {
    h = __float2half_rn(v);
    l = __float2half_rn(v - __half2float(h));
}
__device__ __forceinline__ ushort hfu(__half v) { return __half_as_ushort(v); }

// ---------------------------------------------------------------------------
// transpose_split: x -> row-major hi/lo AND per-batch transposed hi/lo
// ---------------------------------------------------------------------------
__global__ __launch_bounds__(256)
void transpose_split_kernel(const float* __restrict__ x)
{
    __shared__ float tile[64 * 65];
    const int tid = threadIdx.x;
    const int C0 = blockIdx.x * 64;
    const int R0 = blockIdx.y * 64;

    #pragma unroll
    for (int t = 0; t < 4; ++t) {
        const int id = tid + t * 256;
        const int r = id >> 4, f4 = id & 15;
        float4 v = *(const float4*)(x + (size_t)(R0 + r) * CC + C0 + f4 * 4);
        tile[r * 65 + f4 * 4 + 0] = v.x;
        tile[r * 65 + f4 * 4 + 1] = v.y;
        tile[r * 65 + f4 * 4 + 2] = v.z;
        tile[r * 65 + f4 * 4 + 3] = v.w;
    }
    __syncthreads();

    #pragma unroll
    for (int t = 0; t < 2; ++t) {
        const int id = tid + t * 256;
        const int r = id >> 3, g = id & 7;
        ushort h[8], l[8];
        #pragma unroll
        for (int j = 0; j < 8; j++) {
            __half hb, lb; split1(tile[r * 65 + g * 8 + j], hb, lb);
            h[j] = hfu(hb); l[j] = hfu(lb);
        }
        uint4 uh, ul;
        uh.x = h[0] | (h[1] << 16); uh.y = h[2] | (h[3] << 16);
        uh.z = h[4] | (h[5] << 16); uh.w = h[6] | (h[7] << 16);
        ul.x = l[0] | (l[1] << 16); ul.y = l[2] | (l[3] << 16);
        ul.z = l[4] | (l[5] << 16); ul.w = l[6] | (l[7] << 16);
        const size_t off = (size_t)(R0 + r) * CC + C0 + g * 8;
        *(uint4*)(g_xhi + off) = uh;
        *(uint4*)(g_xlo + off) = ul;
    }

    const int bb = R0 >> 12;
    const int n0 = R0 & 4095;
    #pragma unroll
    for (int t = 0; t < 2; ++t) {
        const int id = tid + t * 256;
        const int c = id >> 3, g = id & 7;
        ushort h[8], l[8];
        #pragma unroll
        for (int j = 0; j < 8; j++) {
            __half hb, lb; split1(tile[(g * 8 + j) * 65 + c], hb, lb);
            h[j] = hfu(hb); l[j] = hfu(lb);
        }
        uint4 uh, ul;
        uh.x = h[0] | (h[1] << 16); uh.y = h[2] | (h[3] << 16);
        uh.z = h[4] | (h[5] << 16); uh.w = h[6] | (h[7] << 16);
        ul.x = l[0] | (l[1] << 16); ul.y = l[2] | (l[3] << 16);
        ul.z = l[4] | (l[5] << 16); ul.w = l[6] | (l[7] << 16);
        const size_t off = ((size_t)bb * CC + C0 + c) * NT + n0 + g * 8;
        *(uint4*)(g_xThi + off) = uh;
        *(uint4*)(g_xTlo + off) = ul;
    }
}

// ---------------------------------------------------------------------------
// split: weights only. mode 1: wq, 2: wp
// ---------------------------------------------------------------------------
__global__ __launch_bounds__(256)
void split_kernel(const float4* __restrict__ src, int mode, int n4)
{
    int i = blockIdx.x * 256 + threadIdx.x;
    if (i >= n4) return;
    __half *hi = (mode == 1) ? g_wqh : g_wph;
    __half *lo = (mode == 1) ? g_wql : g_wpl;
    float4 v = src[i];
    float a[4] = {v.x, v.y, v.z, v.w};
    ushort h[4], l[4];
    #pragma unroll
    for (int t = 0; t < 4; t++) {
        __half hb, lb; split1(a[t], hb, lb);
        h[t] = hfu(hb); l[t] = hfu(lb);
    }
    ((ushort4*)hi)[i] = make_ushort4(h[0], h[1], h[2], h[3]);
    ((ushort4*)lo)[i] = make_ushort4(l[0], l[1], l[2], l[3]);
}

// ---------------------------------------------------------------------------
// column sums of x per batch
// ---------------------------------------------------------------------------
__global__ __launch_bounds__(256)
void colsum_part_kernel(const float* __restrict__ x)
{
    const int blk = blockIdx.x, b = blockIdx.y, tid = threadIdx.x;
    const size_t base = ((size_t)b * NT + blk * 128) * CC;
    float acc[3] = {0.f, 0.f, 0.f};
    for (int r = 0; r < 128; ++r) {
        const float* row = x + base + (size_t)r * CC;
        #pragma unroll
        for (int p = 0; p < 3; ++p) acc[p] += row[p * 256 + tid];
    }
    #pragma unroll
    for (int p = 0; p < 3; ++p)
        g_part[((size_t)(b * 32 + blk)) * CC + p * 256 + tid] = acc[p];
}
__global__ void colsum_red_kernel()
{
    const int b = blockIdx.x, tid = threadIdx.x;
    float s = 0.f;
    for (int k = 0; k < 32; ++k) s += g_part[((size_t)(b * 32 + k)) * CC + tid];
    g_s[b * CC + tid] = s;
}

// ---------------------------------------------------------------------------
// U[b][row] = dot(w_qkv[row], s_b), rows 0..1535
// ---------------------------------------------------------------------------
__global__ __launch_bounds__(256)
void uw_kernel(const float* __restrict__ w_qkv)
{
    __shared__ float ss[CC];
    const int b = blockIdx.y, tid = threadIdx.x;
    #pragma unroll
    for (int p = 0; p < 3; ++p) ss[p * 256 + tid] = g_s[b * CC + p * 256 + tid];
    __syncthreads();
    const int row = blockIdx.x * 8 + (tid >> 5);
    const int lane = tid & 31;
    const float* wr = w_qkv + (size_t)row * CC;
    float acc = 0.f;
    #pragma unroll
    for (int k = 0; k < 24; ++k) acc += wr[lane + k * 32] * ss[lane + k * 32];
    #pragma unroll
    for (int off = 16; off > 0; off >>= 1)
        acc += __shfl_xor_sync(0xffffffffu, acc, off);
    if (lane == 0) g_U[b * 1536 + row] = acc;
}

// ---------------------------------------------------------------------------
// biasf[b][j] = b_proj[j] + dot(w_proj[j], r_b)
// ---------------------------------------------------------------------------
__global__ __launch_bounds__(256)
void biasf_kernel(const float* __restrict__ w_proj, const float* __restrict__ b_proj)
{
    __shared__ float rr[CC];
    const int b = blockIdx.y, tid = threadIdx.x;
    #pragma unroll
    for (int p = 0; p < 3; ++p) rr[p * 256 + tid] = g_r[b * CC + p * 256 + tid];
    __syncthreads();
    const int j = blockIdx.x * 8 + (tid >> 5);
    const int lane = tid & 31;
    const float* wr = w_proj + (size_t)j * CC;
    float acc = 0.f;
    #pragma unroll
    for (int k = 0; k < 24; ++k) acc += wr[lane + k * 32] * rr[lane + k * 32];
    #pragma unroll
    for (int off = 16; off > 0; off >>= 1)
        acc += __shfl_xor_sync(0xffffffffu, acc, off);
    if (lane == 0) g_biasf[b * CC + j] = b_proj[j] + acc;
}

// ---------------------------------------------------------------------------
// HMMA fp16-split GEMM, templated on MODE.
//   MODE 0: G_b = Xt_b @ Xt_b^T  (K=4096, symmetric 21 tiles + mirror, fp16 out)
//   MODE 1: T_b = Wq @ G_b       (K=768, fp32 out)
//   MODE 2: P_b = Wp @ MT_b      (K=768, fp16 hi-only out)
//   MODE 3: out = X @ P_b^T + biasf  (K=768, 2-PASS: B hi only, fp32 out)
// ---------------------------------------------------------------------------
#define SROW 80
#define TILE_B (128 * SROW)
#define STAGE_B (4 * TILE_B)
#define SMEM_ASK (2 * STAGE_B)

template <int MODE>
__global__ __launch_bounds__(256, 2)
void tgemm_kernel(float* __restrict__ Cp)
{
    int bm = blockIdx.y, bn = blockIdx.x;
    int b = blockIdx.z;
    if (MODE == 0) {
        int t = blockIdx.x;
        bm = 0;
        while (t >= 6 - bm) { t -= 6 - bm; bm++; }
        bn = bm + t;
    }

    const __half *Ah, *Al, *Wh, *Wl;
    constexpr int K = (MODE == 0) ? 4096 : 768;

    if (MODE == 0) {
        const size_t ab = ((size_t)b * CC + bm * 128) * NT;
        const size_t wb = ((size_t)b * CC + bn * 128) * NT;
        Ah = g_xThi + ab; Al = g_xTlo + ab;
        Wh = g_xThi + wb; Wl = g_xTlo + wb;
    } else if (MODE == 1) {
        Ah = g_wqh + (size_t)bm * 128 * CC; Al = g_wql + (size_t)bm * 128 * CC;
        const size_t wb = (size_t)b * GSZ + (size_t)bn * 128 * CC;
        Wh = g_Ghi + wb; Wl = g_Glo + wb;
    } else if (MODE == 2) {
        Ah = g_wph + (size_t)bm * 128 * CC; Al = g_wpl + (size_t)bm * 128 * CC;
        const size_t wb = (size_t)b * GSZ + (size_t)bn * 128 * CC;
        Wh = g_MThi + wb; Wl = g_MTlo + wb;
    } else {
        b = bm >> 5;
        const size_t ab = (size_t)bm * 128 * CC;
        Ah = g_xhi + ab; Al = g_xlo + ab;
        const size_t wb = (size_t)b * GSZ + (size_t)bn * 128 * CC;
        Wh = g_Phi + wb; Wl = Wh;    // unused in 2-pass
    }

    extern __shared__ char smem[];
    const uint32_t ubase = smem_u32(smem);

    const int tid  = threadIdx.x;
    const int wid  = tid >> 5;
    const int lane = tid & 31;
    const int wm   = wid & 1;
    const int wn   = wid >> 1;

    const int cr = tid >> 2;
    const int cg = tid & 3;

    #define ISSUE(s) do { \
        const uint32_t sb_ = ubase + ((s) & 1) * STAGE_B; \
        const int kof_ = (s) * 32; \
        _Pragma("unroll") \
        for (int t_ = 0; t_ < 2; ++t_) { \
            const int r_ = cr + t_ * 64; \
            const size_t off_ = (size_t)r_ * K + kof_ + cg * 8; \
            const uint32_t d_ = sb_ + r_ * SROW + cg * 16; \
            cp16(d_ + 0 * TILE_B, Ah + off_); \
            cp16(d_ + 1 * TILE_B, Al + off_); \
            cp16(d_ + 2 * TILE_B, Wh + off_); \
            if (MODE != 3) cp16(d_ + 3 * TILE_B, Wl + off_); \
        } \
        cp_commit(); \
    } while (0)

    float acc[4][4][4];
    #pragma unroll
    for (int i = 0; i < 4; i++)
        #pragma unroll
        for (int j = 0; j < 4; j++)
            #pragma unroll
            for (int q = 0; q < 4; q++) acc[i][j][q] = 0.f;

    const int laneRA = lane & 15;
    const int laneGA = lane >> 4;
    const int laneRB = (lane & 7) | ((lane >> 4) << 3);
    const int laneGB = (lane >> 3) & 1;

    const int NK = K >> 5;

    ISSUE(0);
    ISSUE(1);

    for (int kb = 0; kb < NK; ++kb) {
        if (kb + 1 < NK) cp_wait<1>(); else cp_wait<0>();
        __syncthreads();

        const uint32_t sb = ubase + (kb & 1) * STAGE_B;
        const uint32_t aBase = sb + (wm * 64 + laneRA) * SROW + laneGA * 16;
        const uint32_t bBase = sb + 2 * TILE_B + (wn * 32 + laneRB) * SROW + laneGB * 16;

        #pragma unroll
        for (int ks = 0; ks < 2; ++ks) {
            const uint32_t ko = ks * 32;
            uint32_t bh[4][2], bl[4][2];
            #pragma unroll
            for (int fp = 0; fp < 2; fp++) {
                uint32_t q[4];
                ldsm_x4(q, bBase + fp * (16 * SROW) + ko);
                bh[2 * fp][0] = q[0]; bh[2 * fp][1] = q[1];
                bh[2 * fp + 1][0] = q[2]; bh[2 * fp + 1][1] = q[3];
                if (MODE != 3) {
                    ldsm_x4(q, bBase + TILE_B + fp * (16 * SROW) + ko);
                    bl[2 * fp][0] = q[0]; bl[2 * fp][1] = q[1];
                    bl[2 * fp + 1][0] = q[2]; bl[2 * fp + 1][1] = q[3];
                }
            }
            #pragma unroll
            for (int fm = 0; fm < 4; fm++) {
                uint32_t ah[4], al[4];
                ldsm_x4(ah, aBase + fm * (16 * SROW) + ko);
                ldsm_x4(al, aBase + TILE_B + fm * (16 * SROW) + ko);
                #pragma unroll
                for (int fn = 0; fn < 4; fn++) {
                    mma16816(acc[fm][fn], ah, bh[fn]);
                    if (MODE != 3) mma16816(acc[fm][fn], ah, bl[fn]);
                    mma16816(acc[fm][fn], al, bh[fn]);
                }
            }
        }

        if (kb + 2 < NK) {
            __syncthreads();
            ISSUE(kb + 2);
        }
    }

    const int gid4 = lane >> 2;
    const int tig  = lane & 3;

    if (MODE == 1 || MODE == 3) {
        float* C = (MODE == 1) ? (g_T + (size_t)b * GSZ) : Cp;
        const float* bias = (MODE == 3) ? (g_biasf + b * CC) : nullptr;
        #pragma unroll
        for (int fm = 0; fm < 4; fm++) {
            const int m0 = bm * 128 + wm * 64 + fm * 16 + gid4;
            #pragma unroll
            for (int fn = 0; fn < 4; fn++) {
                const int col = bn * 128 + wn * 32 + fn * 8 + tig * 2;
                float bx = 0.f, by = 0.f;
                if (MODE == 3) { bx = bias[col]; by = bias[col + 1]; }
                float2 o;
                o.x = acc[fm][fn][0] + bx; o.y = acc[fm][fn][1] + by;
                *(float2*)(C + (size_t)m0 * CC + col) = o;
                o.x = acc[fm][fn][2] + bx; o.y = acc[fm][fn][3] + by;
                *(float2*)(C + (size_t)(m0 + 8) * CC + col) = o;
            }
        }
    } else if (MODE == 0) {
        __half* Hi = g_Ghi + (size_t)b * GSZ;
        __half* Lo = g_Glo + (size_t)b * GSZ;
        const bool mirror = (bm < bn);
        #pragma unroll
        for (int fm = 0; fm < 4; fm++) {
            const int m0 = bm * 128 + wm * 64 + fm * 16 + gid4;
            #pragma unroll
            for (int fn = 0; fn < 4; fn++) {
                const int col = bn * 128 + wn * 32 + fn * 8 + tig * 2;
                __half h[4], l[4];
                #pragma unroll
                for (int q = 0; q < 4; q++) split1(acc[fm][fn][q], h[q], l[q]);
                *(ushort2*)(Hi + (size_t)m0 * CC + col) =
                    make_ushort2(hfu(h[0]), hfu(h[1]));
                *(ushort2*)(Lo + (size_t)m0 * CC + col) =
                    make_ushort2(hfu(l[0]), hfu(l[1]));
                *(ushort2*)(Hi + (size_t)(m0 + 8) * CC + col) =
                    make_ushort2(hfu(h[2]), hfu(h[3]));
                *(ushort2*)(Lo + (size_t)(m0 + 8) * CC + col) =
                    make_ushort2(hfu(l[2]), hfu(l[3]));
                if (mirror) {
                    Hi[(size_t)col * CC + m0] = h[0];
                    Hi[(size_t)(col + 1) * CC + m0] = h[1];
                    Hi[(size_t)col * CC + m0 + 8] = h[2];
                    Hi[(size_t)(col + 1) * CC + m0 + 8] = h[3];
                    Lo[(size_t)col * CC + m0] = l[0];
                    Lo[(size_t)(col + 1) * CC + m0] = l[1];
                    Lo[(size_t)col * CC + m0 + 8] = l[2];
                    Lo[(size_t)(col + 1) * CC + m0 + 8] = l[3];
                }
            }
        }
    } else {   // MODE 2: P hi only
        __half* Hi = g_Phi + (size_t)b * GSZ;
        #pragma unroll
        for (int fm = 0; fm < 4; fm++) {
            const int m0 = bm * 128 + wm * 64 + fm * 16 + gid4;
            #pragma unroll
            for (int fn = 0; fn < 4; fn++) {
                const int col = bn * 128 + wn * 32 + fn * 8 + tig * 2;
                *(ushort2*)(Hi + (size_t)m0 * CC + col) =
                    make_ushort2(hfu(__float2half_rn(acc[fm][fn][0])),
                                 hfu(__float2half_rn(acc[fm][fn][1])));
                *(ushort2*)(Hi + (size_t)(m0 + 8) * CC + col) =
                    make_ushort2(hfu(__float2half_rn(acc[fm][fn][2])),
                                 hfu(__float2half_rn(acc[fm][fn][3])));
            }
        }
    }
    #undef ISSUE
}

// ---------------------------------------------------------------------------
// logits + softmax per (b,h)
// ---------------------------------------------------------------------------
__global__ __launch_bounds__(256)
void logits_kernel(const float* __restrict__ w_qkv, const float* __restrict__ b_qkv)
{
    const int bh = blockIdx.x;
    const int b = bh >> 3, h = bh & 7;

    __shared__ float buf[9312];
    __shared__ float bqs[96], bks[96], us_[96], ws_[96];

    const int tid = threadIdx.x;
    const int tx = tid & 15;
    const int ty = tid >> 4;

    if (tid < 96) {
        bqs[tid] = b_qkv[h * DD + tid];
        bks[tid] = b_qkv[CC + h * DD + tid];
        ws_[tid] = g_U[b * 1536 + h * DD + tid];
        us_[tid] = g_U[b * 1536 + CC + h * DD + tid];
    }

    const float* Tb = g_T + (size_t)b * GSZ + (size_t)(h * DD) * CC;
    const float* Wk = w_qkv + (size_t)(CC + h * DD) * CC;

    float acc[6][6];
    #pragma unroll
    for (int i = 0; i < 6; i++)
        #pragma unroll
        for (int j = 0; j < 6; j++) acc[i][j] = 0.f;

    for (int c0 = 0; c0 < CC; c0 += 32) {
        __syncthreads();
        #pragma unroll
        for (int t = 0; t < 3; ++t) {
            const int id = tid + t * 256;
            const int row = id >> 3, f4 = id & 7;
            float4 tv = *(const float4*)(Tb + (size_t)row * CC + c0 + f4 * 4);
            float4 kv = *(const float4*)(Wk + (size_t)row * CC + c0 + f4 * 4);
            buf[(f4 * 4 + 0) * 97 + row] = tv.x;
            buf[(f4 * 4 + 1) * 97 + row] = tv.y;
            buf[(f4 * 4 + 2) * 97 + row] = tv.z;
            buf[(f4 * 4 + 3) * 97 + row] = tv.w;
            buf[3104 + (f4 * 4 + 0) * 97 + row] = kv.x;
            buf[3104 + (f4 * 4 + 1) * 97 + row] = kv.y;
            buf[3104 + (f4 * 4 + 2) * 97 + row] = kv.z;
            buf[3104 + (f4 * 4 + 3) * 97 + row] = kv.w;
        }
        __syncthreads();
        #pragma unroll 8
        for (int kk = 0; kk < 32; ++kk) {
            float qr[6], kr[6];
            #pragma unroll
            for (int i = 0; i < 6; i++) qr[i] = buf[kk * 97 + ty * 6 + i];
            #pragma unroll
            for (int j = 0; j < 6; j++) kr[j] = buf[3104 + kk * 97 + tx * 6 + j];
            #pragma unroll
            for (int i = 0; i < 6; i++)
                #pragma unroll
                for (int j = 0; j < 6; j++)
                    acc[i][j] = fmaf(qr[i], kr[j], acc[i][j]);
        }
    }
    __syncthreads();

    const float scale = 0.015625f;
    #pragma unroll
    for (int i = 0; i < 6; i++) {
        const int d = ty * 6 + i;
        #pragma unroll
        for (int j = 0; j < 6; j++) {
            const int e = tx * 6 + j;
            float v = acc[i][j] + bqs[d] * us_[e] + bks[e] * ws_[d]
                      + 4096.f * bqs[d] * bks[e];
            buf[d * 96 + e] = v * scale;
        }
    }
    __syncthreads();

    const int wid = tid >> 5, lane = tid & 31;
    for (int r = wid; r < 96; r += 8) {
        float v0 = buf[r * 96 + lane];
        float v1 = buf[r * 96 + 32 + lane];
        float v2 = buf[r * 96 + 64 + lane];
        float m = fmaxf(v0, fmaxf(v1, v2));
        #pragma unroll
        for (int off = 16; off > 0; off >>= 1)
            m = fmaxf(m, __shfl_xor_sync(0xffffffffu, m, off));
        float e0 = expf(v0 - m), e1 = expf(v1 - m), e2 = expf(v2 - m);
        float s = e0 + e1 + e2;
        #pragma unroll
        for (int off = 16; off > 0; off >>= 1)
            s += __shfl_xor_sync(0xffffffffu, s, off);
        const float inv = 1.f / s;
        float* arow = g_attn + ((size_t)bh * 96 + r) * 96;
        arow[lane]      = e0 * inv;
        arow[lane + 32] = e1 * inv;
        arow[lane + 64] = e2 * inv;
    }
}

// ---------------------------------------------------------------------------
// MT_b[c, h*96+d] = sum_e A_bh[d,e] Wv[h*96+e, c]  (fp16 hi/lo direct);
// r_bh = A_bh @ bv_h
// ---------------------------------------------------------------------------
__global__ __launch_bounds__(256)
void mt_kernel(const float* __restrict__ w_qkv, const float* __restrict__ b_qkv)
{
    const int bh = blockIdx.x;
    const int b = bh >> 3, h = bh & 7;

    __shared__ float As[96 * 97];
    __shared__ float Ws[16 * 132];
    __shared__ float bvs[96];

    const int tid = threadIdx.x;
    const int tx = tid & 15;
    const int ty = tid >> 4;

    const float* asrc = g_attn + (size_t)bh * 9216;
    for (int id = tid; id < 9216; id += 256) {
        const int r = id / 96, c = id - r * 96;
        As[r * 97 + c] = asrc[id];
    }
    if (tid < 96) bvs[tid] = b_qkv[2 * CC + h * DD + tid];
    __syncthreads();

    if (tid < 96) {
        float rv = 0.f;
        #pragma unroll 4
        for (int e = 0; e < 96; ++e) rv += As[tid * 97 + e] * bvs[e];
        g_r[b * CC + h * DD + tid] = rv;
    }

    const float* Wv = w_qkv + (size_t)(2 * CC + h * DD) * CC;
    __half* MTh = g_MThi + (size_t)b * GSZ;
    __half* MTl = g_MTlo + (size_t)b * GSZ;

    for (int c0 = 0; c0 < CC; c0 += 128) {
        float acc[8][6];
        #pragma unroll
        for (int i = 0; i < 8; i++)
            #pragma unroll
            for (int j = 0; j < 6; j++) acc[i][j] = 0.f;

        for (int e0 = 0; e0 < 96; e0 += 16) {
            __syncthreads();
            #pragma unroll
            for (int t = 0; t < 2; ++t) {
                const int id = tid + t * 256;
                const int e = id >> 5, f4 = id & 31;
                float4 v = *(const float4*)(Wv + (size_t)(e0 + e) * CC + c0 + f4 * 4);
                *(float4*)&Ws[e * 132 + f4 * 4] = v;
            }
            __syncthreads();
            #pragma unroll
            for (int e = 0; e < 16; ++e) {
                float vv[8], aa[6];
                #pragma unroll
                for (int i = 0; i < 8; i++) vv[i] = Ws[e * 132 + ty * 8 + i];
                #pragma unroll
                for (int j = 0; j < 6; j++) aa[j] = As[(tx * 6 + j) * 97 + e0 + e];
                #pragma unroll
                for (int i = 0; i < 8; i++)
                    #pragma unroll
                    for (int j = 0; j < 6; j++)
                        acc[i][j] = fmaf(vv[i], aa[j], acc[i][j]);
            }
        }
        #pragma unroll
        for (int i = 0; i < 8; i++) {
            const int c = c0 + ty * 8 + i;
            const size_t base = (size_t)c * CC + h * DD + tx * 6;
            #pragma unroll
            for (int j = 0; j < 6; j += 2) {
                __half h0, l0, h1, l1;
                split1(acc[i][j], h0, l0);
                split1(acc[i][j + 1], h1, l1);
                *(ushort2*)(MTh + base + j) = make_ushort2(hfu(h0), hfu(h1));
                *(ushort2*)(MTl + base + j) = make_ushort2(hfu(l0), hfu(l1));
            }
        }
    }
}

// ---------------------------------------------------------------------------
extern "C" void kernel_launch(void* const* d_in, const int* in_sizes, int n_in,
                              void* d_out, int out_size)
{
    const float* x      = (const float*)d_in[0];
    const float* w_qkv  = (const float*)d_in[1];
    const float* b_qkv  = (const float*)d_in[2];
    const float* w_proj = (const float*)d_in[3];
    const float* b_proj = (const float*)d_in[4];
    float*       out    = (float*)d_out;

    cudaFuncSetAttribute(tgemm_kernel<0>,
                         cudaFuncAttributeMaxDynamicSharedMemorySize, SMEM_ASK);
    cudaFuncSetAttribute(tgemm_kernel<1>,
                         cudaFuncAttributeMaxDynamicSharedMemorySize, SMEM_ASK);
    cudaFuncSetAttribute(tgemm_kernel<2>,
                         cudaFuncAttributeMaxDynamicSharedMemorySize, SMEM_ASK);
    cudaFuncSetAttribute(tgemm_kernel<3>,
                         cudaFuncAttributeMaxDynamicSharedMemorySize, SMEM_ASK);

    // 0) splits + transposed splits + column sums
    transpose_split_kernel<<<dim3(12, 1024), 256>>>(x);
    colsum_part_kernel<<<dim3(32, BB), 256>>>(x);
    colsum_red_kernel<<<BB, 768>>>();
    split_kernel<<<576, 256>>>((const float4*)w_qkv, 1, GSZ / 4);
    split_kernel<<<576, 256>>>((const float4*)w_proj, 2, GSZ / 4);

    // 1) G_b = X_b^T X_b (symmetric: 21 tiles + mirror, fp16 direct)
    tgemm_kernel<0><<<dim3(21, 1, BB), 256, SMEM_ASK>>>(nullptr);

    // 2) T_b = Wq @ G_b
    tgemm_kernel<1><<<dim3(6, 6, BB), 256, SMEM_ASK>>>(nullptr);

    // 3) rank-1 correction dots, logits + softmax
    uw_kernel<<<dim3(192, BB), 256>>>(w_qkv);
    logits_kernel<<<BB * HH, 256>>>(w_qkv, b_qkv);

    // 4) MT_b = (A @ Wv)^T stacked (fp16 direct); r_bh
    mt_kernel<<<BB * HH, 256>>>(w_qkv, b_qkv);

    // 5) P_b = Wp @ MT_b (fp16 hi only); fused output bias
    biasf_kernel<<<dim3(96, BB), 256>>>(w_proj, b_proj);
    tgemm_kernel<2><<<dim3(6, 6, BB), 256, SMEM_ASK>>>(nullptr);

    // 6) out = X @ P_b^T + biasf   (2-pass)
    tgemm_kernel<3><<<dim3(6, 512, 1), 256, SMEM_ASK>>>(out);
}

// round 8
// speedup vs baseline: 5.9200x; 1.1213x over previous
#include <cuda_runtime.h>
#include <cuda_fp16.h>
#include <cstdint>

// Problem constants
#define BB   16
#define NT   4096
#define CC   768
#define HH   8
#define DD   96
#define MM   (BB * NT)          // 65536
#define GSZ  (768 * 768)        // 589824
#define KSPL 4                  // K-split for the G GEMM

// ---------------------------------------------------------------------------
// Scratch (__device__ globals)
// ---------------------------------------------------------------------------
__device__ __half g_xhi[(size_t)MM * CC], g_xlo[(size_t)MM * CC];
__device__ __half g_xThi[(size_t)MM * CC], g_xTlo[(size_t)MM * CC]; // [b,c,n]
__device__ float g_Gpart[(size_t)BB * KSPL * 21 * 16384];           // fp32 partials
__device__ __half g_Ghi[BB * GSZ], g_Glo[BB * GSZ];
__device__ float g_T[BB * GSZ];
__device__ float g_attn[BB * HH * DD * DD];
__device__ __half g_MThi[BB * GSZ], g_MTlo[BB * GSZ];   // [b, c, h*96+d]
__device__ __half g_Phi[BB * GSZ];
__device__ __half g_wqh[GSZ], g_wql[GSZ];
__device__ __half g_wph[GSZ], g_wpl[GSZ];
__device__ float g_s[BB * CC];
__device__ float g_part2[1024 * CC];                    // per-64-row-block colsums
__device__ float g_U[BB * 1536];
__device__ float g_r[BB * CC];
__device__ float g_biasf[BB * CC];

// ---------------------------------------------------------------------------
// PTX helpers (target-agnostic)
// ---------------------------------------------------------------------------
__device__ __forceinline__ uint32_t smem_u32(const void* p) {
    uint32_t a;
    asm("{ .reg .u64 t; cvta.to.shared.u64 t, %1; cvt.u32.u64 %0, t; }"
        : "=r"(a) : "l"(p));
    return a;
}
__device__ __forceinline__ void ldsm_x4(uint32_t* r, uint32_t addr) {
    asm volatile("ldmatrix.sync.aligned.m8n8.x4.shared.b16 {%0,%1,%2,%3}, [%4];"
                 : "=r"(r[0]), "=r"(r[1]), "=r"(r[2]), "=r"(r[3]) : "r"(addr));
}
__device__ __forceinline__ void mma16816(float* c, const uint32_t* a, const uint32_t* b) {
    asm volatile(
        "mma.sync.aligned.m16n8k16.row.col.f32.f16.f16.f32 "
        "{%0,%1,%2,%3}, {%4,%5,%6,%7}, {%8,%9}, {%0,%1,%2,%3};"
        : "+f"(c[0]), "+f"(c[1]), "+f"(c[2]), "+f"(c[3])
        : "r"(a[0]), "r"(a[1]), "r"(a[2]), "r"(a[3]), "r"(b[0]), "r"(b[1]));
}
__device__ __forceinline__ void cp16(uint32_t dst, const void* src) {
    asm volatile("cp.async.cg.shared.global [%0], [%1], 16;"
                 :: "r"(dst), "l"(src) : "memory");
}
__device__ __forceinline__ void cp_commit() {
    asm volatile("cp.async.commit_group;" ::: "memory");
}
template <int N>
__device__ __forceinline__ void cp_wait() {
    asm volatile("cp.async.wait_group %0;" :: "n"(N) : "memory");
}
__device__ __forceinline__ void split1(float v, __half& h, __half& l) {
    h = __float2half_rn(v);
    l = __float2half_rn(v - __half2float(h));
}
__device__ __forceinline__ ushort hfu(__half v) { return __half_as_ushort(v); }

// ---------------------------------------------------------------------------
// transpose_split: x -> row-major hi/lo, per-batch transposed hi/lo,
// AND per-block column partial sums (fused colsum).
// ---------------------------------------------------------------------------
__global__ __launch_bounds__(256)
void transpose_split_kernel(const float* __restrict__ x)
{
    __shared__ float tile[64 * 65];
    __shared__ float colp[4][64];
    const int tid = threadIdx.x;
    const int C0 = blockIdx.x * 64;
    const int R0 = blockIdx.y * 64;

    #pragma unroll
    for (int t = 0; t < 4; ++t) {
        const int id = tid + t * 256;
        const int r = id >> 4, f4 = id & 15;
        float4 v = *(const float4*)(x + (size_t)(R0 + r) * CC + C0 + f4 * 4);
        tile[r * 65 + f4 * 4 + 0] = v.x;
        tile[r * 65 + f4 * 4 + 1] = v.y;
        tile[r * 65 + f4 * 4 + 2] = v.z;
        tile[r * 65 + f4 * 4 + 3] = v.w;
    }
    __syncthreads();

    // fused column partial sums (rows of this 64-block)
    {
        const int c = tid & 63, q = tid >> 6;
        float s = 0.f;
        #pragma unroll
        for (int r = 0; r < 16; ++r) s += tile[(q * 16 + r) * 65 + c];
        colp[q][c] = s;
    }
    __syncthreads();
    if (tid < 64)
        g_part2[(size_t)blockIdx.y * CC + C0 + tid] =
            colp[0][tid] + colp[1][tid] + colp[2][tid] + colp[3][tid];

    #pragma unroll
    for (int t = 0; t < 2; ++t) {
        const int id = tid + t * 256;
        const int r = id >> 3, g = id & 7;
        ushort h[8], l[8];
        #pragma unroll
        for (int j = 0; j < 8; j++) {
            __half hb, lb; split1(tile[r * 65 + g * 8 + j], hb, lb);
            h[j] = hfu(hb); l[j] = hfu(lb);
        }
        uint4 uh, ul;
        uh.x = h[0] | (h[1] << 16); uh.y = h[2] | (h[3] << 16);
        uh.z = h[4] | (h[5] << 16); uh.w = h[6] | (h[7] << 16);
        ul.x = l[0] | (l[1] << 16); ul.y = l[2] | (l[3] << 16);
        ul.z = l[4] | (l[5] << 16); ul.w = l[6] | (l[7] << 16);
        const size_t off = (size_t)(R0 + r) * CC + C0 + g * 8;
        *(uint4*)(g_xhi + off) = uh;
        *(uint4*)(g_xlo + off) = ul;
    }

    const int bb = R0 >> 12;
    const int n0 = R0 & 4095;
    #pragma unroll
    for (int t = 0; t < 2; ++t) {
        const int id = tid + t * 256;
        const int c = id >> 3, g = id & 7;
        ushort h[8], l[8];
        #pragma unroll
        for (int j = 0; j < 8; j++) {
            __half hb, lb; split1(tile[(g * 8 + j) * 65 + c], hb, lb);
            h[j] = hfu(hb); l[j] = hfu(lb);
        }
        uint4 uh, ul;
        uh.x = h[0] | (h[1] << 16); uh.y = h[2] | (h[3] << 16);
        uh.z = h[4] | (h[5] << 16); uh.w = h[6] | (h[7] << 16);
        ul.x = l[0] | (l[1] << 16); ul.y = l[2] | (l[3] << 16);
        ul.z = l[4] | (l[5] << 16); ul.w = l[6] | (l[7] << 16);
        const size_t off = ((size_t)bb * CC + C0 + c) * NT + n0 + g * 8;
        *(uint4*)(g_xThi + off) = uh;
        *(uint4*)(g_xTlo + off) = ul;
    }
}

// ---------------------------------------------------------------------------
// split: weights only. mode 1: wq, 2: wp
// ---------------------------------------------------------------------------
__global__ __launch_bounds__(256)
void split_kernel(const float4* __restrict__ src, int mode, int n4)
{
    int i = blockIdx.x * 256 + threadIdx.x;
    if (i >= n4) return;
    __half *hi = (mode == 1) ? g_wqh : g_wph;
    __half *lo = (mode == 1) ? g_wql : g_wpl;
    float4 v = src[i];
    float a[4] = {v.x, v.y, v.z, v.w};
    ushort h[4], l[4];
    #pragma unroll
    for (int t = 0; t < 4; t++) {
        __half hb, lb; split1(a[t], hb, lb);
        h[t] = hfu(hb); l[t] = hfu(lb);
    }
    ((ushort4*)hi)[i] = make_ushort4(h[0], h[1], h[2], h[3]);
    ((ushort4*)lo)[i] = make_ushort4(l[0], l[1], l[2], l[3]);
}

// ---------------------------------------------------------------------------
// colsum reduction: g_s[b][c] = sum over 64 row-blocks
// ---------------------------------------------------------------------------
__global__ void colsum_red_kernel()
{
    const int b = blockIdx.x, tid = threadIdx.x;   // block 768
    float s = 0.f;
    for (int k = 0; k < 64; ++k)
        s += g_part2[(size_t)(b * 64 + k) * CC + tid];
    g_s[b * CC + tid] = s;
}

// ---------------------------------------------------------------------------
// U[b][row] = dot(w_qkv[row], s_b), rows 0..1535
// ---------------------------------------------------------------------------
__global__ __launch_bounds__(256)
void uw_kernel(const float* __restrict__ w_qkv)
{
    __shared__ float ss[CC];
    const int b = blockIdx.y, tid = threadIdx.x;
    #pragma unroll
    for (int p = 0; p < 3; ++p) ss[p * 256 + tid] = g_s[b * CC + p * 256 + tid];
    __syncthreads();
    const int row = blockIdx.x * 8 + (tid >> 5);
    const int lane = tid & 31;
    const float* wr = w_qkv + (size_t)row * CC;
    float acc = 0.f;
    #pragma unroll
    for (int k = 0; k < 24; ++k) acc += wr[lane + k * 32] * ss[lane + k * 32];
    #pragma unroll
    for (int off = 16; off > 0; off >>= 1)
        acc += __shfl_xor_sync(0xffffffffu, acc, off);
    if (lane == 0) g_U[b * 1536 + row] = acc;
}

// ---------------------------------------------------------------------------
// biasf[b][j] = b_proj[j] + dot(w_proj[j], r_b)
// ---------------------------------------------------------------------------
__global__ __launch_bounds__(256)
void biasf_kernel(const float* __restrict__ w_proj, const float* __restrict__ b_proj)
{
    __shared__ float rr[CC];
    const int b = blockIdx.y, tid = threadIdx.x;
    #pragma unroll
    for (int p = 0; p < 3; ++p) rr[p * 256 + tid] = g_r[b * CC + p * 256 + tid];
    __syncthreads();
    const int j = blockIdx.x * 8 + (tid >> 5);
    const int lane = tid & 31;
    const float* wr = w_proj + (size_t)j * CC;
    float acc = 0.f;
    #pragma unroll
    for (int k = 0; k < 24; ++k) acc += wr[lane + k * 32] * rr[lane + k * 32];
    #pragma unroll
    for (int off = 16; off > 0; off >>= 1)
        acc += __shfl_xor_sync(0xffffffffu, acc, off);
    if (lane == 0) g_biasf[b * CC + j] = b_proj[j] + acc;
}

// ---------------------------------------------------------------------------
// HMMA fp16-split GEMM, templated on MODE.
//   MODE 0: G partials: Xt tile-pair, K-window 1024 per ksplit (fp32 out)
//           grid (21, KSPL, BB)
//   MODE 1: T_b = Wq @ G_b       (K=768, fp32 out)
//   MODE 2: P_b = Wp @ MT_b      (K=768, fp16 hi-only out)
//   MODE 3: out = X @ P_b^T + biasf  (K=768, 2-PASS, fp32 out)
// ---------------------------------------------------------------------------
#define SROW 80
#define TILE_B (128 * SROW)
#define STAGE_B (4 * TILE_B)
#define SMEM_ASK (2 * STAGE_B)

template <int MODE>
__global__ __launch_bounds__(256, 2)
void tgemm_kernel(float* __restrict__ Cp)
{
    int bm = blockIdx.y, bn = blockIdx.x;
    int b = blockIdx.z;
    int ksplit = 0;
    if (MODE == 0) {
        int t = blockIdx.x;
        bm = 0;
        while (t >= 6 - bm) { t -= 6 - bm; bm++; }
        bn = bm + t;
        ksplit = blockIdx.y;
    }

    const __half *Ah, *Al, *Wh, *Wl;
    constexpr int KROW  = (MODE == 0) ? 4096 : 768;   // row stride
    constexpr int KITER = (MODE == 0) ? 1024 : 768;   // K handled per CTA

    if (MODE == 0) {
        const size_t ab = ((size_t)b * CC + bm * 128) * NT + ksplit * KITER;
        const size_t wb = ((size_t)b * CC + bn * 128) * NT + ksplit * KITER;
        Ah = g_xThi + ab; Al = g_xTlo + ab;
        Wh = g_xThi + wb; Wl = g_xTlo + wb;
    } else if (MODE == 1) {
        Ah = g_wqh + (size_t)bm * 128 * CC; Al = g_wql + (size_t)bm * 128 * CC;
        const size_t wb = (size_t)b * GSZ + (size_t)bn * 128 * CC;
        Wh = g_Ghi + wb; Wl = g_Glo + wb;
    } else if (MODE == 2) {
        Ah = g_wph + (size_t)bm * 128 * CC; Al = g_wpl + (size_t)bm * 128 * CC;
        const size_t wb = (size_t)b * GSZ + (size_t)bn * 128 * CC;
        Wh = g_MThi + wb; Wl = g_MTlo + wb;
    } else {
        b = bm >> 5;
        const size_t ab = (size_t)bm * 128 * CC;
        Ah = g_xhi + ab; Al = g_xlo + ab;
        const size_t wb = (size_t)b * GSZ + (size_t)bn * 128 * CC;
        Wh = g_Phi + wb; Wl = Wh;    // unused in 2-pass
    }

    extern __shared__ char smem[];
    const uint32_t ubase = smem_u32(smem);

    const int tid  = threadIdx.x;
    const int wid  = tid >> 5;
    const int lane = tid & 31;
    const int wm   = wid & 1;
    const int wn   = wid >> 1;

    const int cr = tid >> 2;
    const int cg = tid & 3;

    #define ISSUE(s) do { \
        const uint32_t sb_ = ubase + ((s) & 1) * STAGE_B; \
        const int kof_ = (s) * 32; \
        _Pragma("unroll") \
        for (int t_ = 0; t_ < 2; ++t_) { \
            const int r_ = cr + t_ * 64; \
            const size_t off_ = (size_t)r_ * KROW + kof_ + cg * 8; \
            const uint32_t d_ = sb_ + r_ * SROW + cg * 16; \
            cp16(d_ + 0 * TILE_B, Ah + off_); \
            cp16(d_ + 1 * TILE_B, Al + off_); \
            cp16(d_ + 2 * TILE_B, Wh + off_); \
            if (MODE != 3) cp16(d_ + 3 * TILE_B, Wl + off_); \
        } \
        cp_commit(); \
    } while (0)

    float acc[4][4][4];
    #pragma unroll
    for (int i = 0; i < 4; i++)
        #pragma unroll
        for (int j = 0; j < 4; j++)
            #pragma unroll
            for (int q = 0; q < 4; q++) acc[i][j][q] = 0.f;

    const int laneRA = lane & 15;
    const int laneGA = lane >> 4;
    const int laneRB = (lane & 7) | ((lane >> 4) << 3);
    const int laneGB = (lane >> 3) & 1;

    const int NK = KITER >> 5;

    ISSUE(0);
    ISSUE(1);

    for (int kb = 0; kb < NK; ++kb) {
        if (kb + 1 < NK) cp_wait<1>(); else cp_wait<0>();
        __syncthreads();

        const uint32_t sb = ubase + (kb & 1) * STAGE_B;
        const uint32_t aBase = sb + (wm * 64 + laneRA) * SROW + laneGA * 16;
        const uint32_t bBase = sb + 2 * TILE_B + (wn * 32 + laneRB) * SROW + laneGB * 16;

        #pragma unroll
        for (int ks = 0; ks < 2; ++ks) {
            const uint32_t ko = ks * 32;
            uint32_t bh[4][2], bl[4][2];
            #pragma unroll
            for (int fp = 0; fp < 2; fp++) {
                uint32_t q[4];
                ldsm_x4(q, bBase + fp * (16 * SROW) + ko);
                bh[2 * fp][0] = q[0]; bh[2 * fp][1] = q[1];
                bh[2 * fp + 1][0] = q[2]; bh[2 * fp + 1][1] = q[3];
                if (MODE != 3) {
                    ldsm_x4(q, bBase + TILE_B + fp * (16 * SROW) + ko);
                    bl[2 * fp][0] = q[0]; bl[2 * fp][1] = q[1];
                    bl[2 * fp + 1][0] = q[2]; bl[2 * fp + 1][1] = q[3];
                }
            }
            #pragma unroll
            for (int fm = 0; fm < 4; fm++) {
                uint32_t ah[4], al[4];
                ldsm_x4(ah, aBase + fm * (16 * SROW) + ko);
                ldsm_x4(al, aBase + TILE_B + fm * (16 * SROW) + ko);
                #pragma unroll
                for (int fn = 0; fn < 4; fn++) {
                    mma16816(acc[fm][fn], ah, bh[fn]);
                    if (MODE != 3) mma16816(acc[fm][fn], ah, bl[fn]);
                    mma16816(acc[fm][fn], al, bh[fn]);
                }
            }
        }

        if (kb + 2 < NK) {
            __syncthreads();
            ISSUE(kb + 2);
        }
    }

    const int gid4 = lane >> 2;
    const int tig  = lane & 3;

    if (MODE == 1 || MODE == 3) {
        float* C = (MODE == 1) ? (g_T + (size_t)b * GSZ) : Cp;
        const float* bias = (MODE == 3) ? (g_biasf + b * CC) : nullptr;
        #pragma unroll
        for (int fm = 0; fm < 4; fm++) {
            const int m0 = bm * 128 + wm * 64 + fm * 16 + gid4;
            #pragma unroll
            for (int fn = 0; fn < 4; fn++) {
                const int col = bn * 128 + wn * 32 + fn * 8 + tig * 2;
                float bx = 0.f, by = 0.f;
                if (MODE == 3) { bx = bias[col]; by = bias[col + 1]; }
                float2 o;
                o.x = acc[fm][fn][0] + bx; o.y = acc[fm][fn][1] + by;
                *(float2*)(C + (size_t)m0 * CC + col) = o;
                o.x = acc[fm][fn][2] + bx; o.y = acc[fm][fn][3] + by;
                *(float2*)(C + (size_t)(m0 + 8) * CC + col) = o;
            }
        }
    } else if (MODE == 0) {
        // fp32 partial, local 128x128 tile, coalesced
        float* P = g_Gpart + (((size_t)b * KSPL + ksplit) * 21 + blockIdx.x) * 16384;
        #pragma unroll
        for (int fm = 0; fm < 4; fm++) {
            const int m0 = wm * 64 + fm * 16 + gid4;
            #pragma unroll
            for (int fn = 0; fn < 4; fn++) {
                const int col = wn * 32 + fn * 8 + tig * 2;
                *(float2*)(P + (size_t)m0 * 128 + col) =
                    make_float2(acc[fm][fn][0], acc[fm][fn][1]);
                *(float2*)(P + (size_t)(m0 + 8) * 128 + col) =
                    make_float2(acc[fm][fn][2], acc[fm][fn][3]);
            }
        }
    } else {   // MODE 2: P hi only
        __half* Hi = g_Phi + (size_t)b * GSZ;
        #pragma unroll
        for (int fm = 0; fm < 4; fm++) {
            const int m0 = bm * 128 + wm * 64 + fm * 16 + gid4;
            #pragma unroll
            for (int fn = 0; fn < 4; fn++) {
                const int col = bn * 128 + wn * 32 + fn * 8 + tig * 2;
                *(ushort2*)(Hi + (size_t)m0 * CC + col) =
                    make_ushort2(hfu(__float2half_rn(acc[fm][fn][0])),
                                 hfu(__float2half_rn(acc[fm][fn][1])));
                *(ushort2*)(Hi + (size_t)(m0 + 8) * CC + col) =
                    make_ushort2(hfu(__float2half_rn(acc[fm][fn][2])),
                                 hfu(__float2half_rn(acc[fm][fn][3])));
            }
        }
    }
    #undef ISSUE
}

// ---------------------------------------------------------------------------
// greduce: sum KSPL partials of a G tile, split to fp16 hi/lo, write tile
// and its symmetric mirror (smem transpose). grid (21, 16), block 256.
// ---------------------------------------------------------------------------
__global__ __launch_bounds__(256)
void greduce_kernel()
{
    __shared__ float s[64][132];
    int t = blockIdx.x;
    const int b = blockIdx.y;
    int bm = 0;
    while (t >= 6 - bm) { t -= 6 - bm; bm++; }
    const int bn = bm + t;
    const int tid = threadIdx.x;

    const float* P0 = g_Gpart + (((size_t)b * KSPL) * 21 + blockIdx.x) * 16384;
    const float* P1 = P0 + (size_t)21 * 16384;
    const float* P2 = P1 + (size_t)21 * 16384;
    const float* P3 = P2 + (size_t)21 * 16384;
    __half* Hi = g_Ghi + (size_t)b * GSZ;
    __half* Lo = g_Glo + (size_t)b * GSZ;

    for (int hhalf = 0; hhalf < 2; ++hhalf) {
        const int rbase = hhalf * 64;
        for (int e4 = tid; e4 < 2048; e4 += 256) {
            const int r = e4 >> 5, c4 = e4 & 31;
            const size_t o = (size_t)(rbase + r) * 128 + c4 * 4;
            float4 a = *(const float4*)(P0 + o);
            float4 bb = *(const float4*)(P1 + o);
            float4 c = *(const float4*)(P2 + o);
            float4 d = *(const float4*)(P3 + o);
            s[r][c4 * 4 + 0] = a.x + bb.x + c.x + d.x;
            s[r][c4 * 4 + 1] = a.y + bb.y + c.y + d.y;
            s[r][c4 * 4 + 2] = a.z + bb.z + c.z + d.z;
            s[r][c4 * 4 + 3] = a.w + bb.w + c.w + d.w;
        }
        __syncthreads();

        // normal write: rows bm*128+rbase+r, cols bn*128..
        {
            const int r = tid >> 2, cb = (tid & 3) * 32;
            const size_t rowo = (size_t)(bm * 128 + rbase + r) * CC + bn * 128 + cb;
            #pragma unroll
            for (int k = 0; k < 32; k += 8) {
                ushort hh[8], ll[8];
                #pragma unroll
                for (int j = 0; j < 8; ++j) {
                    __half hb, lb; split1(s[r][cb + k + j], hb, lb);
                    hh[j] = hfu(hb); ll[j] = hfu(lb);
                }
                uint4 uh, ul;
                uh.x = hh[0] | (hh[1] << 16); uh.y = hh[2] | (hh[3] << 16);
                uh.z = hh[4] | (hh[5] << 16); uh.w = hh[6] | (hh[7] << 16);
                ul.x = ll[0] | (ll[1] << 16); ul.y = ll[2] | (ll[3] << 16);
                ul.z = ll[4] | (ll[5] << 16); ul.w = ll[6] | (ll[7] << 16);
                *(uint4*)(Hi + rowo + k) = uh;
                *(uint4*)(Lo + rowo + k) = ul;
            }
        }
        // mirror write: rows bn*128+j, cols bm*128+rbase..
        if (bm != bn) {
            const int j = tid >> 1, cb = (tid & 1) * 32;
            const size_t rowo = (size_t)(bn * 128 + j) * CC + bm * 128 + rbase + cb;
            #pragma unroll
            for (int k = 0; k < 32; k += 8) {
                ushort hh[8], ll[8];
                #pragma unroll
                for (int jj = 0; jj < 8; ++jj) {
                    __half hb, lb; split1(s[cb + k + jj][j], hb, lb);
                    hh[jj] = hfu(hb); ll[jj] = hfu(lb);
                }
                uint4 uh, ul;
                uh.x = hh[0] | (hh[1] << 16); uh.y = hh[2] | (hh[3] << 16);
                uh.z = hh[4] | (hh[5] << 16); uh.w = hh[6] | (hh[7] << 16);
                ul.x = ll[0] | (ll[1] << 16); ul.y = ll[2] | (ll[3] << 16);
                ul.z = ll[4] | (ll[5] << 16); ul.w = ll[6] | (ll[7] << 16);
                *(uint4*)(Hi + rowo + k) = uh;
                *(uint4*)(Lo + rowo + k) = ul;
            }
        }
        __syncthreads();
    }
}

// ---------------------------------------------------------------------------
// logits + softmax per (b,h), split into 2 d-halves. grid (128, 2).
// ---------------------------------------------------------------------------
__global__ __launch_bounds__(256)
void logits_kernel(const float* __restrict__ w_qkv, const float* __restrict__ b_qkv)
{
    const int bh = blockIdx.x;
    const int yh = blockIdx.y;           // d-half: rows yh*48 .. yh*48+47
    const int b = bh >> 3, h = bh & 7;

    __shared__ float buf[9312];
    __shared__ float bqs[48], ws_[48], bks[96], us_[96];

    const int tid = threadIdx.x;
    const int tx = tid & 15;
    const int ty = tid >> 4;

    if (tid < 48) {
        bqs[tid] = b_qkv[h * DD + yh * 48 + tid];
        ws_[tid] = g_U[b * 1536 + h * DD + yh * 48 + tid];
    }
    if (tid < 96) {
        bks[tid] = b_qkv[CC + h * DD + tid];
        us_[tid] = g_U[b * 1536 + CC + h * DD + tid];
    }

    const float* Tb = g_T + (size_t)b * GSZ + (size_t)(h * DD) * CC;
    const float* Wk = w_qkv + (size_t)(CC + h * DD) * CC;

    float acc[3][6];
    #pragma unroll
    for (int i = 0; i < 3; i++)
        #pragma unroll
        for (int j = 0; j < 6; j++) acc[i][j] = 0.f;

    for (int c0 = 0; c0 < CC; c0 += 32) {
        __syncthreads();
        #pragma unroll
        for (int t = 0; t < 3; ++t) {
            const int id = tid + t * 256;
            const int row = id >> 3, f4 = id & 7;
            float4 tv = *(const float4*)(Tb + (size_t)row * CC + c0 + f4 * 4);
            float4 kv = *(const float4*)(Wk + (size_t)row * CC + c0 + f4 * 4);
            buf[(f4 * 4 + 0) * 97 + row] = tv.x;
            buf[(f4 * 4 + 1) * 97 + row] = tv.y;
            buf[(f4 * 4 + 2) * 97 + row] = tv.z;
            buf[(f4 * 4 + 3) * 97 + row] = tv.w;
            buf[3104 + (f4 * 4 + 0) * 97 + row] = kv.x;
            buf[3104 + (f4 * 4 + 1) * 97 + row] = kv.y;
            buf[3104 + (f4 * 4 + 2) * 97 + row] = kv.z;
            buf[3104 + (f4 * 4 + 3) * 97 + row] = kv.w;
        }
        __syncthreads();
        #pragma unroll 8
        for (int kk = 0; kk < 32; ++kk) {
            float qr[3], kr[6];
            #pragma unroll
            for (int i = 0; i < 3; i++)
                qr[i] = buf[kk * 97 + yh * 48 + ty * 3 + i];
            #pragma unroll
            for (int j = 0; j < 6; j++) kr[j] = buf[3104 + kk * 97 + tx * 6 + j];
            #pragma unroll
            for (int i = 0; i < 3; i++)
                #pragma unroll
                for (int j = 0; j < 6; j++)
                    acc[i][j] = fmaf(qr[i], kr[j], acc[i][j]);
        }
    }
    __syncthreads();

    const float scale = 0.015625f;
    #pragma unroll
    for (int i = 0; i < 3; i++) {
        const int dl = ty * 3 + i;                  // local d (0..47)
        #pragma unroll
        for (int j = 0; j < 6; j++) {
            const int e = tx * 6 + j;
            float v = acc[i][j] + bqs[dl] * us_[e] + bks[e] * ws_[dl]
                      + 4096.f * bqs[dl] * bks[e];
            buf[dl * 96 + e] = v * scale;
        }
    }
    __syncthreads();

    const int wid = tid >> 5, lane = tid & 31;
    for (int r = wid; r < 48; r += 8) {
        float v0 = buf[r * 96 + lane];
        float v1 = buf[r * 96 + 32 + lane];
        float v2 = buf[r * 96 + 64 + lane];
        float m = fmaxf(v0, fmaxf(v1, v2));
        #pragma unroll
        for (int off = 16; off > 0; off >>= 1)
            m = fmaxf(m, __shfl_xor_sync(0xffffffffu, m, off));
        float e0 = expf(v0 - m), e1 = expf(v1 - m), e2 = expf(v2 - m);
        float s = e0 + e1 + e2;
        #pragma unroll
        for (int off = 16; off > 0; off >>= 1)
            s += __shfl_xor_sync(0xffffffffu, s, off);
        const float inv = 1.f / s;
        float* arow = g_attn + ((size_t)bh * 96 + yh * 48 + r) * 96;
        arow[lane]      = e0 * inv;
        arow[lane + 32] = e1 * inv;
        arow[lane + 64] = e2 * inv;
    }
}

// ---------------------------------------------------------------------------
// MT_b[c, h*96+d] = sum_e A_bh[d,e] Wv[h*96+e, c]  (fp16 hi/lo direct);
// r_bh = A_bh @ bv_h.  grid (6, 128): x = c-block of 128.
// ---------------------------------------------------------------------------
__global__ __launch_bounds__(256)
void mt_kernel(const float* __restrict__ w_qkv, const float* __restrict__ b_qkv)
{
    const int c0 = blockIdx.x * 128;
    const int bh = blockIdx.y;
    const int b = bh >> 3, h = bh & 7;

    __shared__ float As[96 * 97];
    __shared__ float Ws[16 * 132];
    __shared__ float bvs[96];

    const int tid = threadIdx.x;
    const int tx = tid & 15;
    const int ty = tid >> 4;

    const float* asrc = g_attn + (size_t)bh * 9216;
    for (int id = tid; id < 9216; id += 256) {
        const int r = id / 96, c = id - r * 96;
        As[r * 97 + c] = asrc[id];
    }
    if (tid < 96) bvs[tid] = b_qkv[2 * CC + h * DD + tid];
    __syncthreads();

    if (blockIdx.x == 0 && tid < 96) {
        float rv = 0.f;
        #pragma unroll 4
        for (int e = 0; e < 96; ++e) rv += As[tid * 97 + e] * bvs[e];
        g_r[b * CC + h * DD + tid] = rv;
    }

    const float* Wv = w_qkv + (size_t)(2 * CC + h * DD) * CC;
    __half* MTh = g_MThi + (size_t)b * GSZ;
    __half* MTl = g_MTlo + (size_t)b * GSZ;

    float acc[8][6];
    #pragma unroll
    for (int i = 0; i < 8; i++)
        #pragma unroll
        for (int j = 0; j < 6; j++) acc[i][j] = 0.f;

    for (int e0 = 0; e0 < 96; e0 += 16) {
        if (e0) __syncthreads();
        #pragma unroll
        for (int t = 0; t < 2; ++t) {
            const int id = tid + t * 256;
            const int e = id >> 5, f4 = id & 31;
            float4 v = *(const float4*)(Wv + (size_t)(e0 + e) * CC + c0 + f4 * 4);
            *(float4*)&Ws[e * 132 + f4 * 4] = v;
        }
        __syncthreads();
        #pragma unroll
        for (int e = 0; e < 16; ++e) {
            float vv[8], aa[6];
            #pragma unroll
            for (int i = 0; i < 8; i++) vv[i] = Ws[e * 132 + ty * 8 + i];
            #pragma unroll
            for (int j = 0; j < 6; j++) aa[j] = As[(tx * 6 + j) * 97 + e0 + e];
            #pragma unroll
            for (int i = 0; i < 8; i++)
                #pragma unroll
                for (int j = 0; j < 6; j++)
                    acc[i][j] = fmaf(vv[i], aa[j], acc[i][j]);
        }
    }
    #pragma unroll
    for (int i = 0; i < 8; i++) {
        const int c = c0 + ty * 8 + i;
        const size_t base = (size_t)c * CC + h * DD + tx * 6;
        #pragma unroll
        for (int j = 0; j < 6; j += 2) {
            __half h0, l0, h1, l1;
            split1(acc[i][j], h0, l0);
            split1(acc[i][j + 1], h1, l1);
            *(ushort2*)(MTh + base + j) = make_ushort2(hfu(h0), hfu(h1));
            *(ushort2*)(MTl + base + j) = make_ushort2(hfu(l0), hfu(l1));
        }
    }
}

// ---------------------------------------------------------------------------
extern "C" void kernel_launch(void* const* d_in, const int* in_sizes, int n_in,
                              void* d_out, int out_size)
{
    const float* x      = (const float*)d_in[0];
    const float* w_qkv  = (const float*)d_in[1];
    const float* b_qkv  = (const float*)d_in[2];
    const float* w_proj = (const float*)d_in[3];
    const float* b_proj = (const float*)d_in[4];
    float*       out    = (float*)d_out;

    cudaFuncSetAttribute(tgemm_kernel<0>,
                         cudaFuncAttributeMaxDynamicSharedMemorySize, SMEM_ASK);
    cudaFuncSetAttribute(tgemm_kernel<1>,
                         cudaFuncAttributeMaxDynamicSharedMemorySize, SMEM_ASK);
    cudaFuncSetAttribute(tgemm_kernel<2>,
                         cudaFuncAttributeMaxDynamicSharedMemorySize, SMEM_ASK);
    cudaFuncSetAttribute(tgemm_kernel<3>,
                         cudaFuncAttributeMaxDynamicSharedMemorySize, SMEM_ASK);

    // 0) splits + transposed splits + fused column sums
    transpose_split_kernel<<<dim3(12, 1024), 256>>>(x);
    colsum_red_kernel<<<BB, 768>>>();
    split_kernel<<<576, 256>>>((const float4*)w_qkv, 1, GSZ / 4);
    split_kernel<<<576, 256>>>((const float4*)w_proj, 2, GSZ / 4);

    // 1) G partials (K-split x4) + reduce/split/mirror
    tgemm_kernel<0><<<dim3(21, KSPL, BB), 256, SMEM_ASK>>>(nullptr);
    greduce_kernel<<<dim3(21, BB), 256>>>();

    // 2) T_b = Wq @ G_b
    tgemm_kernel<1><<<dim3(6, 6, BB), 256, SMEM_ASK>>>(nullptr);

    // 3) rank-1 correction dots, logits + softmax (d-split x2)
    uw_kernel<<<dim3(192, BB), 256>>>(w_qkv);
    logits_kernel<<<dim3(BB * HH, 2), 256>>>(w_qkv, b_qkv);

    // 4) MT_b = (A @ Wv)^T stacked (c-split x6); r_bh
    mt_kernel<<<dim3(6, BB * HH), 256>>>(w_qkv, b_qkv);

    // 5) P_b = Wp @ MT_b (fp16 hi only); fused output bias
    biasf_kernel<<<dim3(96, BB), 256>>>(w_proj, b_proj);
    tgemm_kernel<2><<<dim3(6, 6, BB), 256, SMEM_ASK>>>(nullptr);

    // 6) out = X @ P_b^T + biasf   (2-pass)
    tgemm_kernel<3><<<dim3(6, 512, 1), 256, SMEM_ASK>>>(out);
}

// round 9
// speedup vs baseline: 6.8808x; 1.1623x over previous
#include <cuda_runtime.h>
#include <cuda_fp16.h>
#include <cstdint>

// Problem constants
#define BB   16
#define NT   4096
#define CC   768
#define HH   8
#define DD   96
#define MM   (BB * NT)          // 65536
#define GSZ  (768 * 768)        // 589824
#define KSPL 4                  // K-split for the G GEMM

// ---------------------------------------------------------------------------
// Scratch (__device__ globals)
// ---------------------------------------------------------------------------
__device__ __half g_xhi[(size_t)MM * CC];
__device__ __half g_xThi[(size_t)MM * CC], g_xTlo[(size_t)MM * CC]; // [b,c,n]
__device__ float g_Gpart[(size_t)BB * KSPL * 21 * 16384];           // fp32 partials
__device__ __half g_Ghi[BB * GSZ], g_Glo[BB * GSZ];
__device__ float g_T[BB * GSZ];
__device__ float g_attn[BB * HH * DD * DD];
__device__ __half g_MThi[BB * GSZ], g_MTlo[BB * GSZ];   // [b, c, h*96+d]
__device__ __half g_Phi[BB * GSZ];
__device__ __half g_wqh[GSZ], g_wql[GSZ];
__device__ __half g_wph[GSZ], g_wpl[GSZ];
__device__ float g_s[BB * CC];
__device__ float g_part2[1024 * CC];                    // per-64-row-block colsums
__device__ float g_U[BB * 1536];
__device__ float g_r[BB * CC];
__device__ float g_biasf[BB * CC];

// ---------------------------------------------------------------------------
// PTX helpers (target-agnostic)
// ---------------------------------------------------------------------------
__device__ __forceinline__ uint32_t smem_u32(const void* p) {
    uint32_t a;
    asm("{ .reg .u64 t; cvta.to.shared.u64 t, %1; cvt.u32.u64 %0, t; }"
        : "=r"(a) : "l"(p));
    return a;
}
__device__ __forceinline__ void ldsm_x4(uint32_t* r, uint32_t addr) {
    asm volatile("ldmatrix.sync.aligned.m8n8.x4.shared.b16 {%0,%1,%2,%3}, [%4];"
                 : "=r"(r[0]), "=r"(r[1]), "=r"(r[2]), "=r"(r[3]) : "r"(addr));
}
__device__ __forceinline__ void mma16816(float* c, const uint32_t* a, const uint32_t* b) {
    asm volatile(
        "mma.sync.aligned.m16n8k16.row.col.f32.f16.f16.f32 "
        "{%0,%1,%2,%3}, {%4,%5,%6,%7}, {%8,%9}, {%0,%1,%2,%3};"
        : "+f"(c[0]), "+f"(c[1]), "+f"(c[2]), "+f"(c[3])
        : "r"(a[0]), "r"(a[1]), "r"(a[2]), "r"(a[3]), "r"(b[0]), "r"(b[1]));
}
__device__ __forceinline__ void cp16(uint32_t dst, const void* src) {
    asm volatile("cp.async.cg.shared.global [%0], [%1], 16;"
                 :: "r"(dst), "l"(src) : "memory");
}
__device__ __forceinline__ void cp_commit() {
    asm volatile("cp.async.commit_group;" ::: "memory");
}
template <int N>
__device__ __forceinline__ void cp_wait() {
    asm volatile("cp.async.wait_group %0;" :: "n"(N) : "memory");
}
__device__ __forceinline__ void split1(float v, __half& h, __half& l) {
    h = __float2half_rn(v);
    l = __float2half_rn(v - __half2float(h));
}
__device__ __forceinline__ ushort hfu(__half v) { return __half_as_ushort(v); }

// ---------------------------------------------------------------------------
// transpose_split: x -> row-major hi, per-batch transposed hi/lo,
// AND per-block column partial sums (fused colsum).
// ---------------------------------------------------------------------------
__global__ __launch_bounds__(256)
void transpose_split_kernel(const float* __restrict__ x)
{
    __shared__ float tile[64 * 65];
    __shared__ float colp[4][64];
    const int tid = threadIdx.x;
    const int C0 = blockIdx.x * 64;
    const int R0 = blockIdx.y * 64;

    #pragma unroll
    for (int t = 0; t < 4; ++t) {
        const int id = tid + t * 256;
        const int r = id >> 4, f4 = id & 15;
        float4 v = *(const float4*)(x + (size_t)(R0 + r) * CC + C0 + f4 * 4);
        tile[r * 65 + f4 * 4 + 0] = v.x;
        tile[r * 65 + f4 * 4 + 1] = v.y;
        tile[r * 65 + f4 * 4 + 2] = v.z;
        tile[r * 65 + f4 * 4 + 3] = v.w;
    }
    __syncthreads();

    // fused column partial sums
    {
        const int c = tid & 63, q = tid >> 6;
        float s = 0.f;
        #pragma unroll
        for (int r = 0; r < 16; ++r) s += tile[(q * 16 + r) * 65 + c];
        colp[q][c] = s;
    }
    __syncthreads();
    if (tid < 64)
        g_part2[(size_t)blockIdx.y * CC + C0 + tid] =
            colp[0][tid] + colp[1][tid] + colp[2][tid] + colp[3][tid];

    // row-major hi only (lo no longer needed downstream)
    #pragma unroll
    for (int t = 0; t < 2; ++t) {
        const int id = tid + t * 256;
        const int r = id >> 3, g = id & 7;
        ushort h[8];
        #pragma unroll
        for (int j = 0; j < 8; j++)
            h[j] = hfu(__float2half_rn(tile[r * 65 + g * 8 + j]));
        uint4 uh;
        uh.x = h[0] | (h[1] << 16); uh.y = h[2] | (h[3] << 16);
        uh.z = h[4] | (h[5] << 16); uh.w = h[6] | (h[7] << 16);
        const size_t off = (size_t)(R0 + r) * CC + C0 + g * 8;
        *(uint4*)(g_xhi + off) = uh;
    }

    const int bb = R0 >> 12;
    const int n0 = R0 & 4095;
    #pragma unroll
    for (int t = 0; t < 2; ++t) {
        const int id = tid + t * 256;
        const int c = id >> 3, g = id & 7;
        ushort h[8], l[8];
        #pragma unroll
        for (int j = 0; j < 8; j++) {
            __half hb, lb; split1(tile[(g * 8 + j) * 65 + c], hb, lb);
            h[j] = hfu(hb); l[j] = hfu(lb);
        }
        uint4 uh, ul;
        uh.x = h[0] | (h[1] << 16); uh.y = h[2] | (h[3] << 16);
        uh.z = h[4] | (h[5] << 16); uh.w = h[6] | (h[7] << 16);
        ul.x = l[0] | (l[1] << 16); ul.y = l[2] | (l[3] << 16);
        ul.z = l[4] | (l[5] << 16); ul.w = l[6] | (l[7] << 16);
        const size_t off = ((size_t)bb * CC + C0 + c) * NT + n0 + g * 8;
        *(uint4*)(g_xThi + off) = uh;
        *(uint4*)(g_xTlo + off) = ul;
    }
}

// ---------------------------------------------------------------------------
// splitw: both weight matrices in one launch. grid 1152.
// ---------------------------------------------------------------------------
__global__ __launch_bounds__(256)
void splitw_kernel(const float4* __restrict__ wq, const float4* __restrict__ wp)
{
    int i = blockIdx.x * 256 + threadIdx.x;
    const float4* src;
    __half *hi, *lo;
    int j;
    if (i < GSZ / 4) { src = wq; hi = g_wqh; lo = g_wql; j = i; }
    else             { src = wp; hi = g_wph; lo = g_wpl; j = i - GSZ / 4; }
    float4 v = src[j];
    float a[4] = {v.x, v.y, v.z, v.w};
    ushort h[4], l[4];
    #pragma unroll
    for (int t = 0; t < 4; t++) {
        __half hb, lb; split1(a[t], hb, lb);
        h[t] = hfu(hb); l[t] = hfu(lb);
    }
    ((ushort4*)hi)[j] = make_ushort4(h[0], h[1], h[2], h[3]);
    ((ushort4*)lo)[j] = make_ushort4(l[0], l[1], l[2], l[3]);
}

// ---------------------------------------------------------------------------
// colsum reduction
// ---------------------------------------------------------------------------
__global__ void colsum_red_kernel()
{
    const int b = blockIdx.x, tid = threadIdx.x;   // block 768
    float s = 0.f;
    for (int k = 0; k < 64; ++k)
        s += g_part2[(size_t)(b * 64 + k) * CC + tid];
    g_s[b * CC + tid] = s;
}

// ---------------------------------------------------------------------------
// U[b][row] = dot(w_qkv[row], s_b), rows 0..1535
// ---------------------------------------------------------------------------
__global__ __launch_bounds__(256)
void uw_kernel(const float* __restrict__ w_qkv)
{
    __shared__ float ss[CC];
    const int b = blockIdx.y, tid = threadIdx.x;
    #pragma unroll
    for (int p = 0; p < 3; ++p) ss[p * 256 + tid] = g_s[b * CC + p * 256 + tid];
    __syncthreads();
    const int row = blockIdx.x * 8 + (tid >> 5);
    const int lane = tid & 31;
    const float* wr = w_qkv + (size_t)row * CC;
    float acc = 0.f;
    #pragma unroll
    for (int k = 0; k < 24; ++k) acc += wr[lane + k * 32] * ss[lane + k * 32];
    #pragma unroll
    for (int off = 16; off > 0; off >>= 1)
        acc += __shfl_xor_sync(0xffffffffu, acc, off);
    if (lane == 0) g_U[b * 1536 + row] = acc;
}

// ---------------------------------------------------------------------------
// biasf[b][j] = b_proj[j] + dot(w_proj[j], r_b)
// ---------------------------------------------------------------------------
__global__ __launch_bounds__(256)
void biasf_kernel(const float* __restrict__ w_proj, const float* __restrict__ b_proj)
{
    __shared__ float rr[CC];
    const int b = blockIdx.y, tid = threadIdx.x;
    #pragma unroll
    for (int p = 0; p < 3; ++p) rr[p * 256 + tid] = g_r[b * CC + p * 256 + tid];
    __syncthreads();
    const int j = blockIdx.x * 8 + (tid >> 5);
    const int lane = tid & 31;
    const float* wr = w_proj + (size_t)j * CC;
    float acc = 0.f;
    #pragma unroll
    for (int k = 0; k < 24; ++k) acc += wr[lane + k * 32] * rr[lane + k * 32];
    #pragma unroll
    for (int off = 16; off > 0; off >>= 1)
        acc += __shfl_xor_sync(0xffffffffu, acc, off);
    if (lane == 0) g_biasf[b * CC + j] = b_proj[j] + acc;
}

// ---------------------------------------------------------------------------
// HMMA fp16-split GEMM, templated on MODE.
//   MODE 0: G partials (K-split, 3-pass, fp32 out), grid (21, KSPL, BB)
//   MODE 1: T_b = Wq @ G_b       (K=768, 3-pass, fp32 out)
//   MODE 2: P_b = Wp @ MT_b      (K=768, 3-pass, fp16 hi-only out)
//   MODE 3: out = X_hi @ P_hi^T + biasf  (K=768, SINGLE-PASS fp16,
//           2 tiles/stage, 4-stage pipeline, 1 barrier/chunk)
// ---------------------------------------------------------------------------
#define SROW 80
#define TILE_B (128 * SROW)
#define SMEM_ASK (8 * TILE_B)    // 81920 both variants

template <int MODE>
__global__ __launch_bounds__(256, 2)
void tgemm_kernel(float* __restrict__ Cp)
{
    constexpr int NTILES = (MODE == 3) ? 2 : 4;
    constexpr int NSTAGE = (MODE == 3) ? 4 : 2;
    constexpr int STAGE_B = NTILES * TILE_B;
    constexpr int BOFF = (MODE == 3) ? TILE_B : 2 * TILE_B;

    int bm = blockIdx.y, bn = blockIdx.x;
    int b = blockIdx.z;
    int ksplit = 0;
    if (MODE == 0) {
        int t = blockIdx.x;
        bm = 0;
        while (t >= 6 - bm) { t -= 6 - bm; bm++; }
        bn = bm + t;
        ksplit = blockIdx.y;
    }

    const __half *Ah, *Al = nullptr, *Wh, *Wl = nullptr;
    constexpr int KROW  = (MODE == 0) ? 4096 : 768;
    constexpr int KITER = (MODE == 0) ? 1024 : 768;

    if (MODE == 0) {
        const size_t ab = ((size_t)b * CC + bm * 128) * NT + ksplit * KITER;
        const size_t wb = ((size_t)b * CC + bn * 128) * NT + ksplit * KITER;
        Ah = g_xThi + ab; Al = g_xTlo + ab;
        Wh = g_xThi + wb; Wl = g_xTlo + wb;
    } else if (MODE == 1) {
        Ah = g_wqh + (size_t)bm * 128 * CC; Al = g_wql + (size_t)bm * 128 * CC;
        const size_t wb = (size_t)b * GSZ + (size_t)bn * 128 * CC;
        Wh = g_Ghi + wb; Wl = g_Glo + wb;
    } else if (MODE == 2) {
        Ah = g_wph + (size_t)bm * 128 * CC; Al = g_wpl + (size_t)bm * 128 * CC;
        const size_t wb = (size_t)b * GSZ + (size_t)bn * 128 * CC;
        Wh = g_MThi + wb; Wl = g_MTlo + wb;
    } else {
        b = bm >> 5;
        Ah = g_xhi + (size_t)bm * 128 * CC;
        Wh = g_Phi + (size_t)b * GSZ + (size_t)bn * 128 * CC;
    }

    extern __shared__ char smem[];
    const uint32_t ubase = smem_u32(smem);

    const int tid  = threadIdx.x;
    const int wid  = tid >> 5;
    const int lane = tid & 31;
    const int wm   = wid & 1;
    const int wn   = wid >> 1;

    const int cr = tid >> 2;
    const int cg = tid & 3;

    #define ISSUE(s) do { \
        const uint32_t sb_ = ubase + ((s) % NSTAGE) * STAGE_B; \
        const int kof_ = (s) * 32; \
        _Pragma("unroll") \
        for (int t_ = 0; t_ < 2; ++t_) { \
            const int r_ = cr + t_ * 64; \
            const size_t off_ = (size_t)r_ * KROW + kof_ + cg * 8; \
            const uint32_t d_ = sb_ + r_ * SROW + cg * 16; \
            cp16(d_ + 0 * TILE_B, Ah + off_); \
            cp16(d_ + BOFF, Wh + off_); \
            if (MODE != 3) { \
                cp16(d_ + 1 * TILE_B, Al + off_); \
                cp16(d_ + 3 * TILE_B, Wl + off_); \
            } \
        } \
        cp_commit(); \
    } while (0)

    float acc[4][4][4];
    #pragma unroll
    for (int i = 0; i < 4; i++)
        #pragma unroll
        for (int j = 0; j < 4; j++)
            #pragma unroll
            for (int q = 0; q < 4; q++) acc[i][j][q] = 0.f;

    const int laneRA = lane & 15;
    const int laneGA = lane >> 4;
    const int laneRB = (lane & 7) | ((lane >> 4) << 3);
    const int laneGB = (lane >> 3) & 1;

    const int NK = KITER >> 5;

    if (MODE == 3) { ISSUE(0); ISSUE(1); ISSUE(2); }
    else           { ISSUE(0); ISSUE(1); }

    for (int kb = 0; kb < NK; ++kb) {
        if (MODE == 3) {
            if (kb + 3 <= NK) cp_wait<2>();
            else if (kb + 2 <= NK) cp_wait<1>();
            else cp_wait<0>();
            __syncthreads();
            if (kb + 3 < NK) ISSUE(kb + 3);   // slot (kb-1)%4: readers done
        } else {
            if (kb + 1 < NK) cp_wait<1>(); else cp_wait<0>();
            __syncthreads();
        }

        const uint32_t sb = ubase + (kb % NSTAGE) * STAGE_B;
        const uint32_t aBase = sb + (wm * 64 + laneRA) * SROW + laneGA * 16;
        const uint32_t bBase = sb + BOFF + (wn * 32 + laneRB) * SROW + laneGB * 16;

        #pragma unroll
        for (int ks = 0; ks < 2; ++ks) {
            const uint32_t ko = ks * 32;
            uint32_t bh[4][2], bl[4][2];
            #pragma unroll
            for (int fp = 0; fp < 2; fp++) {
                uint32_t q[4];
                ldsm_x4(q, bBase + fp * (16 * SROW) + ko);
                bh[2 * fp][0] = q[0]; bh[2 * fp][1] = q[1];
                bh[2 * fp + 1][0] = q[2]; bh[2 * fp + 1][1] = q[3];
                if (MODE != 3) {
                    ldsm_x4(q, bBase + TILE_B + fp * (16 * SROW) + ko);
                    bl[2 * fp][0] = q[0]; bl[2 * fp][1] = q[1];
                    bl[2 * fp + 1][0] = q[2]; bl[2 * fp + 1][1] = q[3];
                }
            }
            #pragma unroll
            for (int fm = 0; fm < 4; fm++) {
                uint32_t ah[4], al[4];
                ldsm_x4(ah, aBase + fm * (16 * SROW) + ko);
                if (MODE != 3)
                    ldsm_x4(al, aBase + TILE_B + fm * (16 * SROW) + ko);
                #pragma unroll
                for (int fn = 0; fn < 4; fn++) {
                    mma16816(acc[fm][fn], ah, bh[fn]);
                    if (MODE != 3) {
                        mma16816(acc[fm][fn], ah, bl[fn]);
                        mma16816(acc[fm][fn], al, bh[fn]);
                    }
                }
            }
        }

        if (MODE != 3 && kb + 2 < NK) {
            __syncthreads();
            ISSUE(kb + 2);
        }
    }

    const int gid4 = lane >> 2;
    const int tig  = lane & 3;

    if (MODE == 1 || MODE == 3) {
        float* C = (MODE == 1) ? (g_T + (size_t)b * GSZ) : Cp;
        const float* bias = (MODE == 3) ? (g_biasf + b * CC) : nullptr;
        #pragma unroll
        for (int fm = 0; fm < 4; fm++) {
            const int m0 = bm * 128 + wm * 64 + fm * 16 + gid4;
            #pragma unroll
            for (int fn = 0; fn < 4; fn++) {
                const int col = bn * 128 + wn * 32 + fn * 8 + tig * 2;
                float bx = 0.f, by = 0.f;
                if (MODE == 3) { bx = bias[col]; by = bias[col + 1]; }
                float2 o;
                o.x = acc[fm][fn][0] + bx; o.y = acc[fm][fn][1] + by;
                *(float2*)(C + (size_t)m0 * CC + col) = o;
                o.x = acc[fm][fn][2] + bx; o.y = acc[fm][fn][3] + by;
                *(float2*)(C + (size_t)(m0 + 8) * CC + col) = o;
            }
        }
    } else if (MODE == 0) {
        float* P = g_Gpart + (((size_t)b * KSPL + ksplit) * 21 + blockIdx.x) * 16384;
        #pragma unroll
        for (int fm = 0; fm < 4; fm++) {
            const int m0 = wm * 64 + fm * 16 + gid4;
            #pragma unroll
            for (int fn = 0; fn < 4; fn++) {
                const int col = wn * 32 + fn * 8 + tig * 2;
                *(float2*)(P + (size_t)m0 * 128 + col) =
                    make_float2(acc[fm][fn][0], acc[fm][fn][1]);
                *(float2*)(P + (size_t)(m0 + 8) * 128 + col) =
                    make_float2(acc[fm][fn][2], acc[fm][fn][3]);
            }
        }
    } else {   // MODE 2: P hi only
        __half* Hi = g_Phi + (size_t)b * GSZ;
        #pragma unroll
        for (int fm = 0; fm < 4; fm++) {
            const int m0 = bm * 128 + wm * 64 + fm * 16 + gid4;
            #pragma unroll
            for (int fn = 0; fn < 4; fn++) {
                const int col = bn * 128 + wn * 32 + fn * 8 + tig * 2;
                *(ushort2*)(Hi + (size_t)m0 * CC + col) =
                    make_ushort2(hfu(__float2half_rn(acc[fm][fn][0])),
                                 hfu(__float2half_rn(acc[fm][fn][1])));
                *(ushort2*)(Hi + (size_t)(m0 + 8) * CC + col) =
                    make_ushort2(hfu(__float2half_rn(acc[fm][fn][2])),
                                 hfu(__float2half_rn(acc[fm][fn][3])));
            }
        }
    }
    #undef ISSUE
}

// ---------------------------------------------------------------------------
// greduce: sum KSPL partials of a G tile, split to fp16 hi/lo, write tile
// and its symmetric mirror. grid (21, 16), block 256.
// ---------------------------------------------------------------------------
__global__ __launch_bounds__(256)
void greduce_kernel()
{
    __shared__ float s[64][132];
    int t = blockIdx.x;
    const int b = blockIdx.y;
    int bm = 0;
    while (t >= 6 - bm) { t -= 6 - bm; bm++; }
    const int bn = bm + t;
    const int tid = threadIdx.x;

    const float* P0 = g_Gpart + (((size_t)b * KSPL) * 21 + blockIdx.x) * 16384;
    const float* P1 = P0 + (size_t)21 * 16384;
    const float* P2 = P1 + (size_t)21 * 16384;
    const float* P3 = P2 + (size_t)21 * 16384;
    __half* Hi = g_Ghi + (size_t)b * GSZ;
    __half* Lo = g_Glo + (size_t)b * GSZ;

    for (int hhalf = 0; hhalf < 2; ++hhalf) {
        const int rbase = hhalf * 64;
        for (int e4 = tid; e4 < 2048; e4 += 256) {
            const int r = e4 >> 5, c4 = e4 & 31;
            const size_t o = (size_t)(rbase + r) * 128 + c4 * 4;
            float4 a = *(const float4*)(P0 + o);
            float4 bb = *(const float4*)(P1 + o);
            float4 c = *(const float4*)(P2 + o);
            float4 d = *(const float4*)(P3 + o);
            s[r][c4 * 4 + 0] = a.x + bb.x + c.x + d.x;
            s[r][c4 * 4 + 1] = a.y + bb.y + c.y + d.y;
            s[r][c4 * 4 + 2] = a.z + bb.z + c.z + d.z;
            s[r][c4 * 4 + 3] = a.w + bb.w + c.w + d.w;
        }
        __syncthreads();

        {
            const int r = tid >> 2, cb = (tid & 3) * 32;
            const size_t rowo = (size_t)(bm * 128 + rbase + r) * CC + bn * 128 + cb;
            #pragma unroll
            for (int k = 0; k < 32; k += 8) {
                ushort hh[8], ll[8];
                #pragma unroll
                for (int j = 0; j < 8; ++j) {
                    __half hb, lb; split1(s[r][cb + k + j], hb, lb);
                    hh[j] = hfu(hb); ll[j] = hfu(lb);
                }
                uint4 uh, ul;
                uh.x = hh[0] | (hh[1] << 16); uh.y = hh[2] | (hh[3] << 16);
                uh.z = hh[4] | (hh[5] << 16); uh.w = hh[6] | (hh[7] << 16);
                ul.x = ll[0] | (ll[1] << 16); ul.y = ll[2] | (ll[3] << 16);
                ul.z = ll[4] | (ll[5] << 16); ul.w = ll[6] | (ll[7] << 16);
                *(uint4*)(Hi + rowo + k) = uh;
                *(uint4*)(Lo + rowo + k) = ul;
            }
        }
        if (bm != bn) {
            const int j = tid >> 1, cb = (tid & 1) * 32;
            const size_t rowo = (size_t)(bn * 128 + j) * CC + bm * 128 + rbase + cb;
            #pragma unroll
            for (int k = 0; k < 32; k += 8) {
                ushort hh[8], ll[8];
                #pragma unroll
                for (int jj = 0; jj < 8; ++jj) {
                    __half hb, lb; split1(s[cb + k + jj][j], hb, lb);
                    hh[jj] = hfu(hb); ll[jj] = hfu(lb);
                }
                uint4 uh, ul;
                uh.x = hh[0] | (hh[1] << 16); uh.y = hh[2] | (hh[3] << 16);
                uh.z = hh[4] | (hh[5] << 16); uh.w = hh[6] | (hh[7] << 16);
                ul.x = ll[0] | (ll[1] << 16); ul.y = ll[2] | (ll[3] << 16);
                ul.z = ll[4] | (ll[5] << 16); ul.w = ll[6] | (ll[7] << 16);
                *(uint4*)(Hi + rowo + k) = uh;
                *(uint4*)(Lo + rowo + k) = ul;
            }
        }
        __syncthreads();
    }
}

// ---------------------------------------------------------------------------
// logits + softmax per (b,h), 2 d-halves. grid (128, 2).
// ---------------------------------------------------------------------------
__global__ __launch_bounds__(256)
void logits_kernel(const float* __restrict__ w_qkv, const float* __restrict__ b_qkv)
{
    const int bh = blockIdx.x;
    const int yh = blockIdx.y;
    const int b = bh >> 3, h = bh & 7;

    __shared__ float buf[9312];
    __shared__ float bqs[48], ws_[48], bks[96], us_[96];

    const int tid = threadIdx.x;
    const int tx = tid & 15;
    const int ty = tid >> 4;

    if (tid < 48) {
        bqs[tid] = b_qkv[h * DD + yh * 48 + tid];
        ws_[tid] = g_U[b * 1536 + h * DD + yh * 48 + tid];
    }
    if (tid < 96) {
        bks[tid] = b_qkv[CC + h * DD + tid];
        us_[tid] = g_U[b * 1536 + CC + h * DD + tid];
    }

    const float* Tb = g_T + (size_t)b * GSZ + (size_t)(h * DD) * CC;
    const float* Wk = w_qkv + (size_t)(CC + h * DD) * CC;

    float acc[3][6];
    #pragma unroll
    for (int i = 0; i < 3; i++)
        #pragma unroll
        for (int j = 0; j < 6; j++) acc[i][j] = 0.f;

    for (int c0 = 0; c0 < CC; c0 += 32) {
        __syncthreads();
        #pragma unroll
        for (int t = 0; t < 3; ++t) {
            const int id = tid + t * 256;
            const int row = id >> 3, f4 = id & 7;
            float4 tv = *(const float4*)(Tb + (size_t)row * CC + c0 + f4 * 4);
            float4 kv = *(const float4*)(Wk + (size_t)row * CC + c0 + f4 * 4);
            buf[(f4 * 4 + 0) * 97 + row] = tv.x;
            buf[(f4 * 4 + 1) * 97 + row] = tv.y;
            buf[(f4 * 4 + 2) * 97 + row] = tv.z;
            buf[(f4 * 4 + 3) * 97 + row] = tv.w;
            buf[3104 + (f4 * 4 + 0) * 97 + row] = kv.x;
            buf[3104 + (f4 * 4 + 1) * 97 + row] = kv.y;
            buf[3104 + (f4 * 4 + 2) * 97 + row] = kv.z;
            buf[3104 + (f4 * 4 + 3) * 97 + row] = kv.w;
        }
        __syncthreads();
        #pragma unroll 8
        for (int kk = 0; kk < 32; ++kk) {
            float qr[3], kr[6];
            #pragma unroll
            for (int i = 0; i < 3; i++)
                qr[i] = buf[kk * 97 + yh * 48 + ty * 3 + i];
            #pragma unroll
            for (int j = 0; j < 6; j++) kr[j] = buf[3104 + kk * 97 + tx * 6 + j];
            #pragma unroll
            for (int i = 0; i < 3; i++)
                #pragma unroll
                for (int j = 0; j < 6; j++)
                    acc[i][j] = fmaf(qr[i], kr[j], acc[i][j]);
        }
    }
    __syncthreads();

    const float scale = 0.015625f;
    #pragma unroll
    for (int i = 0; i < 3; i++) {
        const int dl = ty * 3 + i;
        #pragma unroll
        for (int j = 0; j < 6; j++) {
            const int e = tx * 6 + j;
            float v = acc[i][j] + bqs[dl] * us_[e] + bks[e] * ws_[dl]
                      + 4096.f * bqs[dl] * bks[e];
            buf[dl * 96 + e] = v * scale;
        }
    }
    __syncthreads();

    const int wid = tid >> 5, lane = tid & 31;
    for (int r = wid; r < 48; r += 8) {
        float v0 = buf[r * 96 + lane];
        float v1 = buf[r * 96 + 32 + lane];
        float v2 = buf[r * 96 + 64 + lane];
        float m = fmaxf(v0, fmaxf(v1, v2));
        #pragma unroll
        for (int off = 16; off > 0; off >>= 1)
            m = fmaxf(m, __shfl_xor_sync(0xffffffffu, m, off));
        float e0 = expf(v0 - m), e1 = expf(v1 - m), e2 = expf(v2 - m);
        float s = e0 + e1 + e2;
        #pragma unroll
        for (int off = 16; off > 0; off >>= 1)
            s += __shfl_xor_sync(0xffffffffu, s, off);
        const float inv = 1.f / s;
        float* arow = g_attn + ((size_t)bh * 96 + yh * 48 + r) * 96;
        arow[lane]      = e0 * inv;
        arow[lane + 32] = e1 * inv;
        arow[lane + 64] = e2 * inv;
    }
}

// ---------------------------------------------------------------------------
// MT_b[c, h*96+d] = sum_e A_bh[d,e] Wv[h*96+e, c]; grid (6, 128)
// ---------------------------------------------------------------------------
__global__ __launch_bounds__(256)
void mt_kernel(const float* __restrict__ w_qkv, const float* __restrict__ b_qkv)
{
    const int c0 = blockIdx.x * 128;
    const int bh = blockIdx.y;
    const int b = bh >> 3, h = bh & 7;

    __shared__ float As[96 * 97];
    __shared__ float Ws[16 * 132];
    __shared__ float bvs[96];

    const int tid = threadIdx.x;
    const int tx = tid & 15;
    const int ty = tid >> 4;

    const float* asrc = g_attn + (size_t)bh * 9216;
    for (int id = tid; id < 9216; id += 256) {
        const int r = id / 96, c = id - r * 96;
        As[r * 97 + c] = asrc[id];
    }
    if (tid < 96) bvs[tid] = b_qkv[2 * CC + h * DD + tid];
    __syncthreads();

    if (blockIdx.x == 0 && tid < 96) {
        float rv = 0.f;
        #pragma unroll 4
        for (int e = 0; e < 96; ++e) rv += As[tid * 97 + e] * bvs[e];
        g_r[b * CC + h * DD + tid] = rv;
    }

    const float* Wv = w_qkv + (size_t)(2 * CC + h * DD) * CC;
    __half* MTh = g_MThi + (size_t)b * GSZ;
    __half* MTl = g_MTlo + (size_t)b * GSZ;

    float acc[8][6];
    #pragma unroll
    for (int i = 0; i < 8; i++)
        #pragma unroll
        for (int j = 0; j < 6; j++) acc[i][j] = 0.f;

    for (int e0 = 0; e0 < 96; e0 += 16) {
        if (e0) __syncthreads();
        #pragma unroll
        for (int t = 0; t < 2; ++t) {
            const int id = tid + t * 256;
            const int e = id >> 5, f4 = id & 31;
            float4 v = *(const float4*)(Wv + (size_t)(e0 + e) * CC + c0 + f4 * 4);
            *(float4*)&Ws[e * 132 + f4 * 4] = v;
        }
        __syncthreads();
        #pragma unroll
        for (int e = 0; e < 16; ++e) {
            float vv[8], aa[6];
            #pragma unroll
            for (int i = 0; i < 8; i++) vv[i] = Ws[e * 132 + ty * 8 + i];
            #pragma unroll
            for (int j = 0; j < 6; j++) aa[j] = As[(tx * 6 + j) * 97 + e0 + e];
            #pragma unroll
            for (int i = 0; i < 8; i++)
                #pragma unroll
                for (int j = 0; j < 6; j++)
                    acc[i][j] = fmaf(vv[i], aa[j], acc[i][j]);
        }
    }
    #pragma unroll
    for (int i = 0; i < 8; i++) {
        const int c = c0 + ty * 8 + i;
        const size_t base = (size_t)c * CC + h * DD + tx * 6;
        #pragma unroll
        for (int j = 0; j < 6; j += 2) {
            __half h0, l0, h1, l1;
            split1(acc[i][j], h0, l0);
            split1(acc[i][j + 1], h1, l1);
            *(ushort2*)(MTh + base + j) = make_ushort2(hfu(h0), hfu(h1));
            *(ushort2*)(MTl + base + j) = make_ushort2(hfu(l0), hfu(l1));
        }
    }
}

// ---------------------------------------------------------------------------
extern "C" void kernel_launch(void* const* d_in, const int* in_sizes, int n_in,
                              void* d_out, int out_size)
{
    const float* x      = (const float*)d_in[0];
    const float* w_qkv  = (const float*)d_in[1];
    const float* b_qkv  = (const float*)d_in[2];
    const float* w_proj = (const float*)d_in[3];
    const float* b_proj = (const float*)d_in[4];
    float*       out    = (float*)d_out;

    cudaFuncSetAttribute(tgemm_kernel<0>,
                         cudaFuncAttributeMaxDynamicSharedMemorySize, SMEM_ASK);
    cudaFuncSetAttribute(tgemm_kernel<1>,
                         cudaFuncAttributeMaxDynamicSharedMemorySize, SMEM_ASK);
    cudaFuncSetAttribute(tgemm_kernel<2>,
                         cudaFuncAttributeMaxDynamicSharedMemorySize, SMEM_ASK);
    cudaFuncSetAttribute(tgemm_kernel<3>,
                         cudaFuncAttributeMaxDynamicSharedMemorySize, SMEM_ASK);

    // 0) splits + transposed splits + fused column sums
    transpose_split_kernel<<<dim3(12, 1024), 256>>>(x);
    colsum_red_kernel<<<BB, 768>>>();
    splitw_kernel<<<1152, 256>>>((const float4*)w_qkv, (const float4*)w_proj);

    // 1) G partials (K-split x4) + reduce/split/mirror
    tgemm_kernel<0><<<dim3(21, KSPL, BB), 256, SMEM_ASK>>>(nullptr);
    greduce_kernel<<<dim3(21, BB), 256>>>();

    // 2) T_b = Wq @ G_b
    tgemm_kernel<1><<<dim3(6, 6, BB), 256, SMEM_ASK>>>(nullptr);

    // 3) rank-1 correction dots, logits + softmax (d-split x2)
    uw_kernel<<<dim3(192, BB), 256>>>(w_qkv);
    logits_kernel<<<dim3(BB * HH, 2), 256>>>(w_qkv, b_qkv);

    // 4) MT_b = (A @ Wv)^T stacked (c-split x6); r_bh
    mt_kernel<<<dim3(6, BB * HH), 256>>>(w_qkv, b_qkv);

    // 5) P_b = Wp @ MT_b (fp16 hi only); fused output bias
    biasf_kernel<<<dim3(96, BB), 256>>>(w_proj, b_proj);
    tgemm_kernel<2><<<dim3(6, 6, BB), 256, SMEM_ASK>>>(nullptr);

    // 6) out = X_hi @ P_hi^T + biasf   (single-pass fp16, 4-stage)
    tgemm_kernel<3><<<dim3(6, 512, 1), 256, SMEM_ASK>>>(out);
}